// round 2
// baseline (speedup 1.0000x reference)
#include <cuda_runtime.h>
#include <math.h>

#define PI_D 3.14159265358979323846
#define SC1V 0.03872983346207417f   /* 1/sqrt(2000/3) */
#define SC2V 0.06324555320336759f   /* 1/sqrt(250)    */

// ---------------- constant tables (device-computed) ----------------
__device__ float  c_d1[10][60][19];        // D1[l][z][m+9] = d(l,m,0,beta_in[z]) * w_in[z]
__device__ float  c_dh1[10][19];           // d(l,m,0,pi/2)
__device__ float  c_dinv1[10][20][19][19]; // (2l+1)*d(l,m,n,beta_L1[z])
__device__ float  c_d2[5][20][9][9];       // d(l,m,n,beta_L1[z]) * w_L1[z]
__device__ float  c_dh2[5][9][9];          // d(l,m,n,pi/2)
__device__ float  c_dinv2[5][10][9][9];    // (2l+1)*d(l,m,n,beta_O[z])
__device__ float  c_wint[10];
__device__ float2 c_tw60[19][60];          // e^{-2pi i (m)(p)/60}, m=mm-9
__device__ float2 c_tw20b[19][20];         // e^{+2pi i (m)(j)/20}, m=mm-9
__device__ float2 c_tw20f[9][20];          // e^{-2pi i (m)(k)/20}, m=mm-4
__device__ float2 c_tw10b[9][10];          // e^{+2pi i (m)(j)/10}, m=mm-4

// ---------------- scratch ----------------
__device__ float2 g_xf[32][60][19];
__device__ float2 g_kfc[100][19];
__device__ float2 g_Kk[100][19][20];
__device__ float2 g_xhat1[10][19][32];
__device__ float2 g_F[19][19][32][20];
__device__ float2 g_G[19][32][20][20];
__device__ float2 g_xg[32][100][20][81];
__device__ float2 g_xhat2[5][81][32][100];
__device__ float2 g_k2f[9][100][200];
__device__ float2 g_T2[5][81][32][100];
__device__ float2 g_z2[5][81][32][200];
__device__ float  g_s[32][200];

// ---------------- math helpers (double precision, init only) ----------------
__device__ double dev_ipow(double x, int e){ double r=1.0; for(int i=0;i<e;i++) r*=x; return r; }

__device__ double dev_wigner(int l, int m, int n, double beta){
    double fct[20]; fct[0]=1.0;
    for(int i=1;i<20;i++) fct[i]=fct[i-1]*(double)i;
    double cb = cos(0.5*beta), sb = sin(0.5*beta);
    double pref = sqrt(fct[l+m]*fct[l-m]*fct[l+n]*fct[l-n]);
    int s0 = (n-m > 0) ? (n-m) : 0;
    int s1 = (l+n < l-m) ? (l+n) : (l-m);
    double acc = 0.0;
    for(int s=s0;s<=s1;s++){
        double den = fct[l+n-s]*fct[s]*fct[m-n+s]*fct[l-m-s];
        double sg  = ((m-n+s)&1) ? -1.0 : 1.0;
        acc += sg/den * dev_ipow(cb, 2*l+n-m-2*s) * dev_ipow(sb, m-n+2*s);
    }
    return pref*acc;
}

__device__ double dev_qw(int b, int j){
    double beta = PI_D*(2*j+1)/(4.0*b);
    double s=0.0;
    for(int k=1;k<2*b;k+=2) s += sin(k*beta)/(double)k;
    return 2.0/b*sin(beta)*s;
}

// ---------------- init: all constant tables ----------------
__global__ void k_init(){
    const int total = 11400+190+72200+8100+405+4050+10+1140+380+180+90;
    for(int idx = blockIdx.x*blockDim.x+threadIdx.x; idx<total; idx += gridDim.x*blockDim.x){
        int t = idx;
        if(t < 11400){ int l=t/1140, r=t%1140, z=r/19, mm=r%19, m=mm-9;
            c_d1[l][z][mm] = (abs(m)<=l) ? (float)(dev_wigner(l,m,0, PI_D*(2*z+1)/120.0)*dev_qw(30,z)) : 0.f;
            continue; }
        t -= 11400;
        if(t < 190){ int l=t/19, mm=t%19, m=mm-9;
            c_dh1[l][mm] = (abs(m)<=l) ? (float)dev_wigner(l,m,0, PI_D*0.5) : 0.f; continue; }
        t -= 190;
        if(t < 72200){ int l=t/7220, r=t%7220, z=r/361, mm=(r%361)/19, nn=r%19, m=mm-9, n=nn-9;
            c_dinv1[l][z][mm][nn] = (abs(m)<=l && abs(n)<=l) ? (float)((2*l+1)*dev_wigner(l,m,n, PI_D*(2*z+1)/40.0)) : 0.f;
            continue; }
        t -= 72200;
        if(t < 8100){ int l=t/1620, r=t%1620, z=r/81, mm=(r%81)/9, nn=r%9, m=mm-4, n=nn-4;
            c_d2[l][z][mm][nn] = (abs(m)<=l && abs(n)<=l) ? (float)(dev_wigner(l,m,n, PI_D*(2*z+1)/40.0)*dev_qw(10,z)) : 0.f;
            continue; }
        t -= 8100;
        if(t < 405){ int l=t/81, mm=(t%81)/9, nn=t%9, m=mm-4, n=nn-4;
            c_dh2[l][mm][nn] = (abs(m)<=l && abs(n)<=l) ? (float)dev_wigner(l,m,n, PI_D*0.5) : 0.f; continue; }
        t -= 405;
        if(t < 4050){ int l=t/810, r=t%810, z=r/81, mm=(r%81)/9, nn=r%9, m=mm-4, n=nn-4;
            c_dinv2[l][z][mm][nn] = (abs(m)<=l && abs(n)<=l) ? (float)((2*l+1)*dev_wigner(l,m,n, PI_D*(2*z+1)/20.0)) : 0.f;
            continue; }
        t -= 4050;
        if(t < 10){ c_wint[t] = (float)dev_qw(5,t); continue; }
        t -= 10;
        if(t < 1140){ int mm=t/60, p=t%60; double a = -2.0*PI_D*(double)(mm-9)*(double)p/60.0;
            c_tw60[mm][p] = make_float2((float)cos(a),(float)sin(a)); continue; }
        t -= 1140;
        if(t < 380){ int mm=t/20, j=t%20; double a = 2.0*PI_D*(double)(mm-9)*(double)j/20.0;
            c_tw20b[mm][j] = make_float2((float)cos(a),(float)sin(a)); continue; }
        t -= 380;
        if(t < 180){ int mm=t/20, k=t%20; double a = -2.0*PI_D*(double)(mm-4)*(double)k/20.0;
            c_tw20f[mm][k] = make_float2((float)cos(a),(float)sin(a)); continue; }
        t -= 180;
        { int mm=t/10, j=t%10; double a = 2.0*PI_D*(double)(mm-4)*(double)j/10.0;
            c_tw10b[mm][j] = make_float2((float)cos(a),(float)sin(a)); }
    }
}

// ---------------- stage A: S2 conv ----------------
// xf[b][z][mm] = sum_p x[b,0,z,p] e^{-2pi i m p/60}
__global__ void k_xf(const float* __restrict__ x){
    int idx = blockIdx.x*blockDim.x+threadIdx.x;
    if(idx >= 32*60*19) return;
    int mm = idx%19, z = (idx/19)%60, b = idx/(19*60);
    const float* row = x + (b*60 + z)*60;
    float2 acc = make_float2(0.f,0.f);
    #pragma unroll 4
    for(int p=0;p<60;p++){
        float v = row[p]; float2 w = c_tw60[mm][p];
        acc.x += v*w.x; acc.y += v*w.y;
    }
    g_xf[b][z][mm] = acc;
}

// kfc[o][mm] = SC1 * sum_p k1[0,o,p] e^{-2pi i m p/60}
__global__ void k_kfc(const float* __restrict__ k1){
    int idx = blockIdx.x*blockDim.x+threadIdx.x;
    if(idx >= 1900) return;
    int mm = idx%19, o = idx/19;
    float2 acc = make_float2(0.f,0.f);
    for(int p=0;p<60;p++){
        float v = k1[o*60+p]; float2 w = c_tw60[mm][p];
        acc.x += v*w.x; acc.y += v*w.y;
    }
    g_kfc[o][mm] = make_float2(acc.x*SC1V, acc.y*SC1V);
}

// Kk[o][nn][k] = conj(kfc[o][nn]) * e^{+2pi i n k/20}
__global__ void k_Kk(){
    int idx = blockIdx.x*blockDim.x+threadIdx.x;
    if(idx >= 38000) return;
    int k = idx%20, mm = (idx/20)%19, o = idx/380;
    float2 kf = g_kfc[o][mm];
    float2 e  = c_tw20b[mm][k];
    g_Kk[o][mm][k] = make_float2(kf.x*e.x + kf.y*e.y, kf.x*e.y - kf.y*e.x);
}

// xhat1[l][mm][b] = sum_z xf[b][z][mm] * c_d1[l][z][mm]
__global__ void k_xhat1(){
    int idx = blockIdx.x*blockDim.x+threadIdx.x;
    if(idx >= 10*19*32) return;
    int b = idx%32, mm = (idx/32)%19, l = idx/(32*19);
    int m = mm-9;
    float2 acc = make_float2(0.f,0.f);
    if(abs(m)<=l){
        for(int z=0;z<60;z++){
            float d = c_d1[l][z][mm]; float2 v = g_xf[b][z][mm];
            acc.x += v.x*d; acc.y += v.y*d;
        }
    }
    g_xhat1[l][mm][b] = acc;
}

// F[mm][nn][b][z2] = sum_{l>=max|m|,|n|} xhat1[l][mm][b]*dh1[l][nn]*dinv1[l][z2][mm][nn]
__global__ void k_F(){
    int idx = blockIdx.x*blockDim.x+threadIdx.x;
    if(idx >= 19*19*32*20) return;
    int z2 = idx%20, b = (idx/20)%32, nn = (idx/640)%19, mm = idx/(640*19);
    int m = mm-9, n = nn-9;
    int l0 = max(abs(m),abs(n));
    float2 acc = make_float2(0.f,0.f);
    for(int l=l0;l<10;l++){
        float c = c_dh1[l][nn]*c_dinv1[l][z2][mm][nn];
        float2 xh = g_xhat1[l][mm][b];
        acc.x += xh.x*c; acc.y += xh.y*c;
    }
    g_F[mm][nn][b][z2] = acc;
}

// G[nn][b][z2][j] = sum_mm F[mm][nn][b][z2] e^{+2pi i m j/20}
__global__ void k_G(){
    int idx = blockIdx.x*blockDim.x+threadIdx.x;
    if(idx >= 19*32*20*20) return;
    int j = idx%20, z2 = (idx/20)%20, b = (idx/400)%32, nn = idx/12800;
    float2 acc = make_float2(0.f,0.f);
    for(int mm=0;mm<19;mm++){
        float2 f = g_F[mm][nn][b][z2]; float2 e = c_tw20b[mm][j];
        acc.x += f.x*e.x - f.y*e.y;
        acc.y += f.x*e.y + f.y*e.x;
    }
    g_G[nn][b][z2][j] = acc;
}

// fused: h[b,i,z2,j,k] = relu(b1[i] + Re sum_n Kk[i,n,k]*G[n,b,z2,j]); then 20x20 -> 9x9 forward DFT -> xg
// blockDim = 400 (one thread per (j,k) in the ReLU stage; t<380 covers shared tiles)
__global__ void k_s2fuse(const float* __restrict__ b1){
    __shared__ float2 Gs[19][20];
    __shared__ float2 Kks[19][20];
    __shared__ float  hs[20][20];
    __shared__ float2 tms[9][20];
    int bz = blockIdx.x;
    int b = bz/20, z2 = bz%20;
    int t = threadIdx.x;
    if(t<380){ int nn=t/20, j=t%20; Gs[nn][j] = g_G[nn][b][z2][j]; }
    __syncthreads();
    for(int i=0;i<100;i++){
        if(t<380){ int nn=t/20, k=t%20; Kks[nn][k] = g_Kk[i][nn][k]; }
        __syncthreads();
        float bias = b1[i];
        {
            int j = t/20, k = t%20;   // t < 400 always
            float acc = bias;
            #pragma unroll
            for(int nn=0;nn<19;nn++)
                acc += Kks[nn][k].x*Gs[nn][j].x - Kks[nn][k].y*Gs[nn][j].y;
            hs[j][k] = fmaxf(acc, 0.f);
        }
        __syncthreads();
        if(t<180){ int mm=t/20, k=t%20;
            float2 a = make_float2(0.f,0.f);
            #pragma unroll 4
            for(int j=0;j<20;j++){
                float v = hs[j][k]; float2 e = c_tw20f[mm][j];
                a.x += v*e.x; a.y += v*e.y;
            }
            tms[mm][k] = a;
        }
        __syncthreads();
        if(t<81){ int mm=t/9, nn=t%9;
            float2 a = make_float2(0.f,0.f);
            #pragma unroll 4
            for(int k=0;k<20;k++){
                float2 v = tms[mm][k]; float2 e = c_tw20f[nn][k];
                a.x += v.x*e.x - v.y*e.y;
                a.y += v.x*e.y + v.y*e.x;
            }
            g_xg[b][i][z2][t] = a;
        }
        __syncthreads();
    }
}

// ---------------- stage B: SO3 conv ----------------
// k2f[mm][i][o] = SC2 * sum_p k2[i,o,p] e^{-2pi i m p/20}
__global__ void k_k2f(const float* __restrict__ k2){
    int idx = blockIdx.x*blockDim.x+threadIdx.x;
    if(idx >= 9*100*200) return;
    int o = idx%200, i = (idx/200)%100, mm = idx/20000;
    float2 acc = make_float2(0.f,0.f);
    #pragma unroll
    for(int p=0;p<20;p++){
        float v = k2[(i*200+o)*20+p]; float2 e = c_tw20f[mm][p];
        acc.x += v*e.x; acc.y += v*e.y;
    }
    g_k2f[mm][i][o] = make_float2(acc.x*SC2V, acc.y*SC2V);
}

// xhat2[l][mn][b][i] = sum_z xg[b][i][z][mn] * c_d2[l][z][m][n]
__global__ void k_xhat2(){
    int idx = blockIdx.x*blockDim.x+threadIdx.x;
    if(idx >= 5*32*100*81) return;
    int mn = idx%81, i = (idx/81)%100, b = (idx/8100)%32, l = idx/259200;
    int mm = mn/9, nn = mn%9;
    int m = mm-4, n = nn-4;
    float2 acc = make_float2(0.f,0.f);
    if(abs(m)<=l && abs(n)<=l){
        #pragma unroll 4
        for(int z=0;z<20;z++){
            float d = c_d2[l][z][mm][nn]; float2 v = g_xg[b][i][z][mn];
            acc.x += v.x*d; acc.y += v.y*d;
        }
    }
    g_xhat2[l][mn][b][i] = acc;
}

// T2[l][m][n][b][i] = sum_k dh2[l][n][k] * xhat2[l][m][k][b][i]
__global__ void k_T2(){
    int idx = blockIdx.x*blockDim.x+threadIdx.x;
    if(idx >= 5*81*32*100) return;
    int i = idx%100, b = (idx/100)%32, mn = (idx/3200)%81, l = idx/259200;
    int mm = mn/9, nn = mn%9;
    float2 acc = make_float2(0.f,0.f);
    #pragma unroll
    for(int kk=0;kk<9;kk++){
        float d = c_dh2[l][nn][kk];
        float2 v = g_xhat2[l][mm*9+kk][b][i];
        acc.x += v.x*d; acc.y += v.y*d;
    }
    g_T2[l][mn][b][i] = acc;
}

// z2[l][mn][b][o] = sum_i T2[l][mn][b][i] * conj(k2f[n][i][o])
__global__ void k_z2(){
    __shared__ float2 Ts[32][100];
    int l = blockIdx.x/81, mn = blockIdx.x%81;
    int m = mn/9-4, n = mn%9-4;
    if(l < max(abs(m),abs(n))) return;
    int t = threadIdx.x;
    const float2* src = &g_T2[l][mn][0][0];
    for(int idx=t; idx<3200; idx+=256) (&Ts[0][0])[idx] = src[idx];
    __syncthreads();
    if(t<200){
        int o = t, nn = mn%9;
        for(int bc=0;bc<4;bc++){
            float2 acc[8];
            #pragma unroll
            for(int r=0;r<8;r++) acc[r] = make_float2(0.f,0.f);
            for(int i=0;i<100;i++){
                float2 kf = g_k2f[nn][i][o];
                #pragma unroll
                for(int r=0;r<8;r++){
                    float2 Tv = Ts[bc*8+r][i];
                    acc[r].x += Tv.x*kf.x + Tv.y*kf.y;
                    acc[r].y += Tv.y*kf.x - Tv.x*kf.y;
                }
            }
            #pragma unroll
            for(int r=0;r<8;r++) g_z2[l][mn][bc*8+r][o] = acc[r];
        }
    }
}

// per (b,o): accumulate over z3 of wint[z3]*sum_{j,k} relu(b2 + IDFT(g2))
__global__ void k_out2(const float* __restrict__ b2){
    __shared__ float2 zs[405];
    __shared__ float2 g2s[81];
    __shared__ float2 tm[9][10];
    __shared__ float  red[128];
    int b = blockIdx.x/200, o = blockIdx.x%200;
    int t = threadIdx.x;
    for(int idx=t; idx<405; idx+=128){
        int l = idx/81, mn = idx%81, m = mn/9-4, n = mn%9-4;
        zs[idx] = (l >= max(abs(m),abs(n))) ? g_z2[l][mn][b][o] : make_float2(0.f,0.f);
    }
    float b2v = b2[o];
    float psum = 0.f;
    for(int z3=0;z3<10;z3++){
        __syncthreads();
        if(t<81){
            int mm = t/9, nn = t%9, m = mm-4, n = nn-4;
            int l0 = max(abs(m),abs(n));
            float2 a = make_float2(0.f,0.f);
            for(int l=l0;l<5;l++){
                float d = c_dinv2[l][z3][mm][nn]; float2 v = zs[l*81+t];
                a.x += v.x*d; a.y += v.y*d;
            }
            g2s[t] = a;
        }
        __syncthreads();
        if(t<90){
            int mm = t/10, k = t%10;
            float2 a = make_float2(0.f,0.f);
            #pragma unroll
            for(int nn=0;nn<9;nn++){
                float2 v = g2s[mm*9+nn]; float2 e = c_tw10b[nn][k];
                a.x += v.x*e.x - v.y*e.y;
                a.y += v.x*e.y + v.y*e.x;
            }
            tm[mm][k] = a;
        }
        __syncthreads();
        if(t<100){
            int j = t/10, k = t%10;
            float v = 0.f;
            #pragma unroll
            for(int mm=0;mm<9;mm++){
                float2 a = tm[mm][k]; float2 e = c_tw10b[mm][j];
                v += a.x*e.x - a.y*e.y;
            }
            v = fmaxf(v + b2v, 0.f);
            psum += v * c_wint[z3];
        }
        __syncthreads();
    }
    red[t] = psum;
    __syncthreads();
    for(int s=64;s>0;s>>=1){ if(t<s) red[t] += red[t+s]; __syncthreads(); }
    if(t==0) g_s[b][o] = red[0];
}

// final linear
__global__ void k_final(const float* __restrict__ W, const float* __restrict__ bl, float* __restrict__ out){
    int t = threadIdx.x;
    if(t >= 320) return;
    int b = t/10, f = t%10;
    float acc = bl[f];
    for(int o=0;o<200;o++) acc += g_s[b][o]*W[f*200+o];
    out[b*10+f] = acc;
}

extern "C" void kernel_launch(void* const* d_in, const int* in_sizes, int n_in,
                              void* d_out, int out_size){
    const float* x  = (const float*)d_in[0];
    const float* k1 = (const float*)d_in[1];
    const float* b1 = (const float*)d_in[2];
    const float* k2 = (const float*)d_in[3];
    const float* b2 = (const float*)d_in[4];
    const float* W  = (const float*)d_in[5];
    const float* bl = (const float*)d_in[6];
    float* out = (float*)d_out;

    k_init  <<<148,128>>>();
    k_xf    <<<(32*60*19+255)/256,256>>>(x);
    k_kfc   <<<(1900+127)/128,128>>>(k1);
    k_Kk    <<<(38000+255)/256,256>>>();
    k_xhat1 <<<(10*19*32+127)/128,128>>>();
    k_F     <<<(19*19*32*20+255)/256,256>>>();
    k_G     <<<(19*32*20*20+255)/256,256>>>();
    k_s2fuse<<<640,400>>>(b1);
    k_k2f   <<<(9*100*200+255)/256,256>>>(k2);
    k_xhat2 <<<(5*32*100*81+255)/256,256>>>();
    k_T2    <<<(5*81*32*100+255)/256,256>>>();
    k_z2    <<<405,256>>>();
    k_out2  <<<6400,128>>>(b2);
    k_final <<<1,320>>>(W,bl,out);
}

// round 3
// speedup vs baseline: 1.6106x; 1.6106x over previous
#include <cuda_runtime.h>
#include <math.h>

#define PI_D 3.14159265358979323846
#define SC1V 0.03872983346207417f   /* 1/sqrt(2000/3) */
#define SC2V 0.06324555320336759f   /* 1/sqrt(250)    */

// ---------------- constant tables (device-computed) ----------------
__device__ float  c_d1[10][60][19];        // d(l,m,0,beta_in[z]) * w_in[z]
__device__ float  c_dh1[10][19];           // d(l,m,0,pi/2)
__device__ float  c_dinv1[10][20][19][19]; // (2l+1)*d(l,m,n,beta_L1[z])
__device__ float  c_d2[5][20][9][9];       // d(l,m,n,beta_L1[z]) * w_L1[z]
__device__ float  c_dh2[5][9][9];          // d(l,m,n,pi/2)
__device__ float  c_dinv2[5][10][9][9];    // (2l+1)*d(l,m,n,beta_O[z])
__device__ double c_w30[60];
__device__ double c_w10[20];
__device__ float  c_w5[10];
__device__ float2 c_tw60[19][60];          // e^{-2pi i m p/60}, m=mm-9
__device__ float2 c_tw20b[19][20];         // e^{+2pi i m j/20}, m=mm-9
__device__ float2 c_tw20f[9][20];          // e^{-2pi i m k/20}, m=mm-4
__device__ float2 c_tw10b[9][10];          // e^{+2pi i m j/10}, m=mm-4

__constant__ double c_fct[20] = {1.,1.,2.,6.,24.,120.,720.,5040.,40320.,362880.,
    3628800.,39916800.,479001600.,6227020800.,87178291200.,1307674368000.,
    20922789888000.,355687428096000.,6402373705728000.,121645100408832000.};

// ---------------- scratch ----------------
__device__ float2 g_xf[32][60][19];
__device__ float2 g_kfc[100][19];
__device__ float2 g_Kk[100][19][20];
__device__ float2 g_xhat1[10][19][32];
__device__ float2 g_G[19][32][20][20];
__device__ float2 g_xg[32][100][20][81];
__device__ float2 g_k2f[9][100][200];
__device__ float2 g_T2[5][81][32][100];
__device__ float2 g_z2[5][81][32][200];
__device__ float  g_s[32][200];

// ---------------- fast Wigner-d (fp64, init only) ----------------
__device__ double dev_wigner(int l, int m, int n, double beta){
    double cb = cos(0.5*beta), sb = sin(0.5*beta);
    double pref = sqrt(c_fct[l+m]*c_fct[l-m]*c_fct[l+n]*c_fct[l-n]);
    int s0 = (n-m > 0) ? (n-m) : 0;
    int s1 = (l+n < l-m) ? (l+n) : (l-m);
    if(s1 < s0) return 0.0;
    int e0 = 2*l+n-m-2*s0, f0 = m-n+2*s0;
    double cbe = 1.0; for(int i=0;i<e0;i++) cbe *= cb;
    double sbf = 1.0; for(int i=0;i<f0;i++) sbf *= sb;
    double r  = (sb*sb)/(cb*cb);
    double pw = cbe*sbf;
    double acc = 0.0;
    for(int s=s0;s<=s1;s++){
        double den = c_fct[l+n-s]*c_fct[s]*c_fct[m-n+s]*c_fct[l-m-s];
        double sg  = ((m-n+s)&1) ? -1.0 : 1.0;
        acc += sg*pw/den;
        pw *= r;
    }
    return pref*acc;
}

__device__ double dev_qw(int b, int j){
    double beta = PI_D*(2*j+1)/(4.0*b);
    double s=0.0;
    for(int k=1;k<2*b;k+=2) s += sin(k*beta)/(double)k;
    return 2.0/b*sin(beta)*s;
}

// ---------------- init 0: quadrature weights (only 90 sin-loops total) ----------------
__global__ void k_qw(){
    int t = threadIdx.x;
    if(t < 60)       c_w30[t]    = dev_qw(30, t);
    else if(t < 80)  c_w10[t-60] = dev_qw(10, t-60);
    else if(t < 90)  c_w5 [t-80] = (float)dev_qw(5, t-80);
}

// ---------------- init 1: all tables ----------------
__global__ void k_init(){
    const int total = 11400+190+72200+8100+405+4050+1140+380+180+90;
    for(int idx = blockIdx.x*blockDim.x+threadIdx.x; idx<total; idx += gridDim.x*blockDim.x){
        int t = idx;
        if(t < 11400){ int l=t/1140, r=t%1140, z=r/19, mm=r%19, m=mm-9;
            c_d1[l][z][mm] = (abs(m)<=l) ? (float)(dev_wigner(l,m,0, PI_D*(2*z+1)/120.0)*c_w30[z]) : 0.f;
            continue; }
        t -= 11400;
        if(t < 190){ int l=t/19, mm=t%19, m=mm-9;
            c_dh1[l][mm] = (abs(m)<=l) ? (float)dev_wigner(l,m,0, PI_D*0.5) : 0.f; continue; }
        t -= 190;
        if(t < 72200){ int l=t/7220, r=t%7220, z=r/361, mm=(r%361)/19, nn=r%19, m=mm-9, n=nn-9;
            c_dinv1[l][z][mm][nn] = (abs(m)<=l && abs(n)<=l) ? (float)((2*l+1)*dev_wigner(l,m,n, PI_D*(2*z+1)/40.0)) : 0.f;
            continue; }
        t -= 72200;
        if(t < 8100){ int l=t/1620, r=t%1620, z=r/81, mm=(r%81)/9, nn=r%9, m=mm-4, n=nn-4;
            c_d2[l][z][mm][nn] = (abs(m)<=l && abs(n)<=l) ? (float)(dev_wigner(l,m,n, PI_D*(2*z+1)/40.0)*c_w10[z]) : 0.f;
            continue; }
        t -= 8100;
        if(t < 405){ int l=t/81, mm=(t%81)/9, nn=t%9, m=mm-4, n=nn-4;
            c_dh2[l][mm][nn] = (abs(m)<=l && abs(n)<=l) ? (float)dev_wigner(l,m,n, PI_D*0.5) : 0.f; continue; }
        t -= 405;
        if(t < 4050){ int l=t/810, r=t%810, z=r/81, mm=(r%81)/9, nn=r%9, m=mm-4, n=nn-4;
            c_dinv2[l][z][mm][nn] = (abs(m)<=l && abs(n)<=l) ? (float)((2*l+1)*dev_wigner(l,m,n, PI_D*(2*z+1)/20.0)) : 0.f;
            continue; }
        t -= 4050;
        if(t < 1140){ int mm=t/60, p=t%60; double a = -2.0*PI_D*(double)(mm-9)*(double)p/60.0;
            c_tw60[mm][p] = make_float2((float)cos(a),(float)sin(a)); continue; }
        t -= 1140;
        if(t < 380){ int mm=t/20, j=t%20; double a = 2.0*PI_D*(double)(mm-9)*(double)j/20.0;
            c_tw20b[mm][j] = make_float2((float)cos(a),(float)sin(a)); continue; }
        t -= 380;
        if(t < 180){ int mm=t/20, k=t%20; double a = -2.0*PI_D*(double)(mm-4)*(double)k/20.0;
            c_tw20f[mm][k] = make_float2((float)cos(a),(float)sin(a)); continue; }
        t -= 180;
        { int mm=t/10, j=t%10; double a = 2.0*PI_D*(double)(mm-4)*(double)j/10.0;
            c_tw10b[mm][j] = make_float2((float)cos(a),(float)sin(a)); }
    }
}

// ---------------- merged input DFTs: xf + kfc + k2f ----------------
__global__ void k_dfts(const float* __restrict__ x, const float* __restrict__ k1,
                       const float* __restrict__ k2){
    int idx = blockIdx.x*blockDim.x+threadIdx.x;
    if(idx < 36480){
        int mm = idx%19, z = (idx/19)%60, b = idx/(19*60);
        const float* row = x + (b*60 + z)*60;
        float2 acc = make_float2(0.f,0.f);
        #pragma unroll 4
        for(int p=0;p<60;p++){
            float v = row[p]; float2 w = c_tw60[mm][p];
            acc.x += v*w.x; acc.y += v*w.y;
        }
        g_xf[b][z][mm] = acc;
        return;
    }
    idx -= 36480;
    if(idx < 1900){
        int mm = idx%19, o = idx/19;
        float2 acc = make_float2(0.f,0.f);
        for(int p=0;p<60;p++){
            float v = k1[o*60+p]; float2 w = c_tw60[mm][p];
            acc.x += v*w.x; acc.y += v*w.y;
        }
        g_kfc[o][mm] = make_float2(acc.x*SC1V, acc.y*SC1V);
        return;
    }
    idx -= 1900;
    if(idx < 180000){
        int o = idx%200, i = (idx/200)%100, mm = idx/20000;
        float2 acc = make_float2(0.f,0.f);
        #pragma unroll
        for(int p=0;p<20;p++){
            float v = k2[(i*200+o)*20+p]; float2 e = c_tw20f[mm][p];
            acc.x += v*e.x; acc.y += v*e.y;
        }
        g_k2f[mm][i][o] = make_float2(acc.x*SC2V, acc.y*SC2V);
    }
}

// ---------------- merged: Kk + xhat1 ----------------
__global__ void k_mid(){
    int idx = blockIdx.x*blockDim.x+threadIdx.x;
    if(idx < 38000){
        int k = idx%20, mm = (idx/20)%19, o = idx/380;
        float2 kf = g_kfc[o][mm];
        float2 e  = c_tw20b[mm][k];
        g_Kk[o][mm][k] = make_float2(kf.x*e.x + kf.y*e.y, kf.x*e.y - kf.y*e.x);
        return;
    }
    idx -= 38000;
    if(idx < 6080){
        int b = idx%32, mm = (idx/32)%19, l = idx/(32*19);
        int m = mm-9;
        float2 acc = make_float2(0.f,0.f);
        if(abs(m)<=l){
            for(int z=0;z<60;z++){
                float d = c_d1[l][z][mm]; float2 v = g_xf[b][z][mm];
                acc.x += v.x*d; acc.y += v.y*d;
            }
        }
        g_xhat1[l][mm][b] = acc;
    }
}

// ---------------- fused F + G per (b,z2) ----------------
// F[mm][nn] = sum_l xhat1[l][mm][b]*dh1[l][nn]*dinv1[l][z2][mm][nn]
// G[nn][j]  = sum_mm F[mm][nn] e^{+2pi i m j/20}
__global__ void k_FG(){
    __shared__ float2 xh1s[10][19];
    __shared__ float2 Fs[19][19];
    int b = blockIdx.x/20, z2 = blockIdx.x%20;
    int t = threadIdx.x;  // 384
    if(t < 190) xh1s[t/19][t%19] = g_xhat1[t/19][t%19][b];
    __syncthreads();
    if(t < 361){
        int mm = t/19, nn = t%19;
        int m = mm-9, n = nn-9;
        int l0 = max(abs(m),abs(n));
        float2 acc = make_float2(0.f,0.f);
        for(int l=l0;l<10;l++){
            float c = c_dh1[l][nn]*c_dinv1[l][z2][mm][nn];
            float2 xh = xh1s[l][mm];
            acc.x += xh.x*c; acc.y += xh.y*c;
        }
        Fs[mm][nn] = acc;
    }
    __syncthreads();
    if(t < 380){
        int nn = t/20, j = t%20;
        float2 acc = make_float2(0.f,0.f);
        #pragma unroll
        for(int mm=0;mm<19;mm++){
            float2 f = Fs[mm][nn]; float2 e = c_tw20b[mm][j];
            acc.x += f.x*e.x - f.y*e.y;
            acc.y += f.x*e.y + f.y*e.x;
        }
        g_G[nn][b][z2][j] = acc;
    }
}

// ---------------- fused S2 epilogue, 2 filters per iteration ----------------
__global__ void k_s2fuse(const float* __restrict__ b1){
    __shared__ float2 Gs[19][20];
    __shared__ float2 Kks[2][19][20];
    __shared__ float  hs[2][20][20];
    __shared__ float2 tms[2][9][20];
    __shared__ float  bs[100];
    int b = blockIdx.x/20, z2 = blockIdx.x%20;
    int t = threadIdx.x;  // 400
    if(t < 380){ Gs[t/20][t%20] = g_G[t/20][b][z2][t%20]; }
    if(t >= 380 && t < 400){
        for(int i=t-380;i<100;i+=20) bs[i] = b1[i];
    }
    __syncthreads();
    for(int i0=0;i0<100;i0+=2){
        for(int idx=t; idx<760; idx+=400){
            int q = idx/380, r = idx%380;
            Kks[q][r/20][r%20] = g_Kk[i0+q][r/20][r%20];
        }
        __syncthreads();
        #pragma unroll
        for(int pass=0;pass<2;pass++){
            int idx = t + pass*400;
            int q = idx/400, r = idx%400, j = r/20, k = r%20;
            float acc = bs[i0+q];
            #pragma unroll
            for(int nn=0;nn<19;nn++)
                acc += Kks[q][nn][k].x*Gs[nn][j].x - Kks[q][nn][k].y*Gs[nn][j].y;
            hs[q][j][k] = fmaxf(acc, 0.f);
        }
        __syncthreads();
        if(t < 360){
            int q = t/180, r = t%180, mm = r/20, k = r%20;
            float2 a = make_float2(0.f,0.f);
            #pragma unroll 4
            for(int j=0;j<20;j++){
                float v = hs[q][j][k]; float2 e = c_tw20f[mm][j];
                a.x += v*e.x; a.y += v*e.y;
            }
            tms[q][mm][k] = a;
        }
        __syncthreads();
        if(t < 162){
            int q = t/81, mn = t%81, mm = mn/9, nn = mn%9;
            float2 a = make_float2(0.f,0.f);
            #pragma unroll 4
            for(int k=0;k<20;k++){
                float2 v = tms[q][mm][k]; float2 e = c_tw20f[nn][k];
                a.x += v.x*e.x - v.y*e.y;
                a.y += v.x*e.y + v.y*e.x;
            }
            g_xg[b][i0+q][z2][mn] = a;
        }
        __syncthreads();
    }
}

// ---------------- fused xhat2 + T2 per (b,i) ----------------
__global__ void k_xh2T2(){
    __shared__ float2 xgs[20][81];
    __shared__ float2 xh[405];
    int b = blockIdx.x/100, i = blockIdx.x%100;
    int t = threadIdx.x;  // 256
    const float2* src = &g_xg[b][i][0][0];
    for(int idx=t; idx<1620; idx+=256) (&xgs[0][0])[idx] = src[idx];
    __syncthreads();
    for(int idx=t; idx<405; idx+=256){
        int l = idx/81, mn = idx%81, mm = mn/9, nn = mn%9;
        int m = mm-4, n = nn-4;
        float2 acc = make_float2(0.f,0.f);
        if(abs(m)<=l && abs(n)<=l){
            #pragma unroll 4
            for(int z=0;z<20;z++){
                float d = c_d2[l][z][mm][nn]; float2 v = xgs[z][mn];
                acc.x += v.x*d; acc.y += v.y*d;
            }
        }
        xh[idx] = acc;
    }
    __syncthreads();
    for(int idx=t; idx<405; idx+=256){
        int l = idx/81, mn = idx%81, mm = mn/9, nn = mn%9;
        float2 acc = make_float2(0.f,0.f);
        #pragma unroll
        for(int kk=0;kk<9;kk++){
            float d = c_dh2[l][nn][kk];
            float2 v = xh[l*81 + mm*9 + kk];
            acc.x += v.x*d; acc.y += v.y*d;
        }
        g_T2[l][mn][b][i] = acc;
    }
}

// ---------------- z2: batched 32x100x200 complex GEMM per (l,mn) ----------------
__global__ void k_z2(){
    __shared__ float2 Ts[32][100];
    int l = blockIdx.x/81, mn = blockIdx.x%81;
    int m = mn/9-4, n = mn%9-4;
    if(l < max(abs(m),abs(n))) return;
    int t = threadIdx.x;
    const float2* src = &g_T2[l][mn][0][0];
    for(int idx=t; idx<3200; idx+=256) (&Ts[0][0])[idx] = src[idx];
    __syncthreads();
    if(t<200){
        int o = t, nn = mn%9;
        for(int bc=0;bc<4;bc++){
            float2 acc[8];
            #pragma unroll
            for(int r=0;r<8;r++) acc[r] = make_float2(0.f,0.f);
            for(int i=0;i<100;i++){
                float2 kf = g_k2f[nn][i][o];
                #pragma unroll
                for(int r=0;r<8;r++){
                    float2 Tv = Ts[bc*8+r][i];
                    acc[r].x += Tv.x*kf.x + Tv.y*kf.y;
                    acc[r].y += Tv.y*kf.x - Tv.x*kf.y;
                }
            }
            #pragma unroll
            for(int r=0;r<8;r++) g_z2[l][mn][bc*8+r][o] = acc[r];
        }
    }
}

// ---------------- out2: all z3 staged at once, 4 barriers ----------------
__global__ void k_out2(const float* __restrict__ b2){
    __shared__ float2 zs[405];
    __shared__ float2 g2a[10][81];
    __shared__ float2 tma[10][9][10];
    __shared__ float  red[256];
    int b = blockIdx.x/200, o = blockIdx.x%200;
    int t = threadIdx.x;  // 256
    for(int idx=t; idx<405; idx+=256){
        int l = idx/81, mn = idx%81, m = mn/9-4, n = mn%9-4;
        zs[idx] = (l >= max(abs(m),abs(n))) ? g_z2[l][mn][b][o] : make_float2(0.f,0.f);
    }
    float b2v = b2[o];
    __syncthreads();
    // stage 1: g2a[z3][mn] = sum_l dinv2[l][z3][mm][nn] * zs[l*81+mn]
    for(int idx=t; idx<810; idx+=256){
        int z3 = idx/81, mn = idx%81, mm = mn/9, nn = mn%9;
        int m = mm-4, n = nn-4;
        int l0 = max(abs(m),abs(n));
        float2 a = make_float2(0.f,0.f);
        for(int l=l0;l<5;l++){
            float d = c_dinv2[l][z3][mm][nn]; float2 v = zs[l*81+mn];
            a.x += v.x*d; a.y += v.y*d;
        }
        g2a[z3][mn] = a;
    }
    __syncthreads();
    // stage 2: tma[z3][mm][k] = sum_nn g2a[z3][mm*9+nn] * e^{+i n k 2pi/10}
    for(int idx=t; idx<900; idx+=256){
        int z3 = idx/90, r = idx%90, mm = r/10, k = r%10;
        float2 a = make_float2(0.f,0.f);
        #pragma unroll
        for(int nn=0;nn<9;nn++){
            float2 v = g2a[z3][mm*9+nn]; float2 e = c_tw10b[nn][k];
            a.x += v.x*e.x - v.y*e.y;
            a.y += v.x*e.y + v.y*e.x;
        }
        tma[z3][mm][k] = a;
    }
    __syncthreads();
    // stage 3: relu + weighted spatial sum
    float psum = 0.f;
    for(int idx=t; idx<1000; idx+=256){
        int z3 = idx/100, r = idx%100, j = r/10, k = r%10;
        float v = 0.f;
        #pragma unroll
        for(int mm=0;mm<9;mm++){
            float2 a = tma[z3][mm][k]; float2 e = c_tw10b[mm][j];
            v += a.x*e.x - a.y*e.y;
        }
        v = fmaxf(v + b2v, 0.f);
        psum += v * c_w5[z3];
    }
    red[t] = psum;
    __syncthreads();
    for(int s=128;s>0;s>>=1){ if(t<s) red[t] += red[t+s]; __syncthreads(); }
    if(t==0) g_s[b][o] = red[0];
}

// ---------------- final linear ----------------
__global__ void k_final(const float* __restrict__ W, const float* __restrict__ bl, float* __restrict__ out){
    int t = threadIdx.x;
    if(t >= 320) return;
    int b = t/10, f = t%10;
    float acc = bl[f];
    for(int o=0;o<200;o++) acc += g_s[b][o]*W[f*200+o];
    out[b*10+f] = acc;
}

extern "C" void kernel_launch(void* const* d_in, const int* in_sizes, int n_in,
                              void* d_out, int out_size){
    const float* x  = (const float*)d_in[0];
    const float* k1 = (const float*)d_in[1];
    const float* b1 = (const float*)d_in[2];
    const float* k2 = (const float*)d_in[3];
    const float* b2 = (const float*)d_in[4];
    const float* W  = (const float*)d_in[5];
    const float* bl = (const float*)d_in[6];
    float* out = (float*)d_out;

    k_qw    <<<1,96>>>();
    k_init  <<<384,256>>>();
    k_dfts  <<<(36480+1900+180000+255)/256,256>>>(x,k1,k2);
    k_mid   <<<(38000+6080+255)/256,256>>>();
    k_FG    <<<640,384>>>();
    k_s2fuse<<<640,400>>>(b1);
    k_xh2T2 <<<3200,256>>>();
    k_z2    <<<405,256>>>();
    k_out2  <<<6400,256>>>(b2);
    k_final <<<1,320>>>(W,bl,out);
}

// round 4
// speedup vs baseline: 2.5572x; 1.5877x over previous
#include <cuda_runtime.h>
#include <math.h>

#define PI_D 3.14159265358979323846
#define SC1V 0.03872983346207417f   /* 1/sqrt(2000/3) */
#define SC2V 0.06324555320336759f   /* 1/sqrt(250)    */

// ---------------- constant tables (device-computed) ----------------
__device__ float  c_d1[10][60][19];         // d(l,m,0,beta_in[z]) * w_in[z]
__device__ float  c_dh1[10][19];            // d(l,m,0,pi/2)
__device__ float  c_dinv1p[10][20][19][10]; // (2l+1)*d(l,m,n,beta_L1[z]), n>=0 only
__device__ float  c_d2[5][20][9][9];        // d(l,m,n,beta_L1[z]) * w_L1[z]
__device__ float  c_dh2[5][9][9];           // d(l,m,n,pi/2)
__device__ float  c_dinv2[5][10][9][9];     // (2l+1)*d(l,m,n,beta_O[z])
__device__ double c_w30[60];
__device__ double c_w10[20];
__device__ float  c_w5[10];
__device__ float2 c_tw60[19][60];           // e^{-2pi i m p/60}, m=mm-9
__device__ float2 c_tw20b[19][20];          // e^{+2pi i m j/20}, m=mm-9
__device__ float2 c_tw20f[9][20];           // e^{-2pi i m k/20}, m=mm-4
__device__ float2 c_tw10b[9][10];           // e^{+2pi i m j/10}, m=mm-4

__constant__ double c_fct[20] = {1.,1.,2.,6.,24.,120.,720.,5040.,40320.,362880.,
    3628800.,39916800.,479001600.,6227020800.,87178291200.,1307674368000.,
    20922789888000.,355687428096000.,6402373705728000.,121645100408832000.};

// ---------------- scratch ----------------
__device__ float2 g_xf[32][60][19];
__device__ float2 g_kfc[100][19];
__device__ float2 g_Kp[100][10][20];      // n>=0 only
__device__ float2 g_xhat1[10][19][32];
__device__ float2 g_G[10][32][20][20];    // n>=0 only
__device__ float2 g_xg[32][100][20][81];
__device__ float2 g_k2f[9][100][200];
__device__ float2 g_T2[5][41][32][100];   // half-set mn only
__device__ float2 g_z2t[32][200][405];    // transposed for out2 coalescing
__device__ float  g_s[32][200];

// ---------------- fast Wigner-d (fp64, init only) ----------------
__device__ double dev_wigner(int l, int m, int n, double beta){
    double cb = cos(0.5*beta), sb = sin(0.5*beta);
    double pref = sqrt(c_fct[l+m]*c_fct[l-m]*c_fct[l+n]*c_fct[l-n]);
    int s0 = (n-m > 0) ? (n-m) : 0;
    int s1 = (l+n < l-m) ? (l+n) : (l-m);
    if(s1 < s0) return 0.0;
    int e0 = 2*l+n-m-2*s0, f0 = m-n+2*s0;
    double cbe = 1.0; for(int i=0;i<e0;i++) cbe *= cb;
    double sbf = 1.0; for(int i=0;i<f0;i++) sbf *= sb;
    double r  = (sb*sb)/(cb*cb);
    double pw = cbe*sbf;
    double acc = 0.0;
    for(int s=s0;s<=s1;s++){
        double den = c_fct[l+n-s]*c_fct[s]*c_fct[m-n+s]*c_fct[l-m-s];
        double sg  = ((m-n+s)&1) ? -1.0 : 1.0;
        acc += sg*pw/den;
        pw *= r;
    }
    return pref*acc;
}

__device__ double dev_qw(int b, int j){
    double beta = PI_D*(2*j+1)/(4.0*b);
    double s=0.0;
    for(int k=1;k<2*b;k+=2) s += sin(k*beta)/(double)k;
    return 2.0/b*sin(beta)*s;
}

// ---------------- init 0: quadrature weights ----------------
__global__ void k_qw(){
    int t = threadIdx.x;
    if(t < 60)       c_w30[t]    = dev_qw(30, t);
    else if(t < 80)  c_w10[t-60] = dev_qw(10, t-60);
    else if(t < 90)  c_w5 [t-80] = (float)dev_qw(5, t-80);
}

// ---------------- init 1: all tables ----------------
__global__ void k_init(){
    const int total = 11400+190+38000+8100+405+4050+1140+380+180+90;
    for(int idx = blockIdx.x*blockDim.x+threadIdx.x; idx<total; idx += gridDim.x*blockDim.x){
        int t = idx;
        if(t < 11400){ int l=t/1140, r=t%1140, z=r/19, mm=r%19, m=mm-9;
            c_d1[l][z][mm] = (abs(m)<=l) ? (float)(dev_wigner(l,m,0, PI_D*(2*z+1)/120.0)*c_w30[z]) : 0.f;
            continue; }
        t -= 11400;
        if(t < 190){ int l=t/19, mm=t%19, m=mm-9;
            c_dh1[l][mm] = (abs(m)<=l) ? (float)dev_wigner(l,m,0, PI_D*0.5) : 0.f; continue; }
        t -= 190;
        if(t < 38000){ int l=t/3800, r=t%3800, z=r/190, mm=(r%190)/10, np=r%10, m=mm-9;
            c_dinv1p[l][z][mm][np] = (abs(m)<=l && np<=l) ? (float)((2*l+1)*dev_wigner(l,m,np, PI_D*(2*z+1)/40.0)) : 0.f;
            continue; }
        t -= 38000;
        if(t < 8100){ int l=t/1620, r=t%1620, z=r/81, mm=(r%81)/9, nn=r%9, m=mm-4, n=nn-4;
            c_d2[l][z][mm][nn] = (abs(m)<=l && abs(n)<=l) ? (float)(dev_wigner(l,m,n, PI_D*(2*z+1)/40.0)*c_w10[z]) : 0.f;
            continue; }
        t -= 8100;
        if(t < 405){ int l=t/81, mm=(t%81)/9, nn=t%9, m=mm-4, n=nn-4;
            c_dh2[l][mm][nn] = (abs(m)<=l && abs(n)<=l) ? (float)dev_wigner(l,m,n, PI_D*0.5) : 0.f; continue; }
        t -= 405;
        if(t < 4050){ int l=t/810, r=t%810, z=r/81, mm=(r%81)/9, nn=r%9, m=mm-4, n=nn-4;
            c_dinv2[l][z][mm][nn] = (abs(m)<=l && abs(n)<=l) ? (float)((2*l+1)*dev_wigner(l,m,n, PI_D*(2*z+1)/20.0)) : 0.f;
            continue; }
        t -= 4050;
        if(t < 1140){ int mm=t/60, p=t%60; double a = -2.0*PI_D*(double)(mm-9)*(double)p/60.0;
            c_tw60[mm][p] = make_float2((float)cos(a),(float)sin(a)); continue; }
        t -= 1140;
        if(t < 380){ int mm=t/20, j=t%20; double a = 2.0*PI_D*(double)(mm-9)*(double)j/20.0;
            c_tw20b[mm][j] = make_float2((float)cos(a),(float)sin(a)); continue; }
        t -= 380;
        if(t < 180){ int mm=t/20, k=t%20; double a = -2.0*PI_D*(double)(mm-4)*(double)k/20.0;
            c_tw20f[mm][k] = make_float2((float)cos(a),(float)sin(a)); continue; }
        t -= 180;
        { int mm=t/10, j=t%10; double a = 2.0*PI_D*(double)(mm-4)*(double)j/10.0;
            c_tw10b[mm][j] = make_float2((float)cos(a),(float)sin(a)); }
    }
}

// ---------------- merged input DFTs: xf + kfc + k2f ----------------
__global__ void k_dfts(const float* __restrict__ x, const float* __restrict__ k1,
                       const float* __restrict__ k2){
    int idx = blockIdx.x*blockDim.x+threadIdx.x;
    if(idx < 36480){
        int mm = idx%19, z = (idx/19)%60, b = idx/(19*60);
        const float* row = x + (b*60 + z)*60;
        float2 acc = make_float2(0.f,0.f);
        #pragma unroll 4
        for(int p=0;p<60;p++){
            float v = row[p]; float2 w = c_tw60[mm][p];
            acc.x += v*w.x; acc.y += v*w.y;
        }
        g_xf[b][z][mm] = acc;
        return;
    }
    idx -= 36480;
    if(idx < 1900){
        int mm = idx%19, o = idx/19;
        float2 acc = make_float2(0.f,0.f);
        for(int p=0;p<60;p++){
            float v = k1[o*60+p]; float2 w = c_tw60[mm][p];
            acc.x += v*w.x; acc.y += v*w.y;
        }
        g_kfc[o][mm] = make_float2(acc.x*SC1V, acc.y*SC1V);
        return;
    }
    idx -= 1900;
    if(idx < 180000){
        int o = idx%200, i = (idx/200)%100, mm = idx/20000;
        float2 acc = make_float2(0.f,0.f);
        #pragma unroll
        for(int p=0;p<20;p++){
            float v = k2[(i*200+o)*20+p]; float2 e = c_tw20f[mm][p];
            acc.x += v*e.x; acc.y += v*e.y;
        }
        g_k2f[mm][i][o] = make_float2(acc.x*SC2V, acc.y*SC2V);
    }
}

// ---------------- merged: Kp (n>=0) + xhat1 ----------------
__global__ void k_mid(){
    int idx = blockIdx.x*blockDim.x+threadIdx.x;
    if(idx < 20000){
        int k = idx%20, np = (idx/20)%10, o = idx/200;
        float2 kf = g_kfc[o][np+9];
        float2 e  = c_tw20b[np+9][k];
        g_Kp[o][np][k] = make_float2(kf.x*e.x + kf.y*e.y, kf.x*e.y - kf.y*e.x);
        return;
    }
    idx -= 20000;
    if(idx < 6080){
        int b = idx%32, mm = (idx/32)%19, l = idx/(32*19);
        int m = mm-9;
        float2 acc = make_float2(0.f,0.f);
        if(abs(m)<=l){
            for(int z=0;z<60;z++){
                float d = c_d1[l][z][mm]; float2 v = g_xf[b][z][mm];
                acc.x += v.x*d; acc.y += v.y*d;
            }
        }
        g_xhat1[l][mm][b] = acc;
    }
}

// ---------------- fused F + G per (b,z2), n>=0 only ----------------
__global__ void k_FG(){
    __shared__ float2 xh1s[10][19];
    __shared__ float2 Fs[19][10];
    int b = blockIdx.x/20, z2 = blockIdx.x%20;
    int t = threadIdx.x;  // 256
    if(t < 190) xh1s[t/19][t%19] = g_xhat1[t/19][t%19][b];
    __syncthreads();
    if(t < 190){
        int mm = t%19, np = t/19;   // np = n in [0,9]
        int m = mm-9;
        int l0 = max(abs(m), np);
        float2 acc = make_float2(0.f,0.f);
        for(int l=l0;l<10;l++){
            float c = c_dh1[l][np+9]*c_dinv1p[l][z2][mm][np];
            float2 xh = xh1s[l][mm];
            acc.x += xh.x*c; acc.y += xh.y*c;
        }
        Fs[mm][np] = acc;
    }
    __syncthreads();
    if(t < 200){
        int np = t/20, j = t%20;
        float2 acc = make_float2(0.f,0.f);
        #pragma unroll
        for(int mm=0;mm<19;mm++){
            float2 f = Fs[mm][np]; float2 e = c_tw20b[mm][j];
            acc.x += f.x*e.x - f.y*e.y;
            acc.y += f.x*e.y + f.y*e.x;
        }
        g_G[np][b][z2][j] = acc;
    }
}

// ---------------- fused S2 epilogue: 4 filters/iter, Hermitian-folded ----------------
__global__ void k_s2fuse(const float* __restrict__ b1){
    __shared__ float2 Gs[10][20];
    __shared__ float2 Kks[4][10][20];
    __shared__ float  hs[4][20][20];
    __shared__ float2 tms[4][9][20];
    __shared__ float  bs[100];
    int b = blockIdx.x/20, z2 = blockIdx.x%20;
    int t = threadIdx.x;  // 400
    if(t < 200){ Gs[t/20][t%20] = g_G[t/20][b][z2][t%20]; }
    if(t >= 300){ int i = t-300; bs[i] = b1[i]; }
    if(t >= 200 && t < 300){ bs[t-200+100-100] = b1[t-200]; }   // covers 0..99 via two ranges
    __syncthreads();
    for(int i0=0;i0<100;i0+=4){
        for(int idx=t; idx<800; idx+=400){
            int q = idx/200, r = idx%200;
            Kks[q][r/20][r%20] = g_Kp[i0+q][r/20][r%20];
        }
        __syncthreads();
        // h-stage: h = relu(bias + term0 + 2*sum_{n>=1})
        {
            int j = t/20, k = t%20;
            #pragma unroll
            for(int q=0;q<4;q++){
                float s0 = Kks[q][0][k].x*Gs[0][j].x - Kks[q][0][k].y*Gs[0][j].y;
                float p = 0.f;
                #pragma unroll
                for(int n=1;n<10;n++)
                    p += Kks[q][n][k].x*Gs[n][j].x - Kks[q][n][k].y*Gs[n][j].y;
                hs[q][j][k] = fmaxf(bs[i0+q] + s0 + 2.f*p, 0.f);
            }
        }
        __syncthreads();
        // st1: only m>=0 computed (mm=4..8), mirror conj to mm=0..3
        {
            int q = t/100, r = t%100, mq = r/20, k = r%20, mm = 4+mq;
            float2 a = make_float2(0.f,0.f);
            #pragma unroll 4
            for(int j=0;j<20;j++){
                float v = hs[q][j][k]; float2 e = c_tw20f[mm][j];
                a.x += v*e.x; a.y += v*e.y;
            }
            tms[q][mm][k] = a;
            if(mq > 0) tms[q][4-mq][k] = make_float2(a.x, -a.y);
        }
        __syncthreads();
        // st2: half-set mn in [0,40], mirror conj to 80-mn
        if(t < 164){
            int q = t/41, mn = t%41, mm = mn/9, nn = mn%9;
            float2 a = make_float2(0.f,0.f);
            #pragma unroll 4
            for(int k=0;k<20;k++){
                float2 v = tms[q][mm][k]; float2 e = c_tw20f[nn][k];
                a.x += v.x*e.x - v.y*e.y;
                a.y += v.x*e.y + v.y*e.x;
            }
            g_xg[b][i0+q][z2][mn] = a;
            if(mn < 40) g_xg[b][i0+q][z2][80-mn] = make_float2(a.x, -a.y);
        }
        __syncthreads();
    }
}

// ---------------- fused xhat2 + T2 per (b,i), half-set ----------------
__global__ void k_xh2T2(){
    __shared__ float2 xgs[20][81];
    __shared__ float2 xh[5][5][9];  // [l][mm 0..4][kk]
    int b = blockIdx.x/100, i = blockIdx.x%100;
    int t = threadIdx.x;  // 256
    const float2* src = &g_xg[b][i][0][0];
    for(int idx=t; idx<1620; idx+=256) (&xgs[0][0])[idx] = src[idx];
    __syncthreads();
    if(t < 225){
        int l = t/45, r = t%45, mm = r/9, kk = r%9;
        int m = mm-4, k = kk-4;
        float2 acc = make_float2(0.f,0.f);
        if(abs(m)<=l && abs(k)<=l){
            #pragma unroll 4
            for(int z=0;z<20;z++){
                float d = c_d2[l][z][mm][kk]; float2 v = xgs[z][mm*9+kk];
                acc.x += v.x*d; acc.y += v.y*d;
            }
        }
        xh[l][mm][kk] = acc;
    }
    __syncthreads();
    if(t < 205){
        int l = t/41, mn = t%41, mm = mn/9, nn = mn%9;
        float2 acc = make_float2(0.f,0.f);
        #pragma unroll
        for(int kk=0;kk<9;kk++){
            float d = c_dh2[l][nn][kk];
            float2 v = xh[l][mm][kk];
            acc.x += v.x*d; acc.y += v.y*d;
        }
        g_T2[l][mn][b][i] = acc;
    }
}

// ---------------- z2: half-set GEMM, mirror-write; 2-o register tiles ----------------
__global__ void k_z2(){
    __shared__ float2 Ts[32][100];
    int l = blockIdx.x/41, h = blockIdx.x%41;
    int mm = h/9, nn = h%9;
    int m = mm-4, n = nn-4;
    if(l < max(abs(m),abs(n))) return;
    int t = threadIdx.x;  // 256
    const float2* src = &g_T2[l][h][0][0];
    for(int idx=t; idx<3200; idx+=256) (&Ts[0][0])[idx] = src[idx];
    __syncthreads();
    if(t < 200){
        int bq = t/100, op = t%100;     // o0 = op, o1 = op+100; b half = bq*16
        float sg = ((mm+nn)&1) ? -1.f : 1.f;
        int idx0 = l*81 + h, idx1 = l*81 + (80-h);
        for(int bc=0;bc<2;bc++){
            int bb0 = bq*16 + bc*8;
            float2 a0[8], a1[8];
            #pragma unroll
            for(int r=0;r<8;r++){ a0[r]=make_float2(0.f,0.f); a1[r]=make_float2(0.f,0.f); }
            for(int i=0;i<100;i++){
                float2 kf0 = g_k2f[nn][i][op];
                float2 kf1 = g_k2f[nn][i][op+100];
                #pragma unroll
                for(int r=0;r<8;r++){
                    float2 Tv = Ts[bb0+r][i];
                    a0[r].x += Tv.x*kf0.x + Tv.y*kf0.y;
                    a0[r].y += Tv.y*kf0.x - Tv.x*kf0.y;
                    a1[r].x += Tv.x*kf1.x + Tv.y*kf1.y;
                    a1[r].y += Tv.y*kf1.x - Tv.x*kf1.y;
                }
            }
            #pragma unroll
            for(int r=0;r<8;r++){
                int bb = bb0+r;
                g_z2t[bb][op    ][idx0] = a0[r];
                g_z2t[bb][op+100][idx0] = a1[r];
                if(h < 40){
                    g_z2t[bb][op    ][idx1] = make_float2(sg*a0[r].x, -sg*a0[r].y);
                    g_z2t[bb][op+100][idx1] = make_float2(sg*a1[r].x, -sg*a1[r].y);
                }
            }
        }
    }
}

// ---------------- out2: coalesced loads, all z3 staged, 4 barriers ----------------
__global__ void k_out2(const float* __restrict__ b2){
    __shared__ float2 zs[405];
    __shared__ float2 g2a[10][81];
    __shared__ float2 tma[10][9][10];
    __shared__ float  red[256];
    int b = blockIdx.x/200, o = blockIdx.x%200;
    int t = threadIdx.x;  // 256
    for(int idx=t; idx<405; idx+=256){
        int l = idx/81, mn = idx%81, m = mn/9-4, n = mn%9-4;
        zs[idx] = (l >= max(abs(m),abs(n))) ? g_z2t[b][o][idx] : make_float2(0.f,0.f);
    }
    float b2v = b2[o];
    __syncthreads();
    for(int idx=t; idx<810; idx+=256){
        int z3 = idx/81, mn = idx%81, mm = mn/9, nn = mn%9;
        int m = mm-4, n = nn-4;
        int l0 = max(abs(m),abs(n));
        float2 a = make_float2(0.f,0.f);
        for(int l=l0;l<5;l++){
            float d = c_dinv2[l][z3][mm][nn]; float2 v = zs[l*81+mn];
            a.x += v.x*d; a.y += v.y*d;
        }
        g2a[z3][mn] = a;
    }
    __syncthreads();
    for(int idx=t; idx<900; idx+=256){
        int z3 = idx/90, r = idx%90, mm = r/10, k = r%10;
        float2 a = make_float2(0.f,0.f);
        #pragma unroll
        for(int nn=0;nn<9;nn++){
            float2 v = g2a[z3][mm*9+nn]; float2 e = c_tw10b[nn][k];
            a.x += v.x*e.x - v.y*e.y;
            a.y += v.x*e.y + v.y*e.x;
        }
        tma[z3][mm][k] = a;
    }
    __syncthreads();
    float psum = 0.f;
    for(int idx=t; idx<1000; idx+=256){
        int z3 = idx/100, r = idx%100, j = r/10, k = r%10;
        float v = 0.f;
        #pragma unroll
        for(int mm=0;mm<9;mm++){
            float2 a = tma[z3][mm][k]; float2 e = c_tw10b[mm][j];
            v += a.x*e.x - a.y*e.y;
        }
        v = fmaxf(v + b2v, 0.f);
        psum += v * c_w5[z3];
    }
    red[t] = psum;
    __syncthreads();
    for(int s=128;s>0;s>>=1){ if(t<s) red[t] += red[t+s]; __syncthreads(); }
    if(t==0) g_s[b][o] = red[0];
}

// ---------------- final linear ----------------
__global__ void k_final(const float* __restrict__ W, const float* __restrict__ bl, float* __restrict__ out){
    int t = threadIdx.x;
    if(t >= 320) return;
    int b = t/10, f = t%10;
    float acc = bl[f];
    for(int o=0;o<200;o++) acc += g_s[b][o]*W[f*200+o];
    out[b*10+f] = acc;
}

extern "C" void kernel_launch(void* const* d_in, const int* in_sizes, int n_in,
                              void* d_out, int out_size){
    const float* x  = (const float*)d_in[0];
    const float* k1 = (const float*)d_in[1];
    const float* b1 = (const float*)d_in[2];
    const float* k2 = (const float*)d_in[3];
    const float* b2 = (const float*)d_in[4];
    const float* W  = (const float*)d_in[5];
    const float* bl = (const float*)d_in[6];
    float* out = (float*)d_out;

    k_qw    <<<1,96>>>();
    k_init  <<<250,256>>>();
    k_dfts  <<<(36480+1900+180000+255)/256,256>>>(x,k1,k2);
    k_mid   <<<(20000+6080+255)/256,256>>>();
    k_FG    <<<640,256>>>();
    k_s2fuse<<<640,400>>>(b1);
    k_xh2T2 <<<3200,256>>>();
    k_z2    <<<205,256>>>();
    k_out2  <<<6400,256>>>(b2);
    k_final <<<1,320>>>(W,bl,out);
}

// round 5
// speedup vs baseline: 2.9357x; 1.1480x over previous
#include <cuda_runtime.h>
#include <math.h>

#define PI_D 3.14159265358979323846
#define SC1V 0.03872983346207417f   /* 1/sqrt(2000/3) */
#define SC2V 0.06324555320336759f   /* 1/sqrt(250)    */

// ---------------- constant tables (device-computed) ----------------
__device__ float  c_d1[10][60][19];         // d(l,m,0,beta_in[z]) * w_in[z]
__device__ float  c_dh1[10][19];            // d(l,m,0,pi/2)
__device__ float  c_dinv1p[10][20][19][10]; // (2l+1)*d(l,m,n,beta_L1[z]), n>=0 only
__device__ float  c_d2[5][20][9][9];        // d(l,m,n,beta_L1[z]) * w_L1[z]
__device__ float  c_dh2[5][9][9];           // d(l,m,n,pi/2)
__device__ float  c_dinv2[5][10][9][9];     // (2l+1)*d(l,m,n,beta_O[z])
__device__ double c_w30[60];
__device__ double c_w10[20];
__device__ float  c_w5[10];
__device__ float2 c_tw60[19][60];           // e^{-2pi i m p/60}, m=mm-9
__device__ float2 c_tw20b[19][20];          // e^{+2pi i m j/20}, m=mm-9
__device__ float2 c_tw20f[9][20];           // e^{-2pi i m k/20}, m=mm-4
__device__ float2 c_tw10b[9][10];           // e^{+2pi i m j/10}, m=mm-4

__constant__ double c_fct[20] = {1.,1.,2.,6.,24.,120.,720.,5040.,40320.,362880.,
    3628800.,39916800.,479001600.,6227020800.,87178291200.,1307674368000.,
    20922789888000.,355687428096000.,6402373705728000.,121645100408832000.};

// ---------------- scratch ----------------
__device__ float2 g_xfT[19][60][32];      // transposed: [mm][z][b]
__device__ float2 g_kfc[100][19];
__device__ float2 g_Kp[100][10][20];      // n>=0 only
__device__ float2 g_xhat1[10][19][32];
__device__ float2 g_G[10][32][20][20];    // n>=0 only
__device__ float2 g_xg[32][100][20][81];
__device__ float2 g_k2f[9][100][200];
__device__ float2 g_T2[5][41][32][100];   // half-set mn only
__device__ float2 g_z2t[32][200][405];    // transposed for out2 coalescing
__device__ float  g_s[32][200];

// ---------------- fast Wigner-d (fp64, init only) ----------------
__device__ double dev_wigner(int l, int m, int n, double beta){
    double cb = cos(0.5*beta), sb = sin(0.5*beta);
    double pref = sqrt(c_fct[l+m]*c_fct[l-m]*c_fct[l+n]*c_fct[l-n]);
    int s0 = (n-m > 0) ? (n-m) : 0;
    int s1 = (l+n < l-m) ? (l+n) : (l-m);
    if(s1 < s0) return 0.0;
    int e0 = 2*l+n-m-2*s0, f0 = m-n+2*s0;
    double cbe = 1.0; for(int i=0;i<e0;i++) cbe *= cb;
    double sbf = 1.0; for(int i=0;i<f0;i++) sbf *= sb;
    double r  = (sb*sb)/(cb*cb);
    double pw = cbe*sbf;
    double acc = 0.0;
    for(int s=s0;s<=s1;s++){
        double den = c_fct[l+n-s]*c_fct[s]*c_fct[m-n+s]*c_fct[l-m-s];
        double sg  = ((m-n+s)&1) ? -1.0 : 1.0;
        acc += sg*pw/den;
        pw *= r;
    }
    return pref*acc;
}

__device__ double dev_qw(int b, int j){
    double beta = PI_D*(2*j+1)/(4.0*b);
    double s=0.0;
    for(int k=1;k<2*b;k+=2) s += sin(k*beta)/(double)k;
    return 2.0/b*sin(beta)*s;
}

// ---------------- init 0: quadrature weights ----------------
__global__ void k_qw(){
    int t = threadIdx.x;
    if(t < 60)       c_w30[t]    = dev_qw(30, t);
    else if(t < 80)  c_w10[t-60] = dev_qw(10, t-60);
    else if(t < 90)  c_w5 [t-80] = (float)dev_qw(5, t-80);
}

// ---------------- init 1: all tables ----------------
__global__ void k_init(){
    const int total = 11400+190+38000+8100+405+4050+1140+380+180+90;
    for(int idx = blockIdx.x*blockDim.x+threadIdx.x; idx<total; idx += gridDim.x*blockDim.x){
        int t = idx;
        if(t < 11400){ int l=t/1140, r=t%1140, z=r/19, mm=r%19, m=mm-9;
            c_d1[l][z][mm] = (abs(m)<=l) ? (float)(dev_wigner(l,m,0, PI_D*(2*z+1)/120.0)*c_w30[z]) : 0.f;
            continue; }
        t -= 11400;
        if(t < 190){ int l=t/19, mm=t%19, m=mm-9;
            c_dh1[l][mm] = (abs(m)<=l) ? (float)dev_wigner(l,m,0, PI_D*0.5) : 0.f; continue; }
        t -= 190;
        if(t < 38000){ int l=t/3800, r=t%3800, z=r/190, mm=(r%190)/10, np=r%10, m=mm-9;
            c_dinv1p[l][z][mm][np] = (abs(m)<=l && np<=l) ? (float)((2*l+1)*dev_wigner(l,m,np, PI_D*(2*z+1)/40.0)) : 0.f;
            continue; }
        t -= 38000;
        if(t < 8100){ int l=t/1620, r=t%1620, z=r/81, mm=(r%81)/9, nn=r%9, m=mm-4, n=nn-4;
            c_d2[l][z][mm][nn] = (abs(m)<=l && abs(n)<=l) ? (float)(dev_wigner(l,m,n, PI_D*(2*z+1)/40.0)*c_w10[z]) : 0.f;
            continue; }
        t -= 8100;
        if(t < 405){ int l=t/81, mm=(t%81)/9, nn=t%9, m=mm-4, n=nn-4;
            c_dh2[l][mm][nn] = (abs(m)<=l && abs(n)<=l) ? (float)dev_wigner(l,m,n, PI_D*0.5) : 0.f; continue; }
        t -= 405;
        if(t < 4050){ int l=t/810, r=t%810, z=r/81, mm=(r%81)/9, nn=r%9, m=mm-4, n=nn-4;
            c_dinv2[l][z][mm][nn] = (abs(m)<=l && abs(n)<=l) ? (float)((2*l+1)*dev_wigner(l,m,n, PI_D*(2*z+1)/20.0)) : 0.f;
            continue; }
        t -= 4050;
        if(t < 1140){ int mm=t/60, p=t%60; double a = -2.0*PI_D*(double)(mm-9)*(double)p/60.0;
            c_tw60[mm][p] = make_float2((float)cos(a),(float)sin(a)); continue; }
        t -= 1140;
        if(t < 380){ int mm=t/20, j=t%20; double a = 2.0*PI_D*(double)(mm-9)*(double)j/20.0;
            c_tw20b[mm][j] = make_float2((float)cos(a),(float)sin(a)); continue; }
        t -= 380;
        if(t < 180){ int mm=t/20, k=t%20; double a = -2.0*PI_D*(double)(mm-4)*(double)k/20.0;
            c_tw20f[mm][k] = make_float2((float)cos(a),(float)sin(a)); continue; }
        t -= 180;
        { int mm=t/10, j=t%10; double a = 2.0*PI_D*(double)(mm-4)*(double)j/10.0;
            c_tw10b[mm][j] = make_float2((float)cos(a),(float)sin(a)); }
    }
}

// ---------------- merged input DFTs: xf + kfc + k2f ----------------
__global__ void k_dfts(const float* __restrict__ x, const float* __restrict__ k1,
                       const float* __restrict__ k2){
    int idx = blockIdx.x*blockDim.x+threadIdx.x;
    if(idx < 36480){
        int mm = idx%19, z = (idx/19)%60, b = idx/(19*60);
        const float* row = x + (b*60 + z)*60;
        float2 acc = make_float2(0.f,0.f);
        #pragma unroll 4
        for(int p=0;p<60;p++){
            float v = row[p]; float2 w = c_tw60[mm][p];
            acc.x += v*w.x; acc.y += v*w.y;
        }
        g_xfT[mm][z][b] = acc;
        return;
    }
    idx -= 36480;
    if(idx < 1900){
        int mm = idx%19, o = idx/19;
        float2 acc = make_float2(0.f,0.f);
        for(int p=0;p<60;p++){
            float v = k1[o*60+p]; float2 w = c_tw60[mm][p];
            acc.x += v*w.x; acc.y += v*w.y;
        }
        g_kfc[o][mm] = make_float2(acc.x*SC1V, acc.y*SC1V);
        return;
    }
    idx -= 1900;
    if(idx < 180000){
        int o = idx%200, i = (idx/200)%100, mm = idx/20000;
        float2 acc = make_float2(0.f,0.f);
        #pragma unroll
        for(int p=0;p<20;p++){
            float v = k2[(i*200+o)*20+p]; float2 e = c_tw20f[mm][p];
            acc.x += v*e.x; acc.y += v*e.y;
        }
        g_k2f[mm][i][o] = make_float2(acc.x*SC2V, acc.y*SC2V);
    }
}

// ---------------- merged: Kp (n>=0) + xhat1 (coalesced via g_xfT) ----------------
__global__ void k_mid(){
    int idx = blockIdx.x*blockDim.x+threadIdx.x;
    if(idx < 20000){
        int k = idx%20, np = (idx/20)%10, o = idx/200;
        float2 kf = g_kfc[o][np+9];
        float2 e  = c_tw20b[np+9][k];
        g_Kp[o][np][k] = make_float2(kf.x*e.x + kf.y*e.y, kf.x*e.y - kf.y*e.x);
        return;
    }
    idx -= 20000;
    if(idx < 6080){
        int b = idx%32, mm = (idx/32)%19, l = idx/608;
        int m = mm-9;
        float2 acc = make_float2(0.f,0.f);
        if(abs(m)<=l){
            #pragma unroll 4
            for(int z=0;z<60;z++){
                float d = c_d1[l][z][mm]; float2 v = g_xfT[mm][z][b];
                acc.x += v.x*d; acc.y += v.y*d;
            }
        }
        g_xhat1[l][mm][b] = acc;
    }
}

// ---------------- fused F + G per (b,z2), n>=0 only ----------------
__global__ void k_FG(){
    __shared__ float2 xh1s[10][19];
    __shared__ float2 Fs[19][10];
    int b = blockIdx.x/20, z2 = blockIdx.x%20;
    int t = threadIdx.x;  // 256
    if(t < 190) xh1s[t/19][t%19] = g_xhat1[t/19][t%19][b];
    __syncthreads();
    if(t < 190){
        int mm = t%19, np = t/19;
        int m = mm-9;
        int l0 = max(abs(m), np);
        float2 acc = make_float2(0.f,0.f);
        for(int l=l0;l<10;l++){
            float c = c_dh1[l][np+9]*c_dinv1p[l][z2][mm][np];
            float2 xh = xh1s[l][mm];
            acc.x += xh.x*c; acc.y += xh.y*c;
        }
        Fs[mm][np] = acc;
    }
    __syncthreads();
    if(t < 200){
        int np = t/20, j = t%20;
        float2 acc = make_float2(0.f,0.f);
        #pragma unroll
        for(int mm=0;mm<19;mm++){
            float2 f = Fs[mm][np]; float2 e = c_tw20b[mm][j];
            acc.x += f.x*e.x - f.y*e.y;
            acc.y += f.x*e.y + f.y*e.x;
        }
        g_G[np][b][z2][j] = acc;
    }
}

// ---------------- fused S2 epilogue: G in registers, broadcast Kks ----------------
__global__ void k_s2fuse(const float* __restrict__ b1){
    __shared__ float2 Kks[4][10][20];
    __shared__ float  hs[4][20][21];   // padded: 21 to avoid bank conflicts
    __shared__ float2 tms[4][9][20];
    __shared__ float  bs[100];
    int b = blockIdx.x/20, z2 = blockIdx.x%20;
    int t = threadIdx.x;  // 400
    int j = t%20, k = t/20;   // k broadcast across 20 lanes for Kks reads
    float2 Greg[10];
    #pragma unroll
    for(int n=0;n<10;n++) Greg[n] = g_G[n][b][z2][j];
    if(t < 100) bs[t] = b1[t];
    __syncthreads();
    for(int i0=0;i0<100;i0+=4){
        for(int idx=t; idx<800; idx+=400){
            int q = idx/200, r = idx%200;
            Kks[q][r/20][r%20] = g_Kp[i0+q][r/20][r%20];
        }
        __syncthreads();
        // h-stage: h = relu(bias + term0 + 2*sum_{n>=1}); Greg loop-invariant
        #pragma unroll
        for(int q=0;q<4;q++){
            float s0 = Kks[q][0][k].x*Greg[0].x - Kks[q][0][k].y*Greg[0].y;
            float p = 0.f;
            #pragma unroll
            for(int n=1;n<10;n++)
                p += Kks[q][n][k].x*Greg[n].x - Kks[q][n][k].y*Greg[n].y;
            hs[q][j][k] = fmaxf(bs[i0+q] + s0 + 2.f*p, 0.f);
        }
        __syncthreads();
        // st1: only m>=0 computed (mm=4..8), mirror conj to mm=0..3
        {
            int q = t/100, r = t%100, mq = r/20, kk = r%20, mm = 4+mq;
            float2 a = make_float2(0.f,0.f);
            #pragma unroll 4
            for(int jj=0;jj<20;jj++){
                float v = hs[q][jj][kk]; float2 e = c_tw20f[mm][jj];
                a.x += v*e.x; a.y += v*e.y;
            }
            tms[q][mm][kk] = a;
            if(mq > 0) tms[q][4-mq][kk] = make_float2(a.x, -a.y);
        }
        __syncthreads();
        // st2: half-set mn in [0,40], mirror conj to 80-mn
        if(t < 164){
            int q = t/41, mn = t%41, mm = mn/9, nn = mn%9;
            float2 a = make_float2(0.f,0.f);
            #pragma unroll 4
            for(int kk=0;kk<20;kk++){
                float2 v = tms[q][mm][kk]; float2 e = c_tw20f[nn][kk];
                a.x += v.x*e.x - v.y*e.y;
                a.y += v.x*e.y + v.y*e.x;
            }
            g_xg[b][i0+q][z2][mn] = a;
            if(mn < 40) g_xg[b][i0+q][z2][80-mn] = make_float2(a.x, -a.y);
        }
        __syncthreads();
    }
}

// ---------------- fused xhat2 + T2 per (b,i), half-set ----------------
__global__ void k_xh2T2(){
    __shared__ float2 xgs[20][81];
    __shared__ float2 xh[5][5][9];  // [l][mm 0..4][kk]
    int b = blockIdx.x/100, i = blockIdx.x%100;
    int t = threadIdx.x;  // 256
    const float2* src = &g_xg[b][i][0][0];
    for(int idx=t; idx<1620; idx+=256) (&xgs[0][0])[idx] = src[idx];
    __syncthreads();
    if(t < 225){
        int l = t/45, r = t%45, mm = r/9, kk = r%9;
        int m = mm-4, k = kk-4;
        float2 acc = make_float2(0.f,0.f);
        if(abs(m)<=l && abs(k)<=l){
            #pragma unroll 4
            for(int z=0;z<20;z++){
                float d = c_d2[l][z][mm][kk]; float2 v = xgs[z][mm*9+kk];
                acc.x += v.x*d; acc.y += v.y*d;
            }
        }
        xh[l][mm][kk] = acc;
    }
    __syncthreads();
    if(t < 205){
        int l = t/41, mn = t%41, mm = mn/9, nn = mn%9;
        float2 acc = make_float2(0.f,0.f);
        #pragma unroll
        for(int kk=0;kk<9;kk++){
            float d = c_dh2[l][nn][kk];
            float2 v = xh[l][mm][kk];
            acc.x += v.x*d; acc.y += v.y*d;
        }
        g_T2[l][mn][b][i] = acc;
    }
}

// ---------------- z2: half-set GEMM, mirror-write; 2-o register tiles ----------------
__global__ void k_z2(){
    __shared__ float2 Ts[32][100];
    int l = blockIdx.x/41, h = blockIdx.x%41;
    int mm = h/9, nn = h%9;
    int m = mm-4, n = nn-4;
    if(l < max(abs(m),abs(n))) return;
    int t = threadIdx.x;  // 256
    const float2* src = &g_T2[l][h][0][0];
    for(int idx=t; idx<3200; idx+=256) (&Ts[0][0])[idx] = src[idx];
    __syncthreads();
    if(t < 200){
        int bq = t/100, op = t%100;
        float sg = ((mm+nn)&1) ? -1.f : 1.f;
        int idx0 = l*81 + h, idx1 = l*81 + (80-h);
        for(int bc=0;bc<2;bc++){
            int bb0 = bq*16 + bc*8;
            float2 a0[8], a1[8];
            #pragma unroll
            for(int r=0;r<8;r++){ a0[r]=make_float2(0.f,0.f); a1[r]=make_float2(0.f,0.f); }
            for(int i=0;i<100;i++){
                float2 kf0 = g_k2f[nn][i][op];
                float2 kf1 = g_k2f[nn][i][op+100];
                #pragma unroll
                for(int r=0;r<8;r++){
                    float2 Tv = Ts[bb0+r][i];
                    a0[r].x += Tv.x*kf0.x + Tv.y*kf0.y;
                    a0[r].y += Tv.y*kf0.x - Tv.x*kf0.y;
                    a1[r].x += Tv.x*kf1.x + Tv.y*kf1.y;
                    a1[r].y += Tv.y*kf1.x - Tv.x*kf1.y;
                }
            }
            #pragma unroll
            for(int r=0;r<8;r++){
                int bb = bb0+r;
                g_z2t[bb][op    ][idx0] = a0[r];
                g_z2t[bb][op+100][idx0] = a1[r];
                if(h < 40){
                    g_z2t[bb][op    ][idx1] = make_float2(sg*a0[r].x, -sg*a0[r].y);
                    g_z2t[bb][op+100][idx1] = make_float2(sg*a1[r].x, -sg*a1[r].y);
                }
            }
        }
    }
}

// ---------------- out2: Hermitian-halved stages ----------------
__global__ void k_out2(const float* __restrict__ b2){
    __shared__ float2 zs[405];
    __shared__ float2 g2a[10][81];
    __shared__ float2 tma[10][5][10];  // m = 0..4 only
    __shared__ float  red[256];
    int b = blockIdx.x/200, o = blockIdx.x%200;
    int t = threadIdx.x;  // 256
    for(int idx=t; idx<405; idx+=256){
        int l = idx/81, mn = idx%81, m = mn/9-4, n = mn%9-4;
        zs[idx] = (l >= max(abs(m),abs(n))) ? g_z2t[b][o][idx] : make_float2(0.f,0.f);
    }
    float b2v = b2[o];
    __syncthreads();
    // stage 1 (half): g2a for mn in [0,40], mirror conj to 80-mn
    for(int idx=t; idx<410; idx+=256){
        int z3 = idx/41, mn = idx%41, mm = mn/9, nn = mn%9;
        int m = mm-4, n = nn-4;
        int l0 = max(abs(m),abs(n));
        float2 a = make_float2(0.f,0.f);
        for(int l=l0;l<5;l++){
            float d = c_dinv2[l][z3][mm][nn]; float2 v = zs[l*81+mn];
            a.x += v.x*d; a.y += v.y*d;
        }
        g2a[z3][mn] = a;
        g2a[z3][80-mn] = make_float2(a.x, -a.y);
    }
    __syncthreads();
    // stage 2 (half): tma only for m = 0..4 (mm = 4+mq)
    for(int idx=t; idx<500; idx+=256){
        int z3 = idx/50, r = idx%50, mq = r/10, k = r%10;
        int mm = 4+mq;
        float2 a = make_float2(0.f,0.f);
        #pragma unroll
        for(int nn=0;nn<9;nn++){
            float2 v = g2a[z3][mm*9+nn]; float2 e = c_tw10b[nn][k];
            a.x += v.x*e.x - v.y*e.y;
            a.y += v.x*e.y + v.y*e.x;
        }
        tma[z3][mq][k] = a;
    }
    __syncthreads();
    // stage 3: v = tma[m=0].x + 2*sum_{m=1..4} Re(tma[m] e^{imj})
    float psum = 0.f;
    for(int idx=t; idx<1000; idx+=256){
        int z3 = idx/100, r = idx%100, j = r/10, k = r%10;
        float v = tma[z3][0][k].x;
        #pragma unroll
        for(int mq=1;mq<5;mq++){
            float2 a = tma[z3][mq][k]; float2 e = c_tw10b[4+mq][j];
            v += 2.f*(a.x*e.x - a.y*e.y);
        }
        v = fmaxf(v + b2v, 0.f);
        psum += v * c_w5[z3];
    }
    red[t] = psum;
    __syncthreads();
    for(int s=128;s>0;s>>=1){ if(t<s) red[t] += red[t+s]; __syncthreads(); }
    if(t==0) g_s[b][o] = red[0];
}

// ---------------- final linear ----------------
__global__ void k_final(const float* __restrict__ W, const float* __restrict__ bl, float* __restrict__ out){
    int t = threadIdx.x;
    if(t >= 320) return;
    int b = t/10, f = t%10;
    float acc = bl[f];
    for(int o=0;o<200;o++) acc += g_s[b][o]*W[f*200+o];
    out[b*10+f] = acc;
}

extern "C" void kernel_launch(void* const* d_in, const int* in_sizes, int n_in,
                              void* d_out, int out_size){
    const float* x  = (const float*)d_in[0];
    const float* k1 = (const float*)d_in[1];
    const float* b1 = (const float*)d_in[2];
    const float* k2 = (const float*)d_in[3];
    const float* b2 = (const float*)d_in[4];
    const float* W  = (const float*)d_in[5];
    const float* bl = (const float*)d_in[6];
    float* out = (float*)d_out;

    k_qw    <<<1,96>>>();
    k_init  <<<250,256>>>();
    k_dfts  <<<(36480+1900+180000+255)/256,256>>>(x,k1,k2);
    k_mid   <<<(20000+6080+255)/256,256>>>();
    k_FG    <<<640,256>>>();
    k_s2fuse<<<640,400>>>(b1);
    k_xh2T2 <<<3200,256>>>();
    k_z2    <<<205,256>>>();
    k_out2  <<<6400,256>>>(b2);
    k_final <<<1,320>>>(W,bl,out);
}

// round 6
// speedup vs baseline: 3.0797x; 1.0490x over previous
#include <cuda_runtime.h>
#include <math.h>

#define PI_D 3.14159265358979323846
#define SC1V 0.03872983346207417f   /* 1/sqrt(2000/3) */
#define SC2V 0.06324555320336759f   /* 1/sqrt(250)    */

// ---------------- constant tables (device-computed) ----------------
__device__ float  c_d1[10][60][19];         // d(l,m,0,beta_in[z]) * w_in[z]
__device__ float  c_dh1[10][19];            // d(l,m,0,pi/2)
__device__ float  c_dinv1p[10][20][19][10]; // (2l+1)*d(l,m,n,beta_L1[z]), n>=0 only
__device__ float  c_d2[5][20][9][9];        // d(l,m,n,beta_L1[z]) * w_L1[z]
__device__ float  c_dh2[5][9][9];           // d(l,m,n,pi/2)
__device__ float  c_dinv2[5][10][9][9];     // (2l+1)*d(l,m,n,beta_O[z])
__device__ double c_w30[60];
__device__ double c_w10[20];
__device__ float  c_w5[10];
__device__ double c_ifct[20];               // 1/n!
__device__ float2 c_tw60[19][60];           // e^{-2pi i m p/60}, m=mm-9
__device__ float2 c_tw20b[19][20];          // e^{+2pi i m j/20}, m=mm-9
__device__ float2 c_tw20f[9][20];           // e^{-2pi i m k/20}, m=mm-4
__device__ float2 c_tw10b[9][10];           // e^{+2pi i m j/10}, m=mm-4

__constant__ double c_fct[20] = {1.,1.,2.,6.,24.,120.,720.,5040.,40320.,362880.,
    3628800.,39916800.,479001600.,6227020800.,87178291200.,1307674368000.,
    20922789888000.,355687428096000.,6402373705728000.,121645100408832000.};

// ---------------- scratch ----------------
__device__ float2 g_xfT[19][60][32];      // transposed: [mm][z][b]
__device__ float2 g_kfc[100][19];
__device__ float2 g_Kp[100][10][20];      // n>=0 only
__device__ float2 g_xhat1[10][19][32];
__device__ float2 g_G[10][32][20][20];    // n>=0 only
__device__ float2 g_xg[32][100][20][81];
__device__ float2 g_k2f[9][100][200];
__device__ float2 g_T2[5][41][32][100];   // half-set mn only
__device__ float2 g_z2t[32][200][405];    // transposed for out2 coalescing
__device__ float  g_s[32][200];

// ---------------- fast Wigner-d (fp64, init only, division-free s-loop) ----------------
__device__ double dev_wigner(int l, int m, int n, double beta){
    double cb = cos(0.5*beta), sb = sin(0.5*beta);
    double pref = sqrt(c_fct[l+m]*c_fct[l-m]*c_fct[l+n]*c_fct[l-n]);
    int s0 = (n-m > 0) ? (n-m) : 0;
    int s1 = (l+n < l-m) ? (l+n) : (l-m);
    if(s1 < s0) return 0.0;
    int e0 = 2*l+n-m-2*s0, f0 = m-n+2*s0;
    double cbe = 1.0; for(int i=0;i<e0;i++) cbe *= cb;
    double sbf = 1.0; for(int i=0;i<f0;i++) sbf *= sb;
    double r  = (sb*sb)/(cb*cb);
    double pw = cbe*sbf;
    double acc = 0.0;
    for(int s=s0;s<=s1;s++){
        double deni = c_ifct[l+n-s]*c_ifct[s]*c_ifct[m-n+s]*c_ifct[l-m-s];
        double sg   = ((m-n+s)&1) ? -1.0 : 1.0;
        acc += sg*pw*deni;
        pw *= r;
    }
    return pref*acc;
}

__device__ double dev_qw(int b, int j){
    double beta = PI_D*(2*j+1)/(4.0*b);
    double s=0.0;
    for(int k=1;k<2*b;k+=2) s += sin(k*beta)/(double)k;
    return 2.0/b*sin(beta)*s;
}

// ---------------- init 0: quadrature weights + 1/n! ----------------
__global__ void k_qw(){
    int t = threadIdx.x;
    if(t < 60)        c_w30[t]     = dev_qw(30, t);
    else if(t < 80)   c_w10[t-60]  = dev_qw(10, t-60);
    else if(t < 90)   c_w5 [t-80]  = (float)dev_qw(5, t-80);
    else if(t < 110)  c_ifct[t-90] = 1.0/c_fct[t-90];
}

// ---------------- init 1: all tables ----------------
__global__ void k_init(){
    const int total = 11400+190+38000+8100+405+4050+1140+380+180+90;
    for(int idx = blockIdx.x*blockDim.x+threadIdx.x; idx<total; idx += gridDim.x*blockDim.x){
        int t = idx;
        if(t < 11400){ int l=t/1140, r=t%1140, z=r/19, mm=r%19, m=mm-9;
            c_d1[l][z][mm] = (abs(m)<=l) ? (float)(dev_wigner(l,m,0, PI_D*(2*z+1)/120.0)*c_w30[z]) : 0.f;
            continue; }
        t -= 11400;
        if(t < 190){ int l=t/19, mm=t%19, m=mm-9;
            c_dh1[l][mm] = (abs(m)<=l) ? (float)dev_wigner(l,m,0, PI_D*0.5) : 0.f; continue; }
        t -= 190;
        if(t < 38000){ int l=t/3800, r=t%3800, z=r/190, mm=(r%190)/10, np=r%10, m=mm-9;
            c_dinv1p[l][z][mm][np] = (abs(m)<=l && np<=l) ? (float)((2*l+1)*dev_wigner(l,m,np, PI_D*(2*z+1)/40.0)) : 0.f;
            continue; }
        t -= 38000;
        if(t < 8100){ int l=t/1620, r=t%1620, z=r/81, mm=(r%81)/9, nn=r%9, m=mm-4, n=nn-4;
            c_d2[l][z][mm][nn] = (abs(m)<=l && abs(n)<=l) ? (float)(dev_wigner(l,m,n, PI_D*(2*z+1)/40.0)*c_w10[z]) : 0.f;
            continue; }
        t -= 8100;
        if(t < 405){ int l=t/81, mm=(t%81)/9, nn=t%9, m=mm-4, n=nn-4;
            c_dh2[l][mm][nn] = (abs(m)<=l && abs(n)<=l) ? (float)dev_wigner(l,m,n, PI_D*0.5) : 0.f; continue; }
        t -= 405;
        if(t < 4050){ int l=t/810, r=t%810, z=r/81, mm=(r%81)/9, nn=r%9, m=mm-4, n=nn-4;
            c_dinv2[l][z][mm][nn] = (abs(m)<=l && abs(n)<=l) ? (float)((2*l+1)*dev_wigner(l,m,n, PI_D*(2*z+1)/20.0)) : 0.f;
            continue; }
        t -= 4050;
        if(t < 1140){ int mm=t/60, p=t%60; double a = -2.0*PI_D*(double)(mm-9)*(double)p/60.0;
            c_tw60[mm][p] = make_float2((float)cos(a),(float)sin(a)); continue; }
        t -= 1140;
        if(t < 380){ int mm=t/20, j=t%20; double a = 2.0*PI_D*(double)(mm-9)*(double)j/20.0;
            c_tw20b[mm][j] = make_float2((float)cos(a),(float)sin(a)); continue; }
        t -= 380;
        if(t < 180){ int mm=t/20, k=t%20; double a = -2.0*PI_D*(double)(mm-4)*(double)k/20.0;
            c_tw20f[mm][k] = make_float2((float)cos(a),(float)sin(a)); continue; }
        t -= 180;
        { int mm=t/10, j=t%10; double a = 2.0*PI_D*(double)(mm-4)*(double)j/10.0;
            c_tw10b[mm][j] = make_float2((float)cos(a),(float)sin(a)); }
    }
}

// ---------------- merged input DFTs: rows in registers, Hermitian-folded ----------------
__global__ void k_dfts(const float* __restrict__ x, const float* __restrict__ k1,
                       const float* __restrict__ k2){
    int idx = blockIdx.x*blockDim.x+threadIdx.x;
    if(idx < 1920){
        // x DFT: one thread per (b,z); compute m>=0, mirror conj
        int b = idx%32, z = idx/32;
        const float4* row4 = reinterpret_cast<const float4*>(x + (b*60 + z)*60);
        float r[60];
        #pragma unroll
        for(int i=0;i<15;i++){
            float4 v = row4[i];
            r[i*4+0]=v.x; r[i*4+1]=v.y; r[i*4+2]=v.z; r[i*4+3]=v.w;
        }
        for(int mm=9;mm<19;mm++){
            float2 acc = make_float2(0.f,0.f);
            #pragma unroll
            for(int p=0;p<60;p++){
                float2 w = c_tw60[mm][p];
                acc.x += r[p]*w.x; acc.y += r[p]*w.y;
            }
            g_xfT[mm][z][b] = acc;
            if(mm > 9) g_xfT[18-mm][z][b] = make_float2(acc.x, -acc.y);
        }
        return;
    }
    idx -= 1920;
    if(idx < 100){
        // k1 DFT: one thread per o; only mm 9..18 consumed downstream
        int o = idx;
        const float4* row4 = reinterpret_cast<const float4*>(k1 + o*60);
        float r[60];
        #pragma unroll
        for(int i=0;i<15;i++){
            float4 v = row4[i];
            r[i*4+0]=v.x; r[i*4+1]=v.y; r[i*4+2]=v.z; r[i*4+3]=v.w;
        }
        for(int mm=9;mm<19;mm++){
            float2 acc = make_float2(0.f,0.f);
            #pragma unroll
            for(int p=0;p<60;p++){
                float2 w = c_tw60[mm][p];
                acc.x += r[p]*w.x; acc.y += r[p]*w.y;
            }
            g_kfc[o][mm] = make_float2(acc.x*SC1V, acc.y*SC1V);
        }
        return;
    }
    idx -= 100;
    if(idx < 20000){
        // k2 DFT: one thread per (i,o), all 9 mm from a register-resident row
        int o = idx%200, i = idx/200;
        const float4* row4 = reinterpret_cast<const float4*>(k2 + (i*200+o)*20);
        float r[20];
        #pragma unroll
        for(int q=0;q<5;q++){
            float4 v = row4[q];
            r[q*4+0]=v.x; r[q*4+1]=v.y; r[q*4+2]=v.z; r[q*4+3]=v.w;
        }
        #pragma unroll
        for(int mm=0;mm<9;mm++){
            float2 acc = make_float2(0.f,0.f);
            #pragma unroll
            for(int p=0;p<20;p++){
                float2 e = c_tw20f[mm][p];
                acc.x += r[p]*e.x; acc.y += r[p]*e.y;
            }
            g_k2f[mm][i][o] = make_float2(acc.x*SC2V, acc.y*SC2V);
        }
    }
}

// ---------------- merged: Kp (n>=0) + xhat1 (split-z, shfl combine) ----------------
__global__ void k_mid(){
    int idx = blockIdx.x*blockDim.x+threadIdx.x;
    if(idx < 20000){
        int k = idx%20, np = (idx/20)%10, o = idx/200;
        float2 kf = g_kfc[o][np+9];
        float2 e  = c_tw20b[np+9][k];
        g_Kp[o][np][k] = make_float2(kf.x*e.x + kf.y*e.y, kf.x*e.y - kf.y*e.x);
        return;
    }
    idx -= 20000;
    if(idx < 12160){
        int half = idx & 1;
        int q = idx >> 1;                 // 6080 outputs
        int b = q%32, mm = (q/32)%19, l = q/608;
        int m = mm-9;
        float2 acc = make_float2(0.f,0.f);
        if(abs(m)<=l){
            int z0 = half*30;
            #pragma unroll 6
            for(int z=z0; z<z0+30; z++){
                float d = c_d1[l][z][mm]; float2 v = g_xfT[mm][z][b];
                acc.x += v.x*d; acc.y += v.y*d;
            }
        }
        acc.x += __shfl_xor_sync(0xFFFFFFFFu, acc.x, 1);
        acc.y += __shfl_xor_sync(0xFFFFFFFFu, acc.y, 1);
        if(half == 0) g_xhat1[l][mm][b] = acc;
    }
}

// ---------------- fused F + G per (b,z2), n>=0 only ----------------
__global__ void k_FG(){
    __shared__ float2 xh1s[10][19];
    __shared__ float2 Fs[19][10];
    int b = blockIdx.x/20, z2 = blockIdx.x%20;
    int t = threadIdx.x;  // 256
    if(t < 190) xh1s[t/19][t%19] = g_xhat1[t/19][t%19][b];
    __syncthreads();
    if(t < 190){
        int mm = t%19, np = t/19;
        int m = mm-9;
        int l0 = max(abs(m), np);
        float2 acc = make_float2(0.f,0.f);
        for(int l=l0;l<10;l++){
            float c = c_dh1[l][np+9]*c_dinv1p[l][z2][mm][np];
            float2 xh = xh1s[l][mm];
            acc.x += xh.x*c; acc.y += xh.y*c;
        }
        Fs[mm][np] = acc;
    }
    __syncthreads();
    if(t < 200){
        int np = t/20, j = t%20;
        float2 acc = make_float2(0.f,0.f);
        #pragma unroll
        for(int mm=0;mm<19;mm++){
            float2 f = Fs[mm][np]; float2 e = c_tw20b[mm][j];
            acc.x += f.x*e.x - f.y*e.y;
            acc.y += f.x*e.y + f.y*e.x;
        }
        g_G[np][b][z2][j] = acc;
    }
}

// ---------------- fused S2 epilogue: 2j x 2q register tiles, 3 barriers/iter ----------------
__global__ void k_s2fuse(const float* __restrict__ b1){
    __shared__ float2 Kks[4][10][20];
    __shared__ float  hs[4][20][21];   // padded
    __shared__ float2 tms[4][9][20];
    __shared__ float  bs[100];
    int b = blockIdx.x/20, z2 = blockIdx.x%20;
    int t = threadIdx.x;  // 400
    int r  = t%200, tq = t/200;        // tq in {0,1}
    int k  = r/10,  jp = r%10;         // j0 = jp, j1 = jp+10
    float2 G0[10], G1[10];
    #pragma unroll
    for(int n=0;n<10;n++){
        G0[n] = g_G[n][b][z2][jp];
        G1[n] = g_G[n][b][z2][jp+10];
    }
    if(t < 100) bs[t] = b1[t];
    __syncthreads();
    for(int i0=0;i0<100;i0+=4){
        {   // stage Kks: 800 float2, 2 per thread
            int q0 = t/200, r0 = t%200;
            Kks[q0][r0/20][r0%20]     = g_Kp[i0+q0][r0/20][r0%20];
            Kks[q0+2][r0/20][r0%20]   = g_Kp[i0+q0+2][r0/20][r0%20];
        }
        __syncthreads();
        // h-stage: each thread -> 4 outputs (2 q x 2 j), Kks read once per (q,n)
        #pragma unroll
        for(int qq=0;qq<2;qq++){
            int q = tq*2+qq;
            float2 Kv = Kks[q][0][k];
            float a0 = Kv.x*G0[0].x - Kv.y*G0[0].y;
            float a1 = Kv.x*G1[0].x - Kv.y*G1[0].y;
            float p0 = 0.f, p1 = 0.f;
            #pragma unroll
            for(int n=1;n<10;n++){
                Kv = Kks[q][n][k];
                p0 += Kv.x*G0[n].x - Kv.y*G0[n].y;
                p1 += Kv.x*G1[n].x - Kv.y*G1[n].y;
            }
            float bias = bs[i0+q];
            hs[q][jp   ][k] = fmaxf(bias + a0 + 2.f*p0, 0.f);
            hs[q][jp+10][k] = fmaxf(bias + a1 + 2.f*p1, 0.f);
        }
        __syncthreads();
        // st1: only m>=0 (mm=4..8), mirror conj
        {
            int q = t/100, rr = t%100, mq = rr/20, kk = rr%20, mm = 4+mq;
            float2 a = make_float2(0.f,0.f);
            #pragma unroll 4
            for(int jj=0;jj<20;jj++){
                float v = hs[q][jj][kk]; float2 e = c_tw20f[mm][jj];
                a.x += v*e.x; a.y += v*e.y;
            }
            tms[q][mm][kk] = a;
            if(mq > 0) tms[q][4-mq][kk] = make_float2(a.x, -a.y);
        }
        __syncthreads();
        // st2: half-set mn in [0,40], mirror conj to 80-mn (no trailing barrier:
        // next iter writes Kks only, disjoint from tms/global)
        if(t < 164){
            int q = t/41, mn = t%41, mm = mn/9, nn = mn%9;
            float2 a = make_float2(0.f,0.f);
            #pragma unroll 4
            for(int kk=0;kk<20;kk++){
                float2 v = tms[q][mm][kk]; float2 e = c_tw20f[nn][kk];
                a.x += v.x*e.x - v.y*e.y;
                a.y += v.x*e.y + v.y*e.x;
            }
            g_xg[b][i0+q][z2][mn] = a;
            if(mn < 40) g_xg[b][i0+q][z2][80-mn] = make_float2(a.x, -a.y);
        }
    }
}

// ---------------- fused xhat2 + T2 per (b,i): load only the needed 45 mn ----------------
__global__ void k_xh2T2(){
    __shared__ float2 xgs[20][45];
    __shared__ float2 xh[5][5][9];  // [l][mm 0..4][kk]
    int b = blockIdx.x/100, i = blockIdx.x%100;
    int t = threadIdx.x;  // 256
    for(int idx=t; idx<900; idx+=256){
        int z = idx/45, mn = idx%45;
        xgs[z][mn] = g_xg[b][i][z][mn];
    }
    __syncthreads();
    if(t < 225){
        int l = t/45, rr = t%45, mm = rr/9, kk = rr%9;
        int m = mm-4, kq = kk-4;
        float2 acc = make_float2(0.f,0.f);
        if(abs(m)<=l && abs(kq)<=l){
            #pragma unroll 4
            for(int z=0;z<20;z++){
                float d = c_d2[l][z][mm][kk]; float2 v = xgs[z][mm*9+kk];
                acc.x += v.x*d; acc.y += v.y*d;
            }
        }
        xh[l][mm][kk] = acc;
    }
    __syncthreads();
    if(t < 205){
        int l = t/41, mn = t%41, mm = mn/9, nn = mn%9;
        float2 acc = make_float2(0.f,0.f);
        #pragma unroll
        for(int kk=0;kk<9;kk++){
            float d = c_dh2[l][nn][kk];
            float2 v = xh[l][mm][kk];
            acc.x += v.x*d; acc.y += v.y*d;
        }
        g_T2[l][mn][b][i] = acc;
    }
}

// ---------------- z2: half-set GEMM, mirror-write; 2-o register tiles ----------------
__global__ void k_z2(){
    __shared__ float2 Ts[32][100];
    int l = blockIdx.x/41, h = blockIdx.x%41;
    int mm = h/9, nn = h%9;
    int m = mm-4, n = nn-4;
    if(l < max(abs(m),abs(n))) return;
    int t = threadIdx.x;  // 256
    const float2* src = &g_T2[l][h][0][0];
    for(int idx=t; idx<3200; idx+=256) (&Ts[0][0])[idx] = src[idx];
    __syncthreads();
    if(t < 200){
        int bq = t/100, op = t%100;
        float sg = ((mm+nn)&1) ? -1.f : 1.f;
        int idx0 = l*81 + h, idx1 = l*81 + (80-h);
        for(int bc=0;bc<2;bc++){
            int bb0 = bq*16 + bc*8;
            float2 a0[8], a1[8];
            #pragma unroll
            for(int rr=0;rr<8;rr++){ a0[rr]=make_float2(0.f,0.f); a1[rr]=make_float2(0.f,0.f); }
            for(int i=0;i<100;i++){
                float2 kf0 = g_k2f[nn][i][op];
                float2 kf1 = g_k2f[nn][i][op+100];
                #pragma unroll
                for(int rr=0;rr<8;rr++){
                    float2 Tv = Ts[bb0+rr][i];
                    a0[rr].x += Tv.x*kf0.x + Tv.y*kf0.y;
                    a0[rr].y += Tv.y*kf0.x - Tv.x*kf0.y;
                    a1[rr].x += Tv.x*kf1.x + Tv.y*kf1.y;
                    a1[rr].y += Tv.y*kf1.x - Tv.x*kf1.y;
                }
            }
            #pragma unroll
            for(int rr=0;rr<8;rr++){
                int bb = bb0+rr;
                g_z2t[bb][op    ][idx0] = a0[rr];
                g_z2t[bb][op+100][idx0] = a1[rr];
                if(h < 40){
                    g_z2t[bb][op    ][idx1] = make_float2(sg*a0[rr].x, -sg*a0[rr].y);
                    g_z2t[bb][op+100][idx1] = make_float2(sg*a1[rr].x, -sg*a1[rr].y);
                }
            }
        }
    }
}

// ---------------- out2: Hermitian-halved stages, shuffle reduction ----------------
__global__ void k_out2(const float* __restrict__ b2){
    __shared__ float2 zs[405];
    __shared__ float2 g2a[10][81];
    __shared__ float2 tma[10][5][10];  // m = 0..4 only
    __shared__ float  wsum[8];
    int b = blockIdx.x/200, o = blockIdx.x%200;
    int t = threadIdx.x;  // 256
    for(int idx=t; idx<405; idx+=256){
        int l = idx/81, mn = idx%81, m = mn/9-4, n = mn%9-4;
        zs[idx] = (l >= max(abs(m),abs(n))) ? g_z2t[b][o][idx] : make_float2(0.f,0.f);
    }
    float b2v = b2[o];
    __syncthreads();
    for(int idx=t; idx<410; idx+=256){
        int z3 = idx/41, mn = idx%41, mm = mn/9, nn = mn%9;
        int m = mm-4, n = nn-4;
        int l0 = max(abs(m),abs(n));
        float2 a = make_float2(0.f,0.f);
        for(int l=l0;l<5;l++){
            float d = c_dinv2[l][z3][mm][nn]; float2 v = zs[l*81+mn];
            a.x += v.x*d; a.y += v.y*d;
        }
        g2a[z3][mn] = a;
        g2a[z3][80-mn] = make_float2(a.x, -a.y);
    }
    __syncthreads();
    for(int idx=t; idx<500; idx+=256){
        int z3 = idx/50, rr = idx%50, mq = rr/10, k = rr%10;
        int mm = 4+mq;
        float2 a = make_float2(0.f,0.f);
        #pragma unroll
        for(int nn=0;nn<9;nn++){
            float2 v = g2a[z3][mm*9+nn]; float2 e = c_tw10b[nn][k];
            a.x += v.x*e.x - v.y*e.y;
            a.y += v.x*e.y + v.y*e.x;
        }
        tma[z3][mq][k] = a;
    }
    __syncthreads();
    float psum = 0.f;
    for(int idx=t; idx<1000; idx+=256){
        int z3 = idx/100, rr = idx%100, j = rr/10, k = rr%10;
        float v = tma[z3][0][k].x;
        #pragma unroll
        for(int mq=1;mq<5;mq++){
            float2 a = tma[z3][mq][k]; float2 e = c_tw10b[4+mq][j];
            v += 2.f*(a.x*e.x - a.y*e.y);
        }
        v = fmaxf(v + b2v, 0.f);
        psum += v * c_w5[z3];
    }
    #pragma unroll
    for(int off=16; off; off>>=1) psum += __shfl_xor_sync(0xFFFFFFFFu, psum, off);
    if((t&31) == 0) wsum[t>>5] = psum;
    __syncthreads();
    if(t == 0){
        float s = 0.f;
        #pragma unroll
        for(int w=0;w<8;w++) s += wsum[w];
        g_s[b][o] = s;
    }
}

// ---------------- final linear ----------------
__global__ void k_final(const float* __restrict__ W, const float* __restrict__ bl, float* __restrict__ out){
    int t = threadIdx.x;
    if(t >= 320) return;
    int b = t/10, f = t%10;
    float acc = bl[f];
    for(int o=0;o<200;o++) acc += g_s[b][o]*W[f*200+o];
    out[b*10+f] = acc;
}

extern "C" void kernel_launch(void* const* d_in, const int* in_sizes, int n_in,
                              void* d_out, int out_size){
    const float* x  = (const float*)d_in[0];
    const float* k1 = (const float*)d_in[1];
    const float* b1 = (const float*)d_in[2];
    const float* k2 = (const float*)d_in[3];
    const float* b2 = (const float*)d_in[4];
    const float* W  = (const float*)d_in[5];
    const float* bl = (const float*)d_in[6];
    float* out = (float*)d_out;

    k_qw    <<<1,128>>>();
    k_init  <<<250,256>>>();
    k_dfts  <<<(1920+100+20000+255)/256,256>>>(x,k1,k2);
    k_mid   <<<(20000+12160+255)/256,256>>>();
    k_FG    <<<640,256>>>();
    k_s2fuse<<<640,400>>>(b1);
    k_xh2T2 <<<3200,256>>>();
    k_z2    <<<205,256>>>();
    k_out2  <<<6400,256>>>(b2);
    k_final <<<1,320>>>(W,bl,out);
}

// round 8
// speedup vs baseline: 3.2779x; 1.0644x over previous
#include <cuda_runtime.h>
#include <math.h>

#define PI_D 3.14159265358979323846
#define SC1V 0.03872983346207417f   /* 1/sqrt(2000/3) */
#define SC2V 0.06324555320336759f   /* 1/sqrt(250)    */

typedef unsigned long long u64;

// packed f32x2 helpers
__device__ __forceinline__ float2 u2f(u64 v){ float2 r; asm("mov.b64 {%0,%1}, %2;":"=f"(r.x),"=f"(r.y):"l"(v)); return r; }
__device__ __forceinline__ u64 pk2(float a, float b){ u64 r; asm("mov.b64 %0, {%1,%2};":"=l"(r):"f"(a),"f"(b)); return r; }
__device__ __forceinline__ void fma2(u64 &acc, u64 a, u64 b){
    asm("fma.rn.f32x2 %0, %1, %2, %3;" : "=l"(acc) : "l"(a), "l"(b), "l"(acc));
}

// ---------------- constant tables (device-computed) ----------------
__device__ float  c_d1[10][60][19];
__device__ float  c_dh1[10][19];
__device__ float  c_dinv1p[10][20][19][10];
__device__ float  c_d2[5][20][9][9];
__device__ float  c_dh2[5][9][9];
__device__ float  c_dinv2[5][10][9][9];
__device__ float  c_w5[10];
__device__ float2 c_tw60[19][60];    // e^{-2pi i m p/60}
__device__ float2 c_tw20b[19][20];   // e^{+2pi i m j/20}
__device__ float2 c_tw20br[19][20];  // rotated (-y,x)
__device__ float2 c_tw20f[9][20];    // e^{-2pi i m k/20}
__device__ float2 c_tw20fr[9][20];   // rotated
__device__ float2 c_tw10b[9][10];    // e^{+2pi i m j/10}
__device__ float2 c_tw10br[9][10];   // rotated

__constant__ double c_fct[20] = {1.,1.,2.,6.,24.,120.,720.,5040.,40320.,362880.,
    3628800.,39916800.,479001600.,6227020800.,87178291200.,1307674368000.,
    20922789888000.,355687428096000.,6402373705728000.,121645100408832000.};

// ---------------- scratch ----------------
__device__ float2 g_xfT[19][60][32];
__device__ float2 g_kfc[100][19];
__device__ float2 g_Kp[100][10][20];
__device__ float2 g_G[10][32][20][20];
__device__ float2 g_xg[32][100][20][81];
__device__ float2 g_k2f[9][100][200];
__device__ float2 g_T2[5][41][32][100];
__device__ float2 g_z2t[32][200][405];

// ---------------- Wigner-d from precomputed half-angle cos/sin ----------------
__device__ double dev_wigner_cs(int l, int m, int n, double cb, double sb, const double* ifct){
    double pref = sqrt(c_fct[l+m]*c_fct[l-m]*c_fct[l+n]*c_fct[l-n]);
    int s0 = (n-m > 0) ? (n-m) : 0;
    int s1 = (l+n < l-m) ? (l+n) : (l-m);
    if(s1 < s0) return 0.0;
    int e0 = 2*l+n-m-2*s0, f0 = m-n+2*s0;
    double cbe = 1.0; for(int i=0;i<e0;i++) cbe *= cb;
    double sbf = 1.0; for(int i=0;i<f0;i++) sbf *= sb;
    double r  = (sb*sb)/(cb*cb);
    double pw = cbe*sbf;
    double acc = 0.0;
    for(int s=s0;s<=s1;s++){
        double deni = ifct[l+n-s]*ifct[s]*ifct[m-n+s]*ifct[l-m-s];
        double sg   = ((m-n+s)&1) ? -1.0 : 1.0;
        acc += sg*pw*deni;
        pw *= r;
    }
    return pref*acc;
}

__device__ double dev_qw(int b, int j){
    double beta = PI_D*(2*j+1)/(4.0*b);
    double s=0.0;
    for(int k=1;k<2*b;k+=2) s += sin(k*beta)/(double)k;
    return 2.0/b*sin(beta)*s;
}

// ---------------- init: output reset + per-block smem weights + all tables ----------------
__global__ void k_init(const float* __restrict__ bl, float* __restrict__ out){
    // reset output accumulator (out2 uses atomicAdd; must happen every call)
    {
        int gi = blockIdx.x*blockDim.x + threadIdx.x;
        if(gi < 320) out[gi] = bl[gi%10];
    }
    __shared__ double s_w30[60], s_w10[20];
    __shared__ float  s_w5f[10];
    __shared__ double cb120[60], sb120[60], cb40[20], sb40[20], cb20[10], sb20[10];
    __shared__ double s_ifct[20];
    int tt = threadIdx.x;
    if(tt < 60){ s_w30[tt]=dev_qw(30,tt); double a=PI_D*(2*tt+1)/240.0; cb120[tt]=cos(a); sb120[tt]=sin(a); }
    else if(tt < 80){ int z=tt-60; s_w10[z]=dev_qw(10,z); double a=PI_D*(2*z+1)/80.0; cb40[z]=cos(a); sb40[z]=sin(a); }
    else if(tt < 90){ int z=tt-80; s_w5f[z]=(float)dev_qw(5,z); double a=PI_D*(2*z+1)/40.0; cb20[z]=cos(a); sb20[z]=sin(a); }
    else if(tt < 110){ s_ifct[tt-90] = 1.0/c_fct[tt-90]; }
    __syncthreads();
    const double cbh = 0.70710678118654752, sbh = 0.70710678118654752;
    const int total = 11400+190+38000+8100+405+4050+1140+380+180+90+10;
    for(int idx = blockIdx.x*blockDim.x+threadIdx.x; idx<total; idx += gridDim.x*blockDim.x){
        int t = idx;
        if(t < 11400){ int l=t/1140, r=t%1140, z=r/19, mm=r%19, m=mm-9;
            c_d1[l][z][mm] = (abs(m)<=l) ? (float)(dev_wigner_cs(l,m,0,cb120[z],sb120[z],s_ifct)*s_w30[z]) : 0.f;
            continue; }
        t -= 11400;
        if(t < 190){ int l=t/19, mm=t%19, m=mm-9;
            c_dh1[l][mm] = (abs(m)<=l) ? (float)dev_wigner_cs(l,m,0,cbh,sbh,s_ifct) : 0.f; continue; }
        t -= 190;
        if(t < 38000){ int l=t/3800, r=t%3800, z=r/190, mm=(r%190)/10, np=r%10, m=mm-9;
            c_dinv1p[l][z][mm][np] = (abs(m)<=l && np<=l) ? (float)((2*l+1)*dev_wigner_cs(l,m,np,cb40[z],sb40[z],s_ifct)) : 0.f;
            continue; }
        t -= 38000;
        if(t < 8100){ int l=t/1620, r=t%1620, z=r/81, mm=(r%81)/9, nn=r%9, m=mm-4, n=nn-4;
            c_d2[l][z][mm][nn] = (abs(m)<=l && abs(n)<=l) ? (float)(dev_wigner_cs(l,m,n,cb40[z],sb40[z],s_ifct)*s_w10[z]) : 0.f;
            continue; }
        t -= 8100;
        if(t < 405){ int l=t/81, mm=(t%81)/9, nn=t%9, m=mm-4, n=nn-4;
            c_dh2[l][mm][nn] = (abs(m)<=l && abs(n)<=l) ? (float)dev_wigner_cs(l,m,n,cbh,sbh,s_ifct) : 0.f; continue; }
        t -= 405;
        if(t < 4050){ int l=t/810, r=t%810, z=r/81, mm=(r%81)/9, nn=r%9, m=mm-4, n=nn-4;
            c_dinv2[l][z][mm][nn] = (abs(m)<=l && abs(n)<=l) ? (float)((2*l+1)*dev_wigner_cs(l,m,n,cb20[z],sb20[z],s_ifct)) : 0.f;
            continue; }
        t -= 4050;
        if(t < 1140){ int mm=t/60, p=t%60; double a = -2.0*PI_D*(double)(mm-9)*(double)p/60.0;
            c_tw60[mm][p] = make_float2((float)cos(a),(float)sin(a)); continue; }
        t -= 1140;
        if(t < 380){ int mm=t/20, j=t%20; double a = 2.0*PI_D*(double)(mm-9)*(double)j/20.0;
            float cx=(float)cos(a), cy=(float)sin(a);
            c_tw20b[mm][j]  = make_float2(cx,cy);
            c_tw20br[mm][j] = make_float2(-cy,cx);
            continue; }
        t -= 380;
        if(t < 180){ int mm=t/20, k=t%20; double a = -2.0*PI_D*(double)(mm-4)*(double)k/20.0;
            float cx=(float)cos(a), cy=(float)sin(a);
            c_tw20f[mm][k]  = make_float2(cx,cy);
            c_tw20fr[mm][k] = make_float2(-cy,cx);
            continue; }
        t -= 180;
        if(t < 90){ int mm=t/10, j=t%10; double a = 2.0*PI_D*(double)(mm-4)*(double)j/10.0;
            float cx=(float)cos(a), cy=(float)sin(a);
            c_tw10b[mm][j]  = make_float2(cx,cy);
            c_tw10br[mm][j] = make_float2(-cy,cx);
            continue; }
        t -= 90;
        { c_w5[t] = s_w5f[t]; }
    }
}

// ---------------- input DFTs (Hermitian-folded, f32x2) ----------------
__global__ void k_dfts(const float* __restrict__ x, const float* __restrict__ k1,
                       const float* __restrict__ k2){
    int idx = blockIdx.x*blockDim.x+threadIdx.x;
    if(idx < 19200){
        int mmq = idx%10, z = (idx/10)%60, b = idx/600;
        int mm = 9+mmq;
        const float* row = x + (b*60 + z)*60;
        u64 acc = 0;
        #pragma unroll 4
        for(int p=0;p<60;p++){
            float v = row[p];
            fma2(acc, pk2(v,v), *(const u64*)&c_tw60[mm][p]);
        }
        float2 a = u2f(acc);
        g_xfT[mm][z][b] = a;
        if(mmq > 0) g_xfT[18-mm][z][b] = make_float2(a.x, -a.y);
        return;
    }
    idx -= 19200;
    if(idx < 1000){
        int mmq = idx%10, o = idx/10;
        int mm = 9+mmq;
        const float* row = k1 + o*60;
        u64 acc = 0;
        #pragma unroll 4
        for(int p=0;p<60;p++){
            float v = row[p];
            fma2(acc, pk2(v,v), *(const u64*)&c_tw60[mm][p]);
        }
        float2 a = u2f(acc);
        g_kfc[o][mm] = make_float2(a.x*SC1V, a.y*SC1V);
        return;
    }
    idx -= 1000;
    if(idx < 180000){
        int o = idx%200, i = (idx/200)%100, mm = idx/20000;
        const float* row = k2 + (i*200+o)*20;
        u64 acc = 0;
        #pragma unroll
        for(int p=0;p<20;p++){
            float v = row[p];
            fma2(acc, pk2(v,v), *(const u64*)&c_tw20f[mm][p]);
        }
        float2 a = u2f(acc);
        g_k2f[mm][i][o] = make_float2(a.x*SC2V, a.y*SC2V);
    }
}

// ---------------- FG (xhat1 in-block) + Kp ----------------
__global__ void k_FGmid(){
    int blk = blockIdx.x;
    int t = threadIdx.x;  // 256
    if(blk >= 640){
        int o = blk - 640;
        if(t < 200){
            int np = t/20, k = t%20;
            float2 kf = g_kfc[o][np+9];
            float2 e  = c_tw20b[np+9][k];
            g_Kp[o][np][k] = make_float2(kf.x*e.x + kf.y*e.y, kf.x*e.y - kf.y*e.x);
        }
        return;
    }
    __shared__ float2 xh1s[10][19];
    __shared__ float2 Fs[19][10];
    int b = blk/20, z2 = blk%20;
    if(t < 190){
        int l = t/19, mm = t%19, m = mm-9;
        u64 acc = 0;
        if(abs(m)<=l){
            #pragma unroll 4
            for(int z=0;z<60;z++){
                float d = c_d1[l][z][mm];
                fma2(acc, pk2(d,d), *(const u64*)&g_xfT[mm][z][b]);
            }
        }
        xh1s[l][mm] = u2f(acc);
    }
    __syncthreads();
    if(t < 190){
        int mm = t%19, np = t/19, m = mm-9;
        int l0 = max(abs(m), np);
        u64 acc = 0;
        for(int l=l0;l<10;l++){
            float c = c_dh1[l][np+9]*c_dinv1p[l][z2][mm][np];
            fma2(acc, pk2(c,c), *(const u64*)&xh1s[l][mm]);
        }
        Fs[mm][np] = u2f(acc);
    }
    __syncthreads();
    if(t < 200){
        int np = t/20, j = t%20;
        u64 acc = 0;
        #pragma unroll
        for(int mm=0;mm<19;mm++){
            float2 f = Fs[mm][np];
            fma2(acc, pk2(f.x,f.x), *(const u64*)&c_tw20b[mm][j]);
            fma2(acc, pk2(f.y,f.y), *(const u64*)&c_tw20br[mm][j]);
        }
        g_G[np][b][z2][j] = u2f(acc);
    }
}

// ---------------- S2 epilogue: packed h-stage, 3 barriers/iter ----------------
__global__ void k_s2fuse(const float* __restrict__ b1){
    __shared__ float2 Kks[4][10][20];
    __shared__ float  hs[4][20][21];
    __shared__ float2 tms[4][9][20];
    __shared__ float  bs[100];
    int b = blockIdx.x/20, z2 = blockIdx.x%20;
    int t = threadIdx.x;  // 400
    int r  = t%200, tq = t/200;
    int k  = r/10,  jp = r%10;
    u64 Gx[10], Gyn[10];   // packed (j0,j1) of G.x ; negated G.y
    #pragma unroll
    for(int n=0;n<10;n++){
        float2 g0 = g_G[n][b][z2][jp];
        float2 g1 = g_G[n][b][z2][jp+10];
        Gx[n]  = pk2(g0.x, g1.x);
        Gyn[n] = pk2(-g0.y, -g1.y);
    }
    if(t < 100) bs[t] = b1[t];
    __syncthreads();
    for(int i0=0;i0<100;i0+=4){
        {
            int q0 = t/200, r0 = t%200;
            Kks[q0][r0/20][r0%20]   = g_Kp[i0+q0][r0/20][r0%20];
            Kks[q0+2][r0/20][r0%20] = g_Kp[i0+q0+2][r0/20][r0%20];
        }
        __syncthreads();
        #pragma unroll
        for(int qq=0;qq<2;qq++){
            int q = tq*2+qq;
            float2 Kv = Kks[q][0][k];
            u64 a = 0, p = 0;
            fma2(a, pk2(Kv.x,Kv.x), Gx[0]);
            fma2(a, pk2(Kv.y,Kv.y), Gyn[0]);
            #pragma unroll
            for(int n=1;n<10;n++){
                Kv = Kks[q][n][k];
                fma2(p, pk2(Kv.x,Kv.x), Gx[n]);
                fma2(p, pk2(Kv.y,Kv.y), Gyn[n]);
            }
            float2 af = u2f(a), pf = u2f(p);
            float bias = bs[i0+q];
            hs[q][jp   ][k] = fmaxf(bias + af.x + 2.f*pf.x, 0.f);
            hs[q][jp+10][k] = fmaxf(bias + af.y + 2.f*pf.y, 0.f);
        }
        __syncthreads();
        {
            int q = t/100, rr = t%100, mq = rr/20, kk = rr%20, mm = 4+mq;
            u64 acc = 0;
            #pragma unroll 4
            for(int jj=0;jj<20;jj++){
                float v = hs[q][jj][kk];
                fma2(acc, pk2(v,v), *(const u64*)&c_tw20f[mm][jj]);
            }
            float2 a = u2f(acc);
            tms[q][mm][kk] = a;
            if(mq > 0) tms[q][4-mq][kk] = make_float2(a.x, -a.y);
        }
        __syncthreads();
        if(t < 164){
            int q = t/41, mn = t%41, mm = mn/9, nn = mn%9;
            u64 acc = 0;
            #pragma unroll 4
            for(int kk=0;kk<20;kk++){
                float2 v = tms[q][mm][kk];
                fma2(acc, pk2(v.x,v.x), *(const u64*)&c_tw20f[nn][kk]);
                fma2(acc, pk2(v.y,v.y), *(const u64*)&c_tw20fr[nn][kk]);
            }
            float2 a = u2f(acc);
            g_xg[b][i0+q][z2][mn] = a;
            if(mn < 40) g_xg[b][i0+q][z2][80-mn] = make_float2(a.x, -a.y);
        }
    }
}

// ---------------- xhat2 + T2 per (b,i), half-set ----------------
__global__ void k_xh2T2(){
    __shared__ float2 xgs[20][45];
    __shared__ float2 xh[5][5][9];
    int b = blockIdx.x/100, i = blockIdx.x%100;
    int t = threadIdx.x;  // 256
    for(int idx=t; idx<900; idx+=256){
        int z = idx/45, mn = idx%45;
        xgs[z][mn] = g_xg[b][i][z][mn];
    }
    __syncthreads();
    if(t < 225){
        int l = t/45, rr = t%45, mm = rr/9, kk = rr%9;
        int m = mm-4, kq = kk-4;
        u64 acc = 0;
        if(abs(m)<=l && abs(kq)<=l){
            #pragma unroll 4
            for(int z=0;z<20;z++){
                float d = c_d2[l][z][mm][kk];
                fma2(acc, pk2(d,d), *(const u64*)&xgs[z][mm*9+kk]);
            }
        }
        xh[l][mm][kk] = u2f(acc);
    }
    __syncthreads();
    if(t < 205){
        int l = t/41, mn = t%41, mm = mn/9, nn = mn%9;
        u64 acc = 0;
        #pragma unroll
        for(int kk=0;kk<9;kk++){
            float d = c_dh2[l][nn][kk];
            fma2(acc, pk2(d,d), *(const u64*)&xh[l][mm][kk]);
        }
        g_T2[l][mn][b][i] = u2f(acc);
    }
}

// ---------------- z2: half-set GEMM, b-split x2, packed ----------------
__global__ void k_z2(){
    __shared__ float2 Ts[16][100];
    int blk = blockIdx.x;
    int bh = blk/205, lh = blk%205;
    int l = lh/41, h = lh%41;
    int mm = h/9, nn = h%9;
    int m = mm-4, n = nn-4;
    int t = threadIdx.x;  // 256
    if(l < max(abs(m),abs(n))) return;
    const float2* src = &g_T2[l][h][bh*16][0];
    for(int idx=t; idx<1600; idx+=256) (&Ts[0][0])[idx] = src[idx];
    __syncthreads();
    if(t < 200){
        int bq = t/100, op = t%100;
        float sg = ((mm+nn)&1) ? -1.f : 1.f;
        int idx0 = l*81 + h, idx1 = l*81 + (80-h);
        int bb0 = bq*8;
        u64 a0[8], a1[8];
        #pragma unroll
        for(int rr=0;rr<8;rr++){ a0[rr]=0; a1[rr]=0; }
        for(int i=0;i<100;i++){
            float2 kf0 = g_k2f[nn][i][op];
            float2 kf1 = g_k2f[nn][i][op+100];
            u64 ka0 = pk2(kf0.x,-kf0.y), kb0 = pk2(kf0.y,kf0.x);
            u64 ka1 = pk2(kf1.x,-kf1.y), kb1 = pk2(kf1.y,kf1.x);
            #pragma unroll
            for(int rr=0;rr<8;rr++){
                float2 Tv = Ts[bb0+rr][i];
                u64 tx = pk2(Tv.x,Tv.x), ty = pk2(Tv.y,Tv.y);
                fma2(a0[rr], tx, ka0); fma2(a0[rr], ty, kb0);
                fma2(a1[rr], tx, ka1); fma2(a1[rr], ty, kb1);
            }
        }
        #pragma unroll
        for(int rr=0;rr<8;rr++){
            int bb = bh*16 + bb0 + rr;
            float2 v0 = u2f(a0[rr]), v1 = u2f(a1[rr]);
            g_z2t[bb][op    ][idx0] = v0;
            g_z2t[bb][op+100][idx0] = v1;
            if(h < 40){
                g_z2t[bb][op    ][idx1] = make_float2(sg*v0.x, -sg*v0.y);
                g_z2t[bb][op+100][idx1] = make_float2(sg*v1.x, -sg*v1.y);
            }
        }
    }
}

// ---------------- out2: packed stages + fused final via atomics ----------------
__global__ void k_out2(const float* __restrict__ b2, const float* __restrict__ W,
                       float* __restrict__ out){
    __shared__ float2 zs[405];
    __shared__ float2 g2a[10][81];
    __shared__ float2 tma[10][5][10];
    __shared__ float  wsum[8];
    int b = blockIdx.x/200, o = blockIdx.x%200;
    int t = threadIdx.x;  // 256
    for(int idx=t; idx<405; idx+=256){
        int l = idx/81, mn = idx%81, m = mn/9-4, n = mn%9-4;
        zs[idx] = (l >= max(abs(m),abs(n))) ? g_z2t[b][o][idx] : make_float2(0.f,0.f);
    }
    float b2v = b2[o];
    __syncthreads();
    for(int idx=t; idx<410; idx+=256){
        int z3 = idx/41, mn = idx%41, mm = mn/9, nn = mn%9;
        int m = mm-4, n = nn-4;
        int l0 = max(abs(m),abs(n));
        u64 acc = 0;
        for(int l=l0;l<5;l++){
            float d = c_dinv2[l][z3][mm][nn];
            fma2(acc, pk2(d,d), *(const u64*)&zs[l*81+mn]);
        }
        float2 a = u2f(acc);
        g2a[z3][mn] = a;
        g2a[z3][80-mn] = make_float2(a.x, -a.y);
    }
    __syncthreads();
    for(int idx=t; idx<500; idx+=256){
        int z3 = idx/50, rr = idx%50, mq = rr/10, k = rr%10;
        int mm = 4+mq;
        u64 acc = 0;
        #pragma unroll
        for(int nn=0;nn<9;nn++){
            float2 v = g2a[z3][mm*9+nn];
            fma2(acc, pk2(v.x,v.x), *(const u64*)&c_tw10b[nn][k]);
            fma2(acc, pk2(v.y,v.y), *(const u64*)&c_tw10br[nn][k]);
        }
        tma[z3][mq][k] = u2f(acc);
    }
    __syncthreads();
    float psum = 0.f;
    for(int idx=t; idx<1000; idx+=256){
        int z3 = idx/100, rr = idx%100, j = rr/10, k = rr%10;
        float v = tma[z3][0][k].x;
        #pragma unroll
        for(int mq=1;mq<5;mq++){
            float2 a = tma[z3][mq][k]; float2 e = c_tw10b[4+mq][j];
            v += 2.f*(a.x*e.x - a.y*e.y);
        }
        v = fmaxf(v + b2v, 0.f);
        psum += v * c_w5[z3];
    }
    #pragma unroll
    for(int off=16; off; off>>=1) psum += __shfl_xor_sync(0xFFFFFFFFu, psum, off);
    if((t&31) == 0) wsum[t>>5] = psum;
    __syncthreads();
    if(t == 0){
        float s = 0.f;
        #pragma unroll
        for(int w=0;w<8;w++) s += wsum[w];
        #pragma unroll
        for(int f=0;f<10;f++) atomicAdd(&out[b*10+f], s*W[f*200+o]);
    }
}

extern "C" void kernel_launch(void* const* d_in, const int* in_sizes, int n_in,
                              void* d_out, int out_size){
    const float* x  = (const float*)d_in[0];
    const float* k1 = (const float*)d_in[1];
    const float* b1 = (const float*)d_in[2];
    const float* k2 = (const float*)d_in[3];
    const float* b2 = (const float*)d_in[4];
    const float* W  = (const float*)d_in[5];
    const float* bl = (const float*)d_in[6];
    float* out = (float*)d_out;

    k_init  <<<128,256>>>(bl,out);
    k_dfts  <<<(19200+1000+180000+255)/256,256>>>(x,k1,k2);
    k_FGmid <<<740,256>>>();
    k_s2fuse<<<640,400>>>(b1);
    k_xh2T2 <<<3200,256>>>();
    k_z2    <<<410,256>>>();
    k_out2  <<<6400,256>>>(b2,W,out);
}

// round 9
// speedup vs baseline: 3.4179x; 1.0427x over previous
#include <cuda_runtime.h>
#include <math.h>

#define PI_D 3.14159265358979323846
#define SC1V 0.03872983346207417f   /* 1/sqrt(2000/3) */
#define SC2V 0.06324555320336759f   /* 1/sqrt(250)    */

typedef unsigned long long u64;

// packed f32x2 helpers
__device__ __forceinline__ float2 u2f(u64 v){ float2 r; asm("mov.b64 {%0,%1}, %2;":"=f"(r.x),"=f"(r.y):"l"(v)); return r; }
__device__ __forceinline__ u64 pk2(float a, float b){ u64 r; asm("mov.b64 %0, {%1,%2};":"=l"(r):"f"(a),"f"(b)); return r; }
__device__ __forceinline__ void fma2(u64 &acc, u64 a, u64 b){
    asm("fma.rn.f32x2 %0, %1, %2, %3;" : "=l"(acc) : "l"(a), "l"(b), "l"(acc));
}

// ---------------- constant tables (device-computed) ----------------
__device__ float  c_d1[10][60][19];
__device__ float  c_dh1[10][19];
__device__ float  c_dinv1p[10][20][19][10];
__device__ float  c_d2[5][20][9][9];
__device__ float  c_dh2[5][9][9];
__device__ float  c_dinv2[5][10][9][9];
__device__ float  c_w5[10];
__device__ float2 c_tw60[19][60];                 // e^{-2pi i m p/60}
__device__ float2 c_tw20b[19][20];                // e^{+2pi i m j/20}
__device__ float2 c_tw20br[19][20];               // rotated (-y,x)
__device__ __align__(16) float2 c_tw20f[9][20];   // e^{-2pi i m k/20}
__device__ __align__(16) float2 c_tw20fr[9][20];  // rotated
__device__ float2 c_tw10b[9][10];                 // e^{+2pi i m j/10}
__device__ float2 c_tw10br[9][10];                // rotated

__constant__ double c_fct[20] = {1.,1.,2.,6.,24.,120.,720.,5040.,40320.,362880.,
    3628800.,39916800.,479001600.,6227020800.,87178291200.,1307674368000.,
    20922789888000.,355687428096000.,6402373705728000.,121645100408832000.};

// ---------------- scratch ----------------
__device__ float2 g_xfT[19][60][32];
__device__ float2 g_kfc[100][19];
__device__ float2 g_Kp[100][10][20];
__device__ float2 g_G[10][32][20][20];
__device__ float2 g_xg[32][100][20][81];
__device__ float2 g_k2f[9][100][200];
__device__ float2 g_T2[5][41][32][100];
__device__ float2 g_z2t[32][200][405];

// ---------------- Wigner-d from precomputed half-angle cos/sin ----------------
__device__ double dev_wigner_cs(int l, int m, int n, double cb, double sb, const double* ifct){
    double pref = sqrt(c_fct[l+m]*c_fct[l-m]*c_fct[l+n]*c_fct[l-n]);
    int s0 = (n-m > 0) ? (n-m) : 0;
    int s1 = (l+n < l-m) ? (l+n) : (l-m);
    if(s1 < s0) return 0.0;
    int e0 = 2*l+n-m-2*s0, f0 = m-n+2*s0;
    double cbe = 1.0; for(int i=0;i<e0;i++) cbe *= cb;
    double sbf = 1.0; for(int i=0;i<f0;i++) sbf *= sb;
    double r  = (sb*sb)/(cb*cb);
    double pw = cbe*sbf;
    double acc = 0.0;
    for(int s=s0;s<=s1;s++){
        double deni = ifct[l+n-s]*ifct[s]*ifct[m-n+s]*ifct[l-m-s];
        double sg   = ((m-n+s)&1) ? -1.0 : 1.0;
        acc += sg*pw*deni;
        pw *= r;
    }
    return pref*acc;
}

__device__ double dev_qw(int b, int j){
    double beta = PI_D*(2*j+1)/(4.0*b);
    double s=0.0;
    for(int k=1;k<2*b;k+=2) s += sin(k*beta)/(double)k;
    return 2.0/b*sin(beta)*s;
}

// ---------------- init: output reset + per-block smem weights + all tables ----------------
__global__ void k_init(const float* __restrict__ bl, float* __restrict__ out){
    {
        int gi = blockIdx.x*blockDim.x + threadIdx.x;
        if(gi < 320) out[gi] = bl[gi%10];
    }
    __shared__ double s_w30[60], s_w10[20];
    __shared__ float  s_w5f[10];
    __shared__ double cb120[60], sb120[60], cb40[20], sb40[20], cb20[10], sb20[10];
    __shared__ double s_ifct[20];
    int tt = threadIdx.x;
    if(tt < 60){ s_w30[tt]=dev_qw(30,tt); double a=PI_D*(2*tt+1)/240.0; cb120[tt]=cos(a); sb120[tt]=sin(a); }
    else if(tt < 80){ int z=tt-60; s_w10[z]=dev_qw(10,z); double a=PI_D*(2*z+1)/80.0; cb40[z]=cos(a); sb40[z]=sin(a); }
    else if(tt < 90){ int z=tt-80; s_w5f[z]=(float)dev_qw(5,z); double a=PI_D*(2*z+1)/40.0; cb20[z]=cos(a); sb20[z]=sin(a); }
    else if(tt < 110){ s_ifct[tt-90] = 1.0/c_fct[tt-90]; }
    __syncthreads();
    const double cbh = 0.70710678118654752, sbh = 0.70710678118654752;
    const int total = 11400+190+38000+8100+405+4050+1140+380+180+90+10;
    for(int idx = blockIdx.x*blockDim.x+threadIdx.x; idx<total; idx += gridDim.x*blockDim.x){
        int t = idx;
        if(t < 11400){ int l=t/1140, r=t%1140, z=r/19, mm=r%19, m=mm-9;
            c_d1[l][z][mm] = (abs(m)<=l) ? (float)(dev_wigner_cs(l,m,0,cb120[z],sb120[z],s_ifct)*s_w30[z]) : 0.f;
            continue; }
        t -= 11400;
        if(t < 190){ int l=t/19, mm=t%19, m=mm-9;
            c_dh1[l][mm] = (abs(m)<=l) ? (float)dev_wigner_cs(l,m,0,cbh,sbh,s_ifct) : 0.f; continue; }
        t -= 190;
        if(t < 38000){ int l=t/3800, r=t%3800, z=r/190, mm=(r%190)/10, np=r%10, m=mm-9;
            c_dinv1p[l][z][mm][np] = (abs(m)<=l && np<=l) ? (float)((2*l+1)*dev_wigner_cs(l,m,np,cb40[z],sb40[z],s_ifct)) : 0.f;
            continue; }
        t -= 38000;
        if(t < 8100){ int l=t/1620, r=t%1620, z=r/81, mm=(r%81)/9, nn=r%9, m=mm-4, n=nn-4;
            c_d2[l][z][mm][nn] = (abs(m)<=l && abs(n)<=l) ? (float)(dev_wigner_cs(l,m,n,cb40[z],sb40[z],s_ifct)*s_w10[z]) : 0.f;
            continue; }
        t -= 8100;
        if(t < 405){ int l=t/81, mm=(t%81)/9, nn=t%9, m=mm-4, n=nn-4;
            c_dh2[l][mm][nn] = (abs(m)<=l && abs(n)<=l) ? (float)dev_wigner_cs(l,m,n,cbh,sbh,s_ifct) : 0.f; continue; }
        t -= 405;
        if(t < 4050){ int l=t/810, r=t%810, z=r/81, mm=(r%81)/9, nn=r%9, m=mm-4, n=nn-4;
            c_dinv2[l][z][mm][nn] = (abs(m)<=l && abs(n)<=l) ? (float)((2*l+1)*dev_wigner_cs(l,m,n,cb20[z],sb20[z],s_ifct)) : 0.f;
            continue; }
        t -= 4050;
        if(t < 1140){ int mm=t/60, p=t%60; double a = -2.0*PI_D*(double)(mm-9)*(double)p/60.0;
            c_tw60[mm][p] = make_float2((float)cos(a),(float)sin(a)); continue; }
        t -= 1140;
        if(t < 380){ int mm=t/20, j=t%20; double a = 2.0*PI_D*(double)(mm-9)*(double)j/20.0;
            float cx=(float)cos(a), cy=(float)sin(a);
            c_tw20b[mm][j]  = make_float2(cx,cy);
            c_tw20br[mm][j] = make_float2(-cy,cx);
            continue; }
        t -= 380;
        if(t < 180){ int mm=t/20, k=t%20; double a = -2.0*PI_D*(double)(mm-4)*(double)k/20.0;
            float cx=(float)cos(a), cy=(float)sin(a);
            c_tw20f[mm][k]  = make_float2(cx,cy);
            c_tw20fr[mm][k] = make_float2(-cy,cx);
            continue; }
        t -= 180;
        if(t < 90){ int mm=t/10, j=t%10; double a = 2.0*PI_D*(double)(mm-4)*(double)j/10.0;
            float cx=(float)cos(a), cy=(float)sin(a);
            c_tw10b[mm][j]  = make_float2(cx,cy);
            c_tw10br[mm][j] = make_float2(-cy,cx);
            continue; }
        t -= 90;
        { c_w5[t] = s_w5f[t]; }
    }
}

// ---------------- input DFTs (Hermitian-folded, f32x2) ----------------
__global__ void k_dfts(const float* __restrict__ x, const float* __restrict__ k1,
                       const float* __restrict__ k2){
    int idx = blockIdx.x*blockDim.x+threadIdx.x;
    if(idx < 19200){
        int mmq = idx%10, z = (idx/10)%60, b = idx/600;
        int mm = 9+mmq;
        const float* row = x + (b*60 + z)*60;
        u64 acc = 0;
        #pragma unroll 4
        for(int p=0;p<60;p++){
            float v = row[p];
            fma2(acc, pk2(v,v), *(const u64*)&c_tw60[mm][p]);
        }
        float2 a = u2f(acc);
        g_xfT[mm][z][b] = a;
        if(mmq > 0) g_xfT[18-mm][z][b] = make_float2(a.x, -a.y);
        return;
    }
    idx -= 19200;
    if(idx < 1000){
        int mmq = idx%10, o = idx/10;
        int mm = 9+mmq;
        const float* row = k1 + o*60;
        u64 acc = 0;
        #pragma unroll 4
        for(int p=0;p<60;p++){
            float v = row[p];
            fma2(acc, pk2(v,v), *(const u64*)&c_tw60[mm][p]);
        }
        float2 a = u2f(acc);
        g_kfc[o][mm] = make_float2(a.x*SC1V, a.y*SC1V);
        return;
    }
    idx -= 1000;
    if(idx < 180000){
        int o = idx%200, i = (idx/200)%100, mm = idx/20000;
        const float* row = k2 + (i*200+o)*20;
        u64 acc = 0;
        #pragma unroll
        for(int p=0;p<20;p++){
            float v = row[p];
            fma2(acc, pk2(v,v), *(const u64*)&c_tw20f[mm][p]);
        }
        float2 a = u2f(acc);
        g_k2f[mm][i][o] = make_float2(a.x*SC2V, a.y*SC2V);
    }
}

// ---------------- FG (xhat1 in-block) + Kp ----------------
__global__ void k_FGmid(){
    int blk = blockIdx.x;
    int t = threadIdx.x;  // 256
    if(blk >= 640){
        int o = blk - 640;
        if(t < 200){
            int np = t/20, k = t%20;
            float2 kf = g_kfc[o][np+9];
            float2 e  = c_tw20b[np+9][k];
            g_Kp[o][np][k] = make_float2(kf.x*e.x + kf.y*e.y, kf.x*e.y - kf.y*e.x);
        }
        return;
    }
    __shared__ float2 xh1s[10][19];
    __shared__ float2 Fs[19][10];
    int b = blk/20, z2 = blk%20;
    if(t < 190){
        int l = t/19, mm = t%19, m = mm-9;
        u64 acc = 0;
        if(abs(m)<=l){
            #pragma unroll 4
            for(int z=0;z<60;z++){
                float d = c_d1[l][z][mm];
                fma2(acc, pk2(d,d), *(const u64*)&g_xfT[mm][z][b]);
            }
        }
        xh1s[l][mm] = u2f(acc);
    }
    __syncthreads();
    if(t < 190){
        int mm = t%19, np = t/19, m = mm-9;
        int l0 = max(abs(m), np);
        u64 acc = 0;
        for(int l=l0;l<10;l++){
            float c = c_dh1[l][np+9]*c_dinv1p[l][z2][mm][np];
            fma2(acc, pk2(c,c), *(const u64*)&xh1s[l][mm]);
        }
        Fs[mm][np] = u2f(acc);
    }
    __syncthreads();
    if(t < 200){
        int np = t/20, j = t%20;
        u64 acc = 0;
        #pragma unroll
        for(int mm=0;mm<19;mm++){
            float2 f = Fs[mm][np];
            fma2(acc, pk2(f.x,f.x), *(const u64*)&c_tw20b[mm][j]);
            fma2(acc, pk2(f.y,f.y), *(const u64*)&c_tw20br[mm][j]);
        }
        g_G[np][b][z2][j] = u2f(acc);
    }
}

// ---------------- S2 epilogue: transposed hs + float4 DFT stages, i-split x2 ----------------
__global__ void __launch_bounds__(400,2) k_s2fuse(const float* __restrict__ b1){
    __shared__ float2 Kks[4][10][20];
    __shared__ __align__(16) float  hs[4][20][20];   // [q][k][j] (transposed)
    __shared__ __align__(16) float2 tms[4][9][20];
    __shared__ float  bs[100];
    int bb = blockIdx.x;
    int b = bb/40, z2 = (bb%40)>>1, ih = bb&1;
    int t = threadIdx.x;  // 400
    int r  = t%200, tq = t/200;
    int k  = r/10,  jp = r%10;
    u64 Gx[10], Gyn[10];   // packed (j0,j1) of G.x ; negated G.y
    #pragma unroll
    for(int n=0;n<10;n++){
        float2 g0 = g_G[n][b][z2][jp];
        float2 g1 = g_G[n][b][z2][jp+10];
        Gx[n]  = pk2(g0.x, g1.x);
        Gyn[n] = pk2(-g0.y, -g1.y);
    }
    if(t < 100) bs[t] = b1[t];
    __syncthreads();
    int istart = ih*52, iend = istart ? 100 : 52;
    for(int i0=istart;i0<iend;i0+=4){
        {
            int q0 = t/200, r0 = t%200;
            Kks[q0][r0/20][r0%20]   = g_Kp[i0+q0][r0/20][r0%20];
            Kks[q0+2][r0/20][r0%20] = g_Kp[i0+q0+2][r0/20][r0%20];
        }
        __syncthreads();
        // h-stage: 2q x 2j per thread; write transposed hs[q][k][j]
        #pragma unroll
        for(int qq=0;qq<2;qq++){
            int q = tq*2+qq;
            float2 Kv = Kks[q][0][k];
            u64 a = 0, p = 0;
            fma2(a, pk2(Kv.x,Kv.x), Gx[0]);
            fma2(a, pk2(Kv.y,Kv.y), Gyn[0]);
            #pragma unroll
            for(int n=1;n<10;n++){
                Kv = Kks[q][n][k];
                fma2(p, pk2(Kv.x,Kv.x), Gx[n]);
                fma2(p, pk2(Kv.y,Kv.y), Gyn[n]);
            }
            float2 af = u2f(a), pf = u2f(p);
            float bias = bs[i0+q];
            hs[q][k][jp   ] = fmaxf(bias + af.x + 2.f*pf.x, 0.f);
            hs[q][k][jp+10] = fmaxf(bias + af.y + 2.f*pf.y, 0.f);
        }
        __syncthreads();
        // st1: m>=0 (mm=4..8); hs row contiguous -> 5 LDS.128; twiddle 2 LDG.128/chunk
        {
            int q = t/100, rr = t%100, mq = rr/20, kk = rr%20, mm = 4+mq;
            const float4* hrow  = (const float4*)&hs[q][kk][0];
            const float4* twrow = (const float4*)&c_tw20f[mm][0];
            u64 acc = 0;
            #pragma unroll
            for(int c=0;c<5;c++){
                float4 h4  = hrow[c];
                float4 e01 = twrow[2*c];
                float4 e23 = twrow[2*c+1];
                fma2(acc, pk2(h4.x,h4.x), pk2(e01.x,e01.y));
                fma2(acc, pk2(h4.y,h4.y), pk2(e01.z,e01.w));
                fma2(acc, pk2(h4.z,h4.z), pk2(e23.x,e23.y));
                fma2(acc, pk2(h4.w,h4.w), pk2(e23.z,e23.w));
            }
            float2 a = u2f(acc);
            tms[q][mm][kk] = a;
            if(mq > 0) tms[q][4-mq][kk] = make_float2(a.x, -a.y);
        }
        __syncthreads();
        // st2: half-set mn in [0,40]; tms row contiguous -> 10 LDS.128
        if(t < 164){
            int q = t/41, mn = t%41, mm = mn/9, nn = mn%9;
            const float4* trow = (const float4*)&tms[q][mm][0];
            const float4* twf  = (const float4*)&c_tw20f[nn][0];
            const float4* twr  = (const float4*)&c_tw20fr[nn][0];
            u64 acc = 0;
            #pragma unroll
            for(int c=0;c<10;c++){
                float4 v  = trow[c];
                float4 e  = twf[c];
                float4 er = twr[c];
                fma2(acc, pk2(v.x,v.x), pk2(e.x,e.y));
                fma2(acc, pk2(v.y,v.y), pk2(er.x,er.y));
                fma2(acc, pk2(v.z,v.z), pk2(e.z,e.w));
                fma2(acc, pk2(v.w,v.w), pk2(er.z,er.w));
            }
            float2 a = u2f(acc);
            g_xg[b][i0+q][z2][mn] = a;
            if(mn < 40) g_xg[b][i0+q][z2][80-mn] = make_float2(a.x, -a.y);
        }
    }
}

// ---------------- xhat2 + T2 per (b,i), half-set ----------------
__global__ void k_xh2T2(){
    __shared__ float2 xgs[20][45];
    __shared__ float2 xh[5][5][9];
    int b = blockIdx.x/100, i = blockIdx.x%100;
    int t = threadIdx.x;  // 256
    for(int idx=t; idx<900; idx+=256){
        int z = idx/45, mn = idx%45;
        xgs[z][mn] = g_xg[b][i][z][mn];
    }
    __syncthreads();
    if(t < 225){
        int l = t/45, rr = t%45, mm = rr/9, kk = rr%9;
        int m = mm-4, kq = kk-4;
        u64 acc = 0;
        if(abs(m)<=l && abs(kq)<=l){
            #pragma unroll 4
            for(int z=0;z<20;z++){
                float d = c_d2[l][z][mm][kk];
                fma2(acc, pk2(d,d), *(const u64*)&xgs[z][mm*9+kk]);
            }
        }
        xh[l][mm][kk] = u2f(acc);
    }
    __syncthreads();
    if(t < 205){
        int l = t/41, mn = t%41, mm = mn/9, nn = mn%9;
        u64 acc = 0;
        #pragma unroll
        for(int kk=0;kk<9;kk++){
            float d = c_dh2[l][nn][kk];
            fma2(acc, pk2(d,d), *(const u64*)&xh[l][mm][kk]);
        }
        g_T2[l][mn][b][i] = u2f(acc);
    }
}

// ---------------- z2: half-set GEMM, b-split x2, packed ----------------
__global__ void k_z2(){
    __shared__ float2 Ts[16][100];
    int blk = blockIdx.x;
    int bh = blk/205, lh = blk%205;
    int l = lh/41, h = lh%41;
    int mm = h/9, nn = h%9;
    int m = mm-4, n = nn-4;
    int t = threadIdx.x;  // 256
    if(l < max(abs(m),abs(n))) return;
    const float2* src = &g_T2[l][h][bh*16][0];
    for(int idx=t; idx<1600; idx+=256) (&Ts[0][0])[idx] = src[idx];
    __syncthreads();
    if(t < 200){
        int bq = t/100, op = t%100;
        float sg = ((mm+nn)&1) ? -1.f : 1.f;
        int idx0 = l*81 + h, idx1 = l*81 + (80-h);
        int bb0 = bq*8;
        u64 a0[8], a1[8];
        #pragma unroll
        for(int rr=0;rr<8;rr++){ a0[rr]=0; a1[rr]=0; }
        for(int i=0;i<100;i++){
            float2 kf0 = g_k2f[nn][i][op];
            float2 kf1 = g_k2f[nn][i][op+100];
            u64 ka0 = pk2(kf0.x,-kf0.y), kb0 = pk2(kf0.y,kf0.x);
            u64 ka1 = pk2(kf1.x,-kf1.y), kb1 = pk2(kf1.y,kf1.x);
            #pragma unroll
            for(int rr=0;rr<8;rr++){
                float2 Tv = Ts[bb0+rr][i];
                u64 tx = pk2(Tv.x,Tv.x), ty = pk2(Tv.y,Tv.y);
                fma2(a0[rr], tx, ka0); fma2(a0[rr], ty, kb0);
                fma2(a1[rr], tx, ka1); fma2(a1[rr], ty, kb1);
            }
        }
        #pragma unroll
        for(int rr=0;rr<8;rr++){
            int bb = bh*16 + bb0 + rr;
            float2 v0 = u2f(a0[rr]), v1 = u2f(a1[rr]);
            g_z2t[bb][op    ][idx0] = v0;
            g_z2t[bb][op+100][idx0] = v1;
            if(h < 40){
                g_z2t[bb][op    ][idx1] = make_float2(sg*v0.x, -sg*v0.y);
                g_z2t[bb][op+100][idx1] = make_float2(sg*v1.x, -sg*v1.y);
            }
        }
    }
}

// ---------------- out2: packed stages + fused final via atomics ----------------
__global__ void k_out2(const float* __restrict__ b2, const float* __restrict__ W,
                       float* __restrict__ out){
    __shared__ float2 zs[405];
    __shared__ float2 g2a[10][81];
    __shared__ float2 tma[10][5][10];
    __shared__ float  wsum[8];
    int b = blockIdx.x/200, o = blockIdx.x%200;
    int t = threadIdx.x;  // 256
    for(int idx=t; idx<405; idx+=256){
        int l = idx/81, mn = idx%81, m = mn/9-4, n = mn%9-4;
        zs[idx] = (l >= max(abs(m),abs(n))) ? g_z2t[b][o][idx] : make_float2(0.f,0.f);
    }
    float b2v = b2[o];
    __syncthreads();
    for(int idx=t; idx<410; idx+=256){
        int z3 = idx/41, mn = idx%41, mm = mn/9, nn = mn%9;
        int m = mm-4, n = nn-4;
        int l0 = max(abs(m),abs(n));
        u64 acc = 0;
        for(int l=l0;l<5;l++){
            float d = c_dinv2[l][z3][mm][nn];
            fma2(acc, pk2(d,d), *(const u64*)&zs[l*81+mn]);
        }
        float2 a = u2f(acc);
        g2a[z3][mn] = a;
        g2a[z3][80-mn] = make_float2(a.x, -a.y);
    }
    __syncthreads();
    for(int idx=t; idx<500; idx+=256){
        int z3 = idx/50, rr = idx%50, mq = rr/10, k = rr%10;
        int mm = 4+mq;
        u64 acc = 0;
        #pragma unroll
        for(int nn=0;nn<9;nn++){
            float2 v = g2a[z3][mm*9+nn];
            fma2(acc, pk2(v.x,v.x), *(const u64*)&c_tw10b[nn][k]);
            fma2(acc, pk2(v.y,v.y), *(const u64*)&c_tw10br[nn][k]);
        }
        tma[z3][mq][k] = u2f(acc);
    }
    __syncthreads();
    float psum = 0.f;
    for(int idx=t; idx<1000; idx+=256){
        int z3 = idx/100, rr = idx%100, j = rr/10, k = rr%10;
        float v = tma[z3][0][k].x;
        #pragma unroll
        for(int mq=1;mq<5;mq++){
            float2 a = tma[z3][mq][k]; float2 e = c_tw10b[4+mq][j];
            v += 2.f*(a.x*e.x - a.y*e.y);
        }
        v = fmaxf(v + b2v, 0.f);
        psum += v * c_w5[z3];
    }
    #pragma unroll
    for(int off=16; off; off>>=1) psum += __shfl_xor_sync(0xFFFFFFFFu, psum, off);
    if((t&31) == 0) wsum[t>>5] = psum;
    __syncthreads();
    if(t == 0){
        float s = 0.f;
        #pragma unroll
        for(int w=0;w<8;w++) s += wsum[w];
        #pragma unroll
        for(int f=0;f<10;f++) atomicAdd(&out[b*10+f], s*W[f*200+o]);
    }
}

extern "C" void kernel_launch(void* const* d_in, const int* in_sizes, int n_in,
                              void* d_out, int out_size){
    const float* x  = (const float*)d_in[0];
    const float* k1 = (const float*)d_in[1];
    const float* b1 = (const float*)d_in[2];
    const float* k2 = (const float*)d_in[3];
    const float* b2 = (const float*)d_in[4];
    const float* W  = (const float*)d_in[5];
    const float* bl = (const float*)d_in[6];
    float* out = (float*)d_out;

    k_init  <<<128,256>>>(bl,out);
    k_dfts  <<<(19200+1000+180000+255)/256,256>>>(x,k1,k2);
    k_FGmid <<<740,256>>>();
    k_s2fuse<<<1280,400>>>(b1);
    k_xh2T2 <<<3200,256>>>();
    k_z2    <<<410,256>>>();
    k_out2  <<<6400,256>>>(b2,W,out);
}

// round 10
// speedup vs baseline: 3.7011x; 1.0829x over previous
#include <cuda_runtime.h>
#include <math.h>

#define PI_D 3.14159265358979323846
#define SC1V 0.03872983346207417f   /* 1/sqrt(2000/3) */
#define SC2V 0.06324555320336759f   /* 1/sqrt(250)    */

typedef unsigned long long u64;

// packed f32x2 helpers
__device__ __forceinline__ float2 u2f(u64 v){ float2 r; asm("mov.b64 {%0,%1}, %2;":"=f"(r.x),"=f"(r.y):"l"(v)); return r; }
__device__ __forceinline__ u64 pk2(float a, float b){ u64 r; asm("mov.b64 %0, {%1,%2};":"=l"(r):"f"(a),"f"(b)); return r; }
__device__ __forceinline__ void fma2(u64 &acc, u64 a, u64 b){
    asm("fma.rn.f32x2 %0, %1, %2, %3;" : "=l"(acc) : "l"(a), "l"(b), "l"(acc));
}

// ---------------- constant tables (device-computed) ----------------
__device__ float  c_d1[10][60][19];
__device__ float  c_dh1[10][19];
__device__ float  c_dinv1p[10][20][19][10];
__device__ float  c_d2[5][20][9][9];
__device__ float  c_dh2[5][9][9];
__device__ float  c_dinv2[5][10][9][9];
__device__ float  c_w5[10];
__device__ float2 c_tw60[19][60];                 // e^{-2pi i m p/60}
__device__ float2 c_tw20b[19][20];                // e^{+2pi i m j/20}
__device__ float2 c_tw20br[19][20];               // rotated (-y,x)
__device__ __align__(16) float2 c_tw20f[9][20];   // e^{-2pi i m k/20}
__device__ __align__(16) float2 c_tw20fr[9][20];  // rotated
__device__ float2 c_tw10b[9][10];                 // e^{+2pi i m j/10}
__device__ float2 c_tw10br[9][10];                // rotated

__constant__ double c_fct[20] = {1.,1.,2.,6.,24.,120.,720.,5040.,40320.,362880.,
    3628800.,39916800.,479001600.,6227020800.,87178291200.,1307674368000.,
    20922789888000.,355687428096000.,6402373705728000.,121645100408832000.};

// ---------------- scratch ----------------
__device__ float2 g_xfT[19][60][32];
__device__ float2 g_kfc[100][19];
__device__ __align__(16) float2 g_Kp[100][20][10];   // [i][k][n]  (n contiguous!)
__device__ float2 g_G[10][32][20][20];
__device__ float2 g_xg[32][100][20][81];
__device__ float2 g_k2f[9][100][200];
__device__ float2 g_T2[5][41][32][100];
__device__ float2 g_z2t[32][200][405];

// ---------------- Wigner-d from precomputed half-angle cos/sin ----------------
__device__ double dev_wigner_cs(int l, int m, int n, double cb, double sb, const double* ifct){
    double pref = sqrt(c_fct[l+m]*c_fct[l-m]*c_fct[l+n]*c_fct[l-n]);
    int s0 = (n-m > 0) ? (n-m) : 0;
    int s1 = (l+n < l-m) ? (l+n) : (l-m);
    if(s1 < s0) return 0.0;
    int e0 = 2*l+n-m-2*s0, f0 = m-n+2*s0;
    double cbe = 1.0; for(int i=0;i<e0;i++) cbe *= cb;
    double sbf = 1.0; for(int i=0;i<f0;i++) sbf *= sb;
    double r  = (sb*sb)/(cb*cb);
    double pw = cbe*sbf;
    double acc = 0.0;
    for(int s=s0;s<=s1;s++){
        double deni = ifct[l+n-s]*ifct[s]*ifct[m-n+s]*ifct[l-m-s];
        double sg   = ((m-n+s)&1) ? -1.0 : 1.0;
        acc += sg*pw*deni;
        pw *= r;
    }
    return pref*acc;
}

__device__ double dev_qw(int b, int j){
    double beta = PI_D*(2*j+1)/(4.0*b);
    double s=0.0;
    for(int k=1;k<2*b;k+=2) s += sin(k*beta)/(double)k;
    return 2.0/b*sin(beta)*s;
}

// ---------------- init: output reset + per-block smem weights + all tables ----------------
__global__ void k_init(const float* __restrict__ bl, float* __restrict__ out){
    {
        int gi = blockIdx.x*blockDim.x + threadIdx.x;
        if(gi < 320) out[gi] = bl[gi%10];
    }
    __shared__ double s_w30[60], s_w10[20];
    __shared__ float  s_w5f[10];
    __shared__ double cb120[60], sb120[60], cb40[20], sb40[20], cb20[10], sb20[10];
    __shared__ double s_ifct[20];
    int tt = threadIdx.x;
    if(tt < 60){ s_w30[tt]=dev_qw(30,tt); double a=PI_D*(2*tt+1)/240.0; cb120[tt]=cos(a); sb120[tt]=sin(a); }
    else if(tt < 80){ int z=tt-60; s_w10[z]=dev_qw(10,z); double a=PI_D*(2*z+1)/80.0; cb40[z]=cos(a); sb40[z]=sin(a); }
    else if(tt < 90){ int z=tt-80; s_w5f[z]=(float)dev_qw(5,z); double a=PI_D*(2*z+1)/40.0; cb20[z]=cos(a); sb20[z]=sin(a); }
    else if(tt < 110){ s_ifct[tt-90] = 1.0/c_fct[tt-90]; }
    __syncthreads();
    const double cbh = 0.70710678118654752, sbh = 0.70710678118654752;
    const int total = 11400+190+38000+8100+405+4050+1140+380+180+90+10;
    for(int idx = blockIdx.x*blockDim.x+threadIdx.x; idx<total; idx += gridDim.x*blockDim.x){
        int t = idx;
        if(t < 11400){ int l=t/1140, r=t%1140, z=r/19, mm=r%19, m=mm-9;
            c_d1[l][z][mm] = (abs(m)<=l) ? (float)(dev_wigner_cs(l,m,0,cb120[z],sb120[z],s_ifct)*s_w30[z]) : 0.f;
            continue; }
        t -= 11400;
        if(t < 190){ int l=t/19, mm=t%19, m=mm-9;
            c_dh1[l][mm] = (abs(m)<=l) ? (float)dev_wigner_cs(l,m,0,cbh,sbh,s_ifct) : 0.f; continue; }
        t -= 190;
        if(t < 38000){ int l=t/3800, r=t%3800, z=r/190, mm=(r%190)/10, np=r%10, m=mm-9;
            c_dinv1p[l][z][mm][np] = (abs(m)<=l && np<=l) ? (float)((2*l+1)*dev_wigner_cs(l,m,np,cb40[z],sb40[z],s_ifct)) : 0.f;
            continue; }
        t -= 38000;
        if(t < 8100){ int l=t/1620, r=t%1620, z=r/81, mm=(r%81)/9, nn=r%9, m=mm-4, n=nn-4;
            c_d2[l][z][mm][nn] = (abs(m)<=l && abs(n)<=l) ? (float)(dev_wigner_cs(l,m,n,cb40[z],sb40[z],s_ifct)*s_w10[z]) : 0.f;
            continue; }
        t -= 8100;
        if(t < 405){ int l=t/81, mm=(t%81)/9, nn=t%9, m=mm-4, n=nn-4;
            c_dh2[l][mm][nn] = (abs(m)<=l && abs(n)<=l) ? (float)dev_wigner_cs(l,m,n,cbh,sbh,s_ifct) : 0.f; continue; }
        t -= 405;
        if(t < 4050){ int l=t/810, r=t%810, z=r/81, mm=(r%81)/9, nn=r%9, m=mm-4, n=nn-4;
            c_dinv2[l][z][mm][nn] = (abs(m)<=l && abs(n)<=l) ? (float)((2*l+1)*dev_wigner_cs(l,m,n,cb20[z],sb20[z],s_ifct)) : 0.f;
            continue; }
        t -= 4050;
        if(t < 1140){ int mm=t/60, p=t%60; double a = -2.0*PI_D*(double)(mm-9)*(double)p/60.0;
            c_tw60[mm][p] = make_float2((float)cos(a),(float)sin(a)); continue; }
        t -= 1140;
        if(t < 380){ int mm=t/20, j=t%20; double a = 2.0*PI_D*(double)(mm-9)*(double)j/20.0;
            float cx=(float)cos(a), cy=(float)sin(a);
            c_tw20b[mm][j]  = make_float2(cx,cy);
            c_tw20br[mm][j] = make_float2(-cy,cx);
            continue; }
        t -= 380;
        if(t < 180){ int mm=t/20, k=t%20; double a = -2.0*PI_D*(double)(mm-4)*(double)k/20.0;
            float cx=(float)cos(a), cy=(float)sin(a);
            c_tw20f[mm][k]  = make_float2(cx,cy);
            c_tw20fr[mm][k] = make_float2(-cy,cx);
            continue; }
        t -= 180;
        if(t < 90){ int mm=t/10, j=t%10; double a = 2.0*PI_D*(double)(mm-4)*(double)j/10.0;
            float cx=(float)cos(a), cy=(float)sin(a);
            c_tw10b[mm][j]  = make_float2(cx,cy);
            c_tw10br[mm][j] = make_float2(-cy,cx);
            continue; }
        t -= 90;
        { c_w5[t] = s_w5f[t]; }
    }
}

// ---------------- input DFTs (Hermitian-folded, f32x2) ----------------
__global__ void k_dfts(const float* __restrict__ x, const float* __restrict__ k1,
                       const float* __restrict__ k2){
    int idx = blockIdx.x*blockDim.x+threadIdx.x;
    if(idx < 19200){
        int mmq = idx%10, z = (idx/10)%60, b = idx/600;
        int mm = 9+mmq;
        const float* row = x + (b*60 + z)*60;
        u64 acc = 0;
        #pragma unroll 4
        for(int p=0;p<60;p++){
            float v = row[p];
            fma2(acc, pk2(v,v), *(const u64*)&c_tw60[mm][p]);
        }
        float2 a = u2f(acc);
        g_xfT[mm][z][b] = a;
        if(mmq > 0) g_xfT[18-mm][z][b] = make_float2(a.x, -a.y);
        return;
    }
    idx -= 19200;
    if(idx < 1000){
        int mmq = idx%10, o = idx/10;
        int mm = 9+mmq;
        const float* row = k1 + o*60;
        u64 acc = 0;
        #pragma unroll 4
        for(int p=0;p<60;p++){
            float v = row[p];
            fma2(acc, pk2(v,v), *(const u64*)&c_tw60[mm][p]);
        }
        float2 a = u2f(acc);
        g_kfc[o][mm] = make_float2(a.x*SC1V, a.y*SC1V);
        return;
    }
    idx -= 1000;
    if(idx < 180000){
        int o = idx%200, i = (idx/200)%100, mm = idx/20000;
        const float* row = k2 + (i*200+o)*20;
        u64 acc = 0;
        #pragma unroll
        for(int p=0;p<20;p++){
            float v = row[p];
            fma2(acc, pk2(v,v), *(const u64*)&c_tw20f[mm][p]);
        }
        float2 a = u2f(acc);
        g_k2f[mm][i][o] = make_float2(a.x*SC2V, a.y*SC2V);
    }
}

// ---------------- FG (xhat1 in-block) + Kp (n-contiguous layout) ----------------
__global__ void k_FGmid(){
    int blk = blockIdx.x;
    int t = threadIdx.x;  // 256
    if(blk >= 640){
        int o = blk - 640;
        if(t < 200){
            int k = t/10, np = t%10;
            float2 kf = g_kfc[o][np+9];
            float2 e  = c_tw20b[np+9][k];
            g_Kp[o][k][np] = make_float2(kf.x*e.x + kf.y*e.y, kf.x*e.y - kf.y*e.x);
        }
        return;
    }
    __shared__ float2 xh1s[10][19];
    __shared__ float2 Fs[19][10];
    int b = blk/20, z2 = blk%20;
    if(t < 190){
        int l = t/19, mm = t%19, m = mm-9;
        u64 acc = 0;
        if(abs(m)<=l){
            #pragma unroll 4
            for(int z=0;z<60;z++){
                float d = c_d1[l][z][mm];
                fma2(acc, pk2(d,d), *(const u64*)&g_xfT[mm][z][b]);
            }
        }
        xh1s[l][mm] = u2f(acc);
    }
    __syncthreads();
    if(t < 190){
        int mm = t%19, np = t/19, m = mm-9;
        int l0 = max(abs(m), np);
        u64 acc = 0;
        for(int l=l0;l<10;l++){
            float c = c_dh1[l][np+9]*c_dinv1p[l][z2][mm][np];
            fma2(acc, pk2(c,c), *(const u64*)&xh1s[l][mm]);
        }
        Fs[mm][np] = u2f(acc);
    }
    __syncthreads();
    if(t < 200){
        int np = t/20, j = t%20;
        u64 acc = 0;
        #pragma unroll
        for(int mm=0;mm<19;mm++){
            float2 f = Fs[mm][np];
            fma2(acc, pk2(f.x,f.x), *(const u64*)&c_tw20b[mm][j]);
            fma2(acc, pk2(f.y,f.y), *(const u64*)&c_tw20br[mm][j]);
        }
        g_G[np][b][z2][j] = u2f(acc);
    }
}

// ---------------- S2 epilogue: vectorized K reads, smem twiddles ----------------
__global__ void __launch_bounds__(400,2) k_s2fuse(const float* __restrict__ b1){
    __shared__ __align__(16) float2 Kks[4][20][10];   // [q][k][n] — n contiguous
    __shared__ __align__(16) float  hs[4][20][20];    // [q][k][j]
    __shared__ __align__(16) float2 tms[4][9][20];
    __shared__ __align__(16) float2 s_twf[9][20];
    __shared__ __align__(16) float2 s_twfr[9][20];
    __shared__ float  bs[100];
    int bb = blockIdx.x;
    int b = bb/40, z2 = (bb%40)>>1, ih = bb&1;
    int t = threadIdx.x;  // 400
    int r  = t%200, tq = t/200;
    int k  = r/10,  jp = r%10;
    u64 Gx[10], Gyn[10];   // packed (j0,j1) of G.x ; negated G.y
    #pragma unroll
    for(int n=0;n<10;n++){
        float2 g0 = g_G[n][b][z2][jp];
        float2 g1 = g_G[n][b][z2][jp+10];
        Gx[n]  = pk2(g0.x, g1.x);
        Gyn[n] = pk2(-g0.y, -g1.y);
    }
    if(t < 100) bs[t] = b1[t];
    if(t >= 100 && t < 280){ int q = t-100; s_twf [q/20][q%20] = c_tw20f [q/20][q%20]; }
    if(t >= 280 && t < 400){ int q = t-280; s_twfr[q/20][q%20] = c_tw20fr[q/20][q%20]; }
    if(t >= 340){ int q = t-340+120; s_twfr[q/20][q%20] = c_tw20fr[q/20][q%20]; }
    __syncthreads();
    int istart = ih*52, iend = istart ? 100 : 52;
    for(int i0=istart;i0<iend;i0+=4){
        // Kks fill: straight float4 copy (4 filters x 200 float2 = 400 float4)
        ((float4*)&Kks[0][0][0])[t] = ((const float4*)&g_Kp[i0][0][0])[t];
        __syncthreads();
        // h-stage: 2q x 2j per thread; K row via 5 broadcast LDS.128
        #pragma unroll
        for(int qq=0;qq<2;qq++){
            int q = tq*2+qq;
            const float4* krow = (const float4*)&Kks[q][k][0];
            float4 K01=krow[0], K23=krow[1], K45=krow[2], K67=krow[3], K89=krow[4];
            u64 a = 0, p = 0;
            fma2(a, pk2(K01.x,K01.x), Gx[0]); fma2(a, pk2(K01.y,K01.y), Gyn[0]);
            fma2(p, pk2(K01.z,K01.z), Gx[1]); fma2(p, pk2(K01.w,K01.w), Gyn[1]);
            fma2(p, pk2(K23.x,K23.x), Gx[2]); fma2(p, pk2(K23.y,K23.y), Gyn[2]);
            fma2(p, pk2(K23.z,K23.z), Gx[3]); fma2(p, pk2(K23.w,K23.w), Gyn[3]);
            fma2(p, pk2(K45.x,K45.x), Gx[4]); fma2(p, pk2(K45.y,K45.y), Gyn[4]);
            fma2(p, pk2(K45.z,K45.z), Gx[5]); fma2(p, pk2(K45.w,K45.w), Gyn[5]);
            fma2(p, pk2(K67.x,K67.x), Gx[6]); fma2(p, pk2(K67.y,K67.y), Gyn[6]);
            fma2(p, pk2(K67.z,K67.z), Gx[7]); fma2(p, pk2(K67.w,K67.w), Gyn[7]);
            fma2(p, pk2(K89.x,K89.x), Gx[8]); fma2(p, pk2(K89.y,K89.y), Gyn[8]);
            fma2(p, pk2(K89.z,K89.z), Gx[9]); fma2(p, pk2(K89.w,K89.w), Gyn[9]);
            float2 af = u2f(a), pf = u2f(p);
            float bias = bs[i0+q];
            hs[q][k][jp   ] = fmaxf(bias + af.x + 2.f*pf.x, 0.f);
            hs[q][k][jp+10] = fmaxf(bias + af.y + 2.f*pf.y, 0.f);
        }
        __syncthreads();
        // st1: m>=0 (mm=4..8); hs row -> 5 LDS.128; twiddles from smem
        {
            int q = t/100, rr = t%100, mq = rr/20, kk = rr%20, mm = 4+mq;
            const float4* hrow  = (const float4*)&hs[q][kk][0];
            const float4* twrow = (const float4*)&s_twf[mm][0];
            u64 acc = 0;
            #pragma unroll
            for(int c=0;c<5;c++){
                float4 h4  = hrow[c];
                float4 e01 = twrow[2*c];
                float4 e23 = twrow[2*c+1];
                fma2(acc, pk2(h4.x,h4.x), pk2(e01.x,e01.y));
                fma2(acc, pk2(h4.y,h4.y), pk2(e01.z,e01.w));
                fma2(acc, pk2(h4.z,h4.z), pk2(e23.x,e23.y));
                fma2(acc, pk2(h4.w,h4.w), pk2(e23.z,e23.w));
            }
            float2 a = u2f(acc);
            tms[q][mm][kk] = a;
            if(mq > 0) tms[q][4-mq][kk] = make_float2(a.x, -a.y);
        }
        __syncthreads();
        // st2: half-set mn in [0,40]; twiddles from smem
        if(t < 164){
            int q = t/41, mn = t%41, mm = mn/9, nn = mn%9;
            const float4* trow = (const float4*)&tms[q][mm][0];
            const float4* twf  = (const float4*)&s_twf[nn][0];
            const float4* twr  = (const float4*)&s_twfr[nn][0];
            u64 acc = 0;
            #pragma unroll
            for(int c=0;c<10;c++){
                float4 v  = trow[c];
                float4 e  = twf[c];
                float4 er = twr[c];
                fma2(acc, pk2(v.x,v.x), pk2(e.x,e.y));
                fma2(acc, pk2(v.y,v.y), pk2(er.x,er.y));
                fma2(acc, pk2(v.z,v.z), pk2(e.z,e.w));
                fma2(acc, pk2(v.w,v.w), pk2(er.z,er.w));
            }
            float2 a = u2f(acc);
            g_xg[b][i0+q][z2][mn] = a;
            if(mn < 40) g_xg[b][i0+q][z2][80-mn] = make_float2(a.x, -a.y);
        }
    }
}

// ---------------- xhat2 + T2 per (b,i), half-set ----------------
__global__ void k_xh2T2(){
    __shared__ float2 xgs[20][45];
    __shared__ float2 xh[5][5][9];
    int b = blockIdx.x/100, i = blockIdx.x%100;
    int t = threadIdx.x;  // 256
    for(int idx=t; idx<900; idx+=256){
        int z = idx/45, mn = idx%45;
        xgs[z][mn] = g_xg[b][i][z][mn];
    }
    __syncthreads();
    if(t < 225){
        int l = t/45, rr = t%45, mm = rr/9, kk = rr%9;
        int m = mm-4, kq = kk-4;
        u64 acc = 0;
        if(abs(m)<=l && abs(kq)<=l){
            #pragma unroll 4
            for(int z=0;z<20;z++){
                float d = c_d2[l][z][mm][kk];
                fma2(acc, pk2(d,d), *(const u64*)&xgs[z][mm*9+kk]);
            }
        }
        xh[l][mm][kk] = u2f(acc);
    }
    __syncthreads();
    if(t < 205){
        int l = t/41, mn = t%41, mm = mn/9, nn = mn%9;
        u64 acc = 0;
        #pragma unroll
        for(int kk=0;kk<9;kk++){
            float d = c_dh2[l][nn][kk];
            fma2(acc, pk2(d,d), *(const u64*)&xh[l][mm][kk]);
        }
        g_T2[l][mn][b][i] = u2f(acc);
    }
}

// ---------------- z2: half-set GEMM, b-split x2, packed ----------------
__global__ void k_z2(){
    __shared__ float2 Ts[16][100];
    int blk = blockIdx.x;
    int bh = blk/205, lh = blk%205;
    int l = lh/41, h = lh%41;
    int mm = h/9, nn = h%9;
    int m = mm-4, n = nn-4;
    int t = threadIdx.x;  // 256
    if(l < max(abs(m),abs(n))) return;
    const float2* src = &g_T2[l][h][bh*16][0];
    for(int idx=t; idx<1600; idx+=256) (&Ts[0][0])[idx] = src[idx];
    __syncthreads();
    if(t < 200){
        int bq = t/100, op = t%100;
        float sg = ((mm+nn)&1) ? -1.f : 1.f;
        int idx0 = l*81 + h, idx1 = l*81 + (80-h);
        int bb0 = bq*8;
        u64 a0[8], a1[8];
        #pragma unroll
        for(int rr=0;rr<8;rr++){ a0[rr]=0; a1[rr]=0; }
        for(int i=0;i<100;i++){
            float2 kf0 = g_k2f[nn][i][op];
            float2 kf1 = g_k2f[nn][i][op+100];
            u64 ka0 = pk2(kf0.x,-kf0.y), kb0 = pk2(kf0.y,kf0.x);
            u64 ka1 = pk2(kf1.x,-kf1.y), kb1 = pk2(kf1.y,kf1.x);
            #pragma unroll
            for(int rr=0;rr<8;rr++){
                float2 Tv = Ts[bb0+rr][i];
                u64 tx = pk2(Tv.x,Tv.x), ty = pk2(Tv.y,Tv.y);
                fma2(a0[rr], tx, ka0); fma2(a0[rr], ty, kb0);
                fma2(a1[rr], tx, ka1); fma2(a1[rr], ty, kb1);
            }
        }
        #pragma unroll
        for(int rr=0;rr<8;rr++){
            int bb = bh*16 + bb0 + rr;
            float2 v0 = u2f(a0[rr]), v1 = u2f(a1[rr]);
            g_z2t[bb][op    ][idx0] = v0;
            g_z2t[bb][op+100][idx0] = v1;
            if(h < 40){
                g_z2t[bb][op    ][idx1] = make_float2(sg*v0.x, -sg*v0.y);
                g_z2t[bb][op+100][idx1] = make_float2(sg*v1.x, -sg*v1.y);
            }
        }
    }
}

// ---------------- out2: packed stages + fused final via atomics ----------------
__global__ void k_out2(const float* __restrict__ b2, const float* __restrict__ W,
                       float* __restrict__ out){
    __shared__ float2 zs[405];
    __shared__ float2 g2a[10][81];
    __shared__ float2 tma[10][5][10];
    __shared__ float  wsum[8];
    int b = blockIdx.x/200, o = blockIdx.x%200;
    int t = threadIdx.x;  // 256
    for(int idx=t; idx<405; idx+=256){
        int l = idx/81, mn = idx%81, m = mn/9-4, n = mn%9-4;
        zs[idx] = (l >= max(abs(m),abs(n))) ? g_z2t[b][o][idx] : make_float2(0.f,0.f);
    }
    float b2v = b2[o];
    __syncthreads();
    for(int idx=t; idx<410; idx+=256){
        int z3 = idx/41, mn = idx%41, mm = mn/9, nn = mn%9;
        int m = mm-4, n = nn-4;
        int l0 = max(abs(m),abs(n));
        u64 acc = 0;
        for(int l=l0;l<5;l++){
            float d = c_dinv2[l][z3][mm][nn];
            fma2(acc, pk2(d,d), *(const u64*)&zs[l*81+mn]);
        }
        float2 a = u2f(acc);
        g2a[z3][mn] = a;
        g2a[z3][80-mn] = make_float2(a.x, -a.y);
    }
    __syncthreads();
    for(int idx=t; idx<500; idx+=256){
        int z3 = idx/50, rr = idx%50, mq = rr/10, k = rr%10;
        int mm = 4+mq;
        u64 acc = 0;
        #pragma unroll
        for(int nn=0;nn<9;nn++){
            float2 v = g2a[z3][mm*9+nn];
            fma2(acc, pk2(v.x,v.x), *(const u64*)&c_tw10b[nn][k]);
            fma2(acc, pk2(v.y,v.y), *(const u64*)&c_tw10br[nn][k]);
        }
        tma[z3][mq][k] = u2f(acc);
    }
    __syncthreads();
    float psum = 0.f;
    for(int idx=t; idx<1000; idx+=256){
        int z3 = idx/100, rr = idx%100, j = rr/10, k = rr%10;
        float v = tma[z3][0][k].x;
        #pragma unroll
        for(int mq=1;mq<5;mq++){
            float2 a = tma[z3][mq][k]; float2 e = c_tw10b[4+mq][j];
            v += 2.f*(a.x*e.x - a.y*e.y);
        }
        v = fmaxf(v + b2v, 0.f);
        psum += v * c_w5[z3];
    }
    #pragma unroll
    for(int off=16; off; off>>=1) psum += __shfl_xor_sync(0xFFFFFFFFu, psum, off);
    if((t&31) == 0) wsum[t>>5] = psum;
    __syncthreads();
    if(t == 0){
        float s = 0.f;
        #pragma unroll
        for(int w=0;w<8;w++) s += wsum[w];
        #pragma unroll
        for(int f=0;f<10;f++) atomicAdd(&out[b*10+f], s*W[f*200+o]);
    }
}

extern "C" void kernel_launch(void* const* d_in, const int* in_sizes, int n_in,
                              void* d_out, int out_size){
    const float* x  = (const float*)d_in[0];
    const float* k1 = (const float*)d_in[1];
    const float* b1 = (const float*)d_in[2];
    const float* k2 = (const float*)d_in[3];
    const float* b2 = (const float*)d_in[4];
    const float* W  = (const float*)d_in[5];
    const float* bl = (const float*)d_in[6];
    float* out = (float*)d_out;

    k_init  <<<128,256>>>(bl,out);
    k_dfts  <<<(19200+1000+180000+255)/256,256>>>(x,k1,k2);
    k_FGmid <<<740,256>>>();
    k_s2fuse<<<1280,400>>>(b1);
    k_xh2T2 <<<3200,256>>>();
    k_z2    <<<410,256>>>();
    k_out2  <<<6400,256>>>(b2,W,out);
}

// round 11
// speedup vs baseline: 4.1359x; 1.1175x over previous
#include <cuda_runtime.h>
#include <math.h>

#define PI_D 3.14159265358979323846
#define SC1V 0.03872983346207417f   /* 1/sqrt(2000/3) */
#define SC2V 0.06324555320336759f   /* 1/sqrt(250)    */

typedef unsigned long long u64;

// packed f32x2 helpers
__device__ __forceinline__ float2 u2f(u64 v){ float2 r; asm("mov.b64 {%0,%1}, %2;":"=f"(r.x),"=f"(r.y):"l"(v)); return r; }
__device__ __forceinline__ u64 pk2(float a, float b){ u64 r; asm("mov.b64 %0, {%1,%2};":"=l"(r):"f"(a),"f"(b)); return r; }
__device__ __forceinline__ void fma2(u64 &acc, u64 a, u64 b){
    asm("fma.rn.f32x2 %0, %1, %2, %3;" : "=l"(acc) : "l"(a), "l"(b), "l"(acc));
}

// ---------------- constant tables (device-computed) ----------------
__device__ float  c_d1[10][60][19];
__device__ float  c_dh1[10][19];
__device__ float  c_dinv1p[10][20][19][10];
__device__ float  c_d2[5][20][9][9];
__device__ float  c_dh2[5][9][9];
__device__ float  c_dinv2[5][10][9][9];
__device__ float  c_w5[10];
__device__ float2 c_tw60[19][60];                 // e^{-2pi i m p/60}
__device__ float2 c_tw20b[19][20];                // e^{+2pi i m j/20}
__device__ float2 c_tw20br[19][20];               // rotated (-y,x)
__device__ __align__(16) float2 c_tw20f[9][20];   // e^{-2pi i m k/20}
__device__ __align__(16) float2 c_tw20fr[9][20];  // rotated
__device__ float2 c_tw10b[9][10];                 // e^{+2pi i m j/10}
__device__ float2 c_tw10br[9][10];                // rotated

__constant__ double c_fct[20] = {1.,1.,2.,6.,24.,120.,720.,5040.,40320.,362880.,
    3628800.,39916800.,479001600.,6227020800.,87178291200.,1307674368000.,
    20922789888000.,355687428096000.,6402373705728000.,121645100408832000.};

// ---------------- scratch ----------------
__device__ float2 g_xfT[19][60][32];
__device__ float2 g_kfc[100][19];
__device__ __align__(16) float2 g_Kp[100][20][10];   // [i][k][n]  (n contiguous)
__device__ float2 g_G[10][32][20][20];
__device__ float2 g_xg[32][100][20][81];
__device__ float2 g_k2f[9][100][200];
__device__ float2 g_T2[5][41][32][100];
__device__ float2 g_z2t[32][200][405];

// ---------------- Wigner-d from precomputed half-angle cos/sin ----------------
__device__ double dev_wigner_cs(int l, int m, int n, double cb, double sb, const double* ifct){
    double pref = sqrt(c_fct[l+m]*c_fct[l-m]*c_fct[l+n]*c_fct[l-n]);
    int s0 = (n-m > 0) ? (n-m) : 0;
    int s1 = (l+n < l-m) ? (l+n) : (l-m);
    if(s1 < s0) return 0.0;
    int e0 = 2*l+n-m-2*s0, f0 = m-n+2*s0;
    double cbe = 1.0; for(int i=0;i<e0;i++) cbe *= cb;
    double sbf = 1.0; for(int i=0;i<f0;i++) sbf *= sb;
    double r  = (sb*sb)/(cb*cb);
    double pw = cbe*sbf;
    double acc = 0.0;
    for(int s=s0;s<=s1;s++){
        double deni = ifct[l+n-s]*ifct[s]*ifct[m-n+s]*ifct[l-m-s];
        double sg   = ((m-n+s)&1) ? -1.0 : 1.0;
        acc += sg*pw*deni;
        pw *= r;
    }
    return pref*acc;
}

__device__ double dev_qw(int b, int j){
    double beta = PI_D*(2*j+1)/(4.0*b);
    double s=0.0;
    for(int k=1;k<2*b;k+=2) s += sin(k*beta)/(double)k;
    return 2.0/b*sin(beta)*s;
}

// ---------------- init: output reset + per-block smem weights + all tables ----------------
__global__ void k_init(const float* __restrict__ bl, float* __restrict__ out){
    {
        int gi = blockIdx.x*blockDim.x + threadIdx.x;
        if(gi < 320) out[gi] = bl[gi%10];
    }
    __shared__ double s_w30[60], s_w10[20];
    __shared__ float  s_w5f[10];
    __shared__ double cb120[60], sb120[60], cb40[20], sb40[20], cb20[10], sb20[10];
    __shared__ double s_ifct[20];
    int tt = threadIdx.x;
    if(tt < 60){ s_w30[tt]=dev_qw(30,tt); double a=PI_D*(2*tt+1)/240.0; cb120[tt]=cos(a); sb120[tt]=sin(a); }
    else if(tt < 80){ int z=tt-60; s_w10[z]=dev_qw(10,z); double a=PI_D*(2*z+1)/80.0; cb40[z]=cos(a); sb40[z]=sin(a); }
    else if(tt < 90){ int z=tt-80; s_w5f[z]=(float)dev_qw(5,z); double a=PI_D*(2*z+1)/40.0; cb20[z]=cos(a); sb20[z]=sin(a); }
    else if(tt < 110){ s_ifct[tt-90] = 1.0/c_fct[tt-90]; }
    __syncthreads();
    const double cbh = 0.70710678118654752, sbh = 0.70710678118654752;
    const int total = 11400+190+38000+8100+405+4050+1140+380+180+90+10;
    for(int idx = blockIdx.x*blockDim.x+threadIdx.x; idx<total; idx += gridDim.x*blockDim.x){
        int t = idx;
        if(t < 11400){ int l=t/1140, r=t%1140, z=r/19, mm=r%19, m=mm-9;
            c_d1[l][z][mm] = (abs(m)<=l) ? (float)(dev_wigner_cs(l,m,0,cb120[z],sb120[z],s_ifct)*s_w30[z]) : 0.f;
            continue; }
        t -= 11400;
        if(t < 190){ int l=t/19, mm=t%19, m=mm-9;
            c_dh1[l][mm] = (abs(m)<=l) ? (float)dev_wigner_cs(l,m,0,cbh,sbh,s_ifct) : 0.f; continue; }
        t -= 190;
        if(t < 38000){ int l=t/3800, r=t%3800, z=r/190, mm=(r%190)/10, np=r%10, m=mm-9;
            c_dinv1p[l][z][mm][np] = (abs(m)<=l && np<=l) ? (float)((2*l+1)*dev_wigner_cs(l,m,np,cb40[z],sb40[z],s_ifct)) : 0.f;
            continue; }
        t -= 38000;
        if(t < 8100){ int l=t/1620, r=t%1620, z=r/81, mm=(r%81)/9, nn=r%9, m=mm-4, n=nn-4;
            c_d2[l][z][mm][nn] = (abs(m)<=l && abs(n)<=l) ? (float)(dev_wigner_cs(l,m,n,cb40[z],sb40[z],s_ifct)*s_w10[z]) : 0.f;
            continue; }
        t -= 8100;
        if(t < 405){ int l=t/81, mm=(t%81)/9, nn=t%9, m=mm-4, n=nn-4;
            c_dh2[l][mm][nn] = (abs(m)<=l && abs(n)<=l) ? (float)dev_wigner_cs(l,m,n,cbh,sbh,s_ifct) : 0.f; continue; }
        t -= 405;
        if(t < 4050){ int l=t/810, r=t%810, z=r/81, mm=(r%81)/9, nn=r%9, m=mm-4, n=nn-4;
            c_dinv2[l][z][mm][nn] = (abs(m)<=l && abs(n)<=l) ? (float)((2*l+1)*dev_wigner_cs(l,m,n,cb20[z],sb20[z],s_ifct)) : 0.f;
            continue; }
        t -= 4050;
        if(t < 1140){ int mm=t/60, p=t%60; double a = -2.0*PI_D*(double)(mm-9)*(double)p/60.0;
            c_tw60[mm][p] = make_float2((float)cos(a),(float)sin(a)); continue; }
        t -= 1140;
        if(t < 380){ int mm=t/20, j=t%20; double a = 2.0*PI_D*(double)(mm-9)*(double)j/20.0;
            float cx=(float)cos(a), cy=(float)sin(a);
            c_tw20b[mm][j]  = make_float2(cx,cy);
            c_tw20br[mm][j] = make_float2(-cy,cx);
            continue; }
        t -= 380;
        if(t < 180){ int mm=t/20, k=t%20; double a = -2.0*PI_D*(double)(mm-4)*(double)k/20.0;
            float cx=(float)cos(a), cy=(float)sin(a);
            c_tw20f[mm][k]  = make_float2(cx,cy);
            c_tw20fr[mm][k] = make_float2(-cy,cx);
            continue; }
        t -= 180;
        if(t < 90){ int mm=t/10, j=t%10; double a = 2.0*PI_D*(double)(mm-4)*(double)j/10.0;
            float cx=(float)cos(a), cy=(float)sin(a);
            c_tw10b[mm][j]  = make_float2(cx,cy);
            c_tw10br[mm][j] = make_float2(-cy,cx);
            continue; }
        t -= 90;
        { c_w5[t] = s_w5f[t]; }
    }
}

// ---------------- input DFTs (Hermitian-folded, f32x2) ----------------
__global__ void k_dfts(const float* __restrict__ x, const float* __restrict__ k1,
                       const float* __restrict__ k2){
    int idx = blockIdx.x*blockDim.x+threadIdx.x;
    if(idx < 19200){
        int mmq = idx%10, z = (idx/10)%60, b = idx/600;
        int mm = 9+mmq;
        const float* row = x + (b*60 + z)*60;
        u64 acc = 0;
        #pragma unroll 4
        for(int p=0;p<60;p++){
            float v = row[p];
            fma2(acc, pk2(v,v), *(const u64*)&c_tw60[mm][p]);
        }
        float2 a = u2f(acc);
        g_xfT[mm][z][b] = a;
        if(mmq > 0) g_xfT[18-mm][z][b] = make_float2(a.x, -a.y);
        return;
    }
    idx -= 19200;
    if(idx < 1000){
        int mmq = idx%10, o = idx/10;
        int mm = 9+mmq;
        const float* row = k1 + o*60;
        u64 acc = 0;
        #pragma unroll 4
        for(int p=0;p<60;p++){
            float v = row[p];
            fma2(acc, pk2(v,v), *(const u64*)&c_tw60[mm][p]);
        }
        float2 a = u2f(acc);
        g_kfc[o][mm] = make_float2(a.x*SC1V, a.y*SC1V);
        return;
    }
    idx -= 1000;
    if(idx < 180000){
        int o = idx%200, i = (idx/200)%100, mm = idx/20000;
        const float* row = k2 + (i*200+o)*20;
        u64 acc = 0;
        #pragma unroll
        for(int p=0;p<20;p++){
            float v = row[p];
            fma2(acc, pk2(v,v), *(const u64*)&c_tw20f[mm][p]);
        }
        float2 a = u2f(acc);
        g_k2f[mm][i][o] = make_float2(a.x*SC2V, a.y*SC2V);
    }
}

// ---------------- FG (xhat1 in-block) + Kp (n-contiguous layout) ----------------
__global__ void k_FGmid(){
    int blk = blockIdx.x;
    int t = threadIdx.x;  // 256
    if(blk >= 640){
        int o = blk - 640;
        if(t < 200){
            int k = t/10, np = t%10;
            float2 kf = g_kfc[o][np+9];
            float2 e  = c_tw20b[np+9][k];
            g_Kp[o][k][np] = make_float2(kf.x*e.x + kf.y*e.y, kf.x*e.y - kf.y*e.x);
        }
        return;
    }
    __shared__ float2 xh1s[10][19];
    __shared__ float2 Fs[19][10];
    int b = blk/20, z2 = blk%20;
    if(t < 190){
        int l = t/19, mm = t%19, m = mm-9;
        u64 acc = 0;
        if(abs(m)<=l){
            #pragma unroll 4
            for(int z=0;z<60;z++){
                float d = c_d1[l][z][mm];
                fma2(acc, pk2(d,d), *(const u64*)&g_xfT[mm][z][b]);
            }
        }
        xh1s[l][mm] = u2f(acc);
    }
    __syncthreads();
    if(t < 190){
        int mm = t%19, np = t/19, m = mm-9;
        int l0 = max(abs(m), np);
        u64 acc = 0;
        for(int l=l0;l<10;l++){
            float c = c_dh1[l][np+9]*c_dinv1p[l][z2][mm][np];
            fma2(acc, pk2(c,c), *(const u64*)&xh1s[l][mm]);
        }
        Fs[mm][np] = u2f(acc);
    }
    __syncthreads();
    if(t < 200){
        int np = t/20, j = t%20;
        u64 acc = 0;
        #pragma unroll
        for(int mm=0;mm<19;mm++){
            float2 f = Fs[mm][np];
            fma2(acc, pk2(f.x,f.x), *(const u64*)&c_tw20b[mm][j]);
            fma2(acc, pk2(f.y,f.y), *(const u64*)&c_tw20br[mm][j]);
        }
        g_G[np][b][z2][j] = u2f(acc);
    }
}

// ---------------- S2 epilogue: parity-folded DFT stages ----------------
__global__ void __launch_bounds__(400,2) k_s2fuse(const float* __restrict__ b1){
    __shared__ __align__(16) float2 Kks[4][20][10];   // [q][k][n]
    __shared__ __align__(16) float2 hs2[4][20][10];   // [q][k][jp] = (h_jp, h_jp+10)
    __shared__ __align__(16) float4 tms4[4][9][10];   // [q][mm][kkp] = (re_k,im_k,re_k+10,im_k+10)
    __shared__ __align__(16) float2 s_twf[9][10];
    __shared__ __align__(16) float2 s_twfr[9][10];
    __shared__ float  bs[100];
    int bb = blockIdx.x;
    int b = bb/40, z2 = (bb%40)>>1, ih = bb&1;
    int t = threadIdx.x;  // 400
    int r  = t%200, tq = t/200;
    int k  = r/10,  jp = r%10;
    u64 Gx[10], Gyn[10];   // packed (j0,j1) of G.x ; negated G.y
    #pragma unroll
    for(int n=0;n<10;n++){
        float2 g0 = g_G[n][b][z2][jp];
        float2 g1 = g_G[n][b][z2][jp+10];
        Gx[n]  = pk2(g0.x, g1.x);
        Gyn[n] = pk2(-g0.y, -g1.y);
    }
    if(t < 100) bs[t] = b1[t];
    if(t >= 100 && t < 190){ int q = t-100; s_twf [q/10][q%10] = c_tw20f [q/10][q%10]; }
    if(t >= 190 && t < 280){ int q = t-190; s_twfr[q/10][q%10] = c_tw20fr[q/10][q%10]; }
    __syncthreads();
    int istart = ih*52, iend = istart ? 100 : 52;
    for(int i0=istart;i0<iend;i0+=4){
        // Kks fill: straight float4 copy
        ((float4*)&Kks[0][0][0])[t] = ((const float4*)&g_Kp[i0][0][0])[t];
        __syncthreads();
        // h-stage: 2q x 2j per thread; the (jp, jp+10) pair is written as one float2
        #pragma unroll
        for(int qq=0;qq<2;qq++){
            int q = tq*2+qq;
            const float4* krow = (const float4*)&Kks[q][k][0];
            float4 K01=krow[0], K23=krow[1], K45=krow[2], K67=krow[3], K89=krow[4];
            u64 a = 0, p = 0;
            fma2(a, pk2(K01.x,K01.x), Gx[0]); fma2(a, pk2(K01.y,K01.y), Gyn[0]);
            fma2(p, pk2(K01.z,K01.z), Gx[1]); fma2(p, pk2(K01.w,K01.w), Gyn[1]);
            fma2(p, pk2(K23.x,K23.x), Gx[2]); fma2(p, pk2(K23.y,K23.y), Gyn[2]);
            fma2(p, pk2(K23.z,K23.z), Gx[3]); fma2(p, pk2(K23.w,K23.w), Gyn[3]);
            fma2(p, pk2(K45.x,K45.x), Gx[4]); fma2(p, pk2(K45.y,K45.y), Gyn[4]);
            fma2(p, pk2(K45.z,K45.z), Gx[5]); fma2(p, pk2(K45.w,K45.w), Gyn[5]);
            fma2(p, pk2(K67.x,K67.x), Gx[6]); fma2(p, pk2(K67.y,K67.y), Gyn[6]);
            fma2(p, pk2(K67.z,K67.z), Gx[7]); fma2(p, pk2(K67.w,K67.w), Gyn[7]);
            fma2(p, pk2(K89.x,K89.x), Gx[8]); fma2(p, pk2(K89.y,K89.y), Gyn[8]);
            fma2(p, pk2(K89.z,K89.z), Gx[9]); fma2(p, pk2(K89.w,K89.w), Gyn[9]);
            float2 af = u2f(a), pf = u2f(p);
            float bias = bs[i0+q];
            hs2[q][k][jp] = make_float2(fmaxf(bias + af.x + 2.f*pf.x, 0.f),
                                        fmaxf(bias + af.y + 2.f*pf.y, 0.f));
        }
        __syncthreads();
        // st1: j-parity fold; mq fast / kk slow mapping
        {
            int q = t/100, rr = t%100, mq = rr%5, kk = rr/5, mm = 4+mq;
            float sgn = (mq&1) ? -1.f : 1.f;
            const float4* hrow  = (const float4*)&hs2[q][kk][0];   // 5 float4 = 10 jp pairs
            const float4* twrow = (const float4*)&s_twf[mm][0];    // 5 float4 = 10 jp
            u64 acc = 0;
            #pragma unroll
            for(int c=0;c<5;c++){
                float4 hv = hrow[c];
                float4 e  = twrow[c];
                float t0 = fmaf(sgn, hv.y, hv.x);
                float t1 = fmaf(sgn, hv.w, hv.z);
                fma2(acc, pk2(t0,t0), pk2(e.x,e.y));
                fma2(acc, pk2(t1,t1), pk2(e.z,e.w));
            }
            float2 a = u2f(acc);
            int kkp = kk%10, half = kk/10;
            ((float2*)&tms4[q][mm][kkp])[half] = a;
            if(mq > 0) ((float2*)&tms4[q][4-mq][kkp])[half] = make_float2(a.x, -a.y);
        }
        __syncthreads();
        // st2: k-parity fold; half-set mn in [0,40], mirror conj to 80-mn
        if(t < 164){
            int q = t/41, mn = t%41, mm = mn/9, nn = mn%9;
            float sgn = (nn&1) ? -1.f : 1.f;
            u64 sg2 = pk2(sgn,sgn);
            const float4* trow = (const float4*)&tms4[q][mm][0];   // 10 float4 (kkp)
            const float4* twf  = (const float4*)&s_twf[nn][0];
            const float4* twr  = (const float4*)&s_twfr[nn][0];
            u64 acc = 0;
            #pragma unroll
            for(int c=0;c<5;c++){
                float4 e  = twf[c];
                float4 er = twr[c];
                float4 v0 = trow[2*c];
                float4 v1 = trow[2*c+1];
                u64 t0 = pk2(v0.x,v0.y); fma2(t0, sg2, pk2(v0.z,v0.w));
                u64 t1 = pk2(v1.x,v1.y); fma2(t1, sg2, pk2(v1.z,v1.w));
                float2 f0 = u2f(t0), f1 = u2f(t1);
                fma2(acc, pk2(f0.x,f0.x), pk2(e.x,e.y));
                fma2(acc, pk2(f0.y,f0.y), pk2(er.x,er.y));
                fma2(acc, pk2(f1.x,f1.x), pk2(e.z,e.w));
                fma2(acc, pk2(f1.y,f1.y), pk2(er.z,er.w));
            }
            float2 a = u2f(acc);
            g_xg[b][i0+q][z2][mn] = a;
            if(mn < 40) g_xg[b][i0+q][z2][80-mn] = make_float2(a.x, -a.y);
        }
    }
}

// ---------------- xhat2 + T2 per (b,i), half-set ----------------
__global__ void k_xh2T2(){
    __shared__ float2 xgs[20][45];
    __shared__ float2 xh[5][5][9];
    int b = blockIdx.x/100, i = blockIdx.x%100;
    int t = threadIdx.x;  // 256
    for(int idx=t; idx<900; idx+=256){
        int z = idx/45, mn = idx%45;
        xgs[z][mn] = g_xg[b][i][z][mn];
    }
    __syncthreads();
    if(t < 225){
        int l = t/45, rr = t%45, mm = rr/9, kk = rr%9;
        int m = mm-4, kq = kk-4;
        u64 acc = 0;
        if(abs(m)<=l && abs(kq)<=l){
            #pragma unroll 4
            for(int z=0;z<20;z++){
                float d = c_d2[l][z][mm][kk];
                fma2(acc, pk2(d,d), *(const u64*)&xgs[z][mm*9+kk]);
            }
        }
        xh[l][mm][kk] = u2f(acc);
    }
    __syncthreads();
    if(t < 205){
        int l = t/41, mn = t%41, mm = mn/9, nn = mn%9;
        u64 acc = 0;
        #pragma unroll
        for(int kk=0;kk<9;kk++){
            float d = c_dh2[l][nn][kk];
            fma2(acc, pk2(d,d), *(const u64*)&xh[l][mm][kk]);
        }
        g_T2[l][mn][b][i] = u2f(acc);
    }
}

// ---------------- z2: half-set GEMM, b-split x2, packed ----------------
__global__ void k_z2(){
    __shared__ float2 Ts[16][100];
    int blk = blockIdx.x;
    int bh = blk/205, lh = blk%205;
    int l = lh/41, h = lh%41;
    int mm = h/9, nn = h%9;
    int m = mm-4, n = nn-4;
    int t = threadIdx.x;  // 256
    if(l < max(abs(m),abs(n))) return;
    const float2* src = &g_T2[l][h][bh*16][0];
    for(int idx=t; idx<1600; idx+=256) (&Ts[0][0])[idx] = src[idx];
    __syncthreads();
    if(t < 200){
        int bq = t/100, op = t%100;
        float sg = ((mm+nn)&1) ? -1.f : 1.f;
        int idx0 = l*81 + h, idx1 = l*81 + (80-h);
        int bb0 = bq*8;
        u64 a0[8], a1[8];
        #pragma unroll
        for(int rr=0;rr<8;rr++){ a0[rr]=0; a1[rr]=0; }
        for(int i=0;i<100;i++){
            float2 kf0 = g_k2f[nn][i][op];
            float2 kf1 = g_k2f[nn][i][op+100];
            u64 ka0 = pk2(kf0.x,-kf0.y), kb0 = pk2(kf0.y,kf0.x);
            u64 ka1 = pk2(kf1.x,-kf1.y), kb1 = pk2(kf1.y,kf1.x);
            #pragma unroll
            for(int rr=0;rr<8;rr++){
                float2 Tv = Ts[bb0+rr][i];
                u64 tx = pk2(Tv.x,Tv.x), ty = pk2(Tv.y,Tv.y);
                fma2(a0[rr], tx, ka0); fma2(a0[rr], ty, kb0);
                fma2(a1[rr], tx, ka1); fma2(a1[rr], ty, kb1);
            }
        }
        #pragma unroll
        for(int rr=0;rr<8;rr++){
            int bb = bh*16 + bb0 + rr;
            float2 v0 = u2f(a0[rr]), v1 = u2f(a1[rr]);
            g_z2t[bb][op    ][idx0] = v0;
            g_z2t[bb][op+100][idx0] = v1;
            if(h < 40){
                g_z2t[bb][op    ][idx1] = make_float2(sg*v0.x, -sg*v0.y);
                g_z2t[bb][op+100][idx1] = make_float2(sg*v1.x, -sg*v1.y);
            }
        }
    }
}

// ---------------- out2: packed stages + fused final via atomics ----------------
__global__ void k_out2(const float* __restrict__ b2, const float* __restrict__ W,
                       float* __restrict__ out){
    __shared__ float2 zs[405];
    __shared__ float2 g2a[10][81];
    __shared__ float2 tma[10][5][10];
    __shared__ float  wsum[8];
    int b = blockIdx.x/200, o = blockIdx.x%200;
    int t = threadIdx.x;  // 256
    for(int idx=t; idx<405; idx+=256){
        int l = idx/81, mn = idx%81, m = mn/9-4, n = mn%9-4;
        zs[idx] = (l >= max(abs(m),abs(n))) ? g_z2t[b][o][idx] : make_float2(0.f,0.f);
    }
    float b2v = b2[o];
    __syncthreads();
    for(int idx=t; idx<410; idx+=256){
        int z3 = idx/41, mn = idx%41, mm = mn/9, nn = mn%9;
        int m = mm-4, n = nn-4;
        int l0 = max(abs(m),abs(n));
        u64 acc = 0;
        for(int l=l0;l<5;l++){
            float d = c_dinv2[l][z3][mm][nn];
            fma2(acc, pk2(d,d), *(const u64*)&zs[l*81+mn]);
        }
        float2 a = u2f(acc);
        g2a[z3][mn] = a;
        g2a[z3][80-mn] = make_float2(a.x, -a.y);
    }
    __syncthreads();
    for(int idx=t; idx<500; idx+=256){
        int z3 = idx/50, rr = idx%50, mq = rr/10, k = rr%10;
        int mm = 4+mq;
        u64 acc = 0;
        #pragma unroll
        for(int nn=0;nn<9;nn++){
            float2 v = g2a[z3][mm*9+nn];
            fma2(acc, pk2(v.x,v.x), *(const u64*)&c_tw10b[nn][k]);
            fma2(acc, pk2(v.y,v.y), *(const u64*)&c_tw10br[nn][k]);
        }
        tma[z3][mq][k] = u2f(acc);
    }
    __syncthreads();
    float psum = 0.f;
    for(int idx=t; idx<1000; idx+=256){
        int z3 = idx/100, rr = idx%100, j = rr/10, k = rr%10;
        float v = tma[z3][0][k].x;
        #pragma unroll
        for(int mq=1;mq<5;mq++){
            float2 a = tma[z3][mq][k]; float2 e = c_tw10b[4+mq][j];
            v += 2.f*(a.x*e.x - a.y*e.y);
        }
        v = fmaxf(v + b2v, 0.f);
        psum += v * c_w5[z3];
    }
    #pragma unroll
    for(int off=16; off; off>>=1) psum += __shfl_xor_sync(0xFFFFFFFFu, psum, off);
    if((t&31) == 0) wsum[t>>5] = psum;
    __syncthreads();
    if(t == 0){
        float s = 0.f;
        #pragma unroll
        for(int w=0;w<8;w++) s += wsum[w];
        #pragma unroll
        for(int f=0;f<10;f++) atomicAdd(&out[b*10+f], s*W[f*200+o]);
    }
}

extern "C" void kernel_launch(void* const* d_in, const int* in_sizes, int n_in,
                              void* d_out, int out_size){
    const float* x  = (const float*)d_in[0];
    const float* k1 = (const float*)d_in[1];
    const float* b1 = (const float*)d_in[2];
    const float* k2 = (const float*)d_in[3];
    const float* b2 = (const float*)d_in[4];
    const float* W  = (const float*)d_in[5];
    const float* bl = (const float*)d_in[6];
    float* out = (float*)d_out;

    k_init  <<<128,256>>>(bl,out);
    k_dfts  <<<(19200+1000+180000+255)/256,256>>>(x,k1,k2);
    k_FGmid <<<740,256>>>();
    k_s2fuse<<<1280,400>>>(b1);
    k_xh2T2 <<<3200,256>>>();
    k_z2    <<<410,256>>>();
    k_out2  <<<6400,256>>>(b2,W,out);
}